// round 1
// baseline (speedup 1.0000x reference)
#include <cuda_runtime.h>
#include <math.h>

#define BATCH 4
#define SEQ   4096
#define DIM   1024
#define MTOT  (BATCH*SEQ)
#define AP    128

// ---------------- scratch (device globals: allowed) ----------------
__device__ float g_q[(size_t)MTOT*DIM];
__device__ float g_k[(size_t)MTOT*DIM];
__device__ float g_v[(size_t)MTOT*DIM];
__device__ float g_a[(size_t)MTOT*DIM];

// ---------------- SGEMM:  C[M,N] = A[M,K] @ B[N,K]^T (+bias, relu) ----------------
#define BM 128
#define BN 128
#define BKK 16

__global__ __launch_bounds__(256, 2)
void sgemm_nt(const float* __restrict__ A, const float* __restrict__ Bw,
              const float* __restrict__ bias, float* __restrict__ C,
              int M, int N, int K, int doRelu)
{
    __shared__ float As[BKK][BM + 4];
    __shared__ float Bs[BKK][BN + 4];

    const int tid = threadIdx.x;
    const int bm = blockIdx.y * BM;
    const int bn = blockIdx.x * BN;
    const int ty = tid >> 4;      // 0..15
    const int tx = tid & 15;      // 0..15

    float acc[8][8];
#pragma unroll
    for (int i = 0; i < 8; i++)
#pragma unroll
        for (int j = 0; j < 8; j++) acc[i][j] = 0.f;

    const int f0 = tid, f1 = tid + 256;
    const int ar0 = f0 >> 2, ac0 = f0 & 3;
    const int ar1 = f1 >> 2, ac1 = f1 & 3;

    // prologue prefetch (k0 = 0)
    float4 ra0 = *(const float4*)(A  + (size_t)(bm + ar0) * K + ac0 * 4);
    float4 ra1 = *(const float4*)(A  + (size_t)(bm + ar1) * K + ac1 * 4);
    float4 rb0 = *(const float4*)(Bw + (size_t)(bn + ar0) * K + ac0 * 4);
    float4 rb1 = *(const float4*)(Bw + (size_t)(bn + ar1) * K + ac1 * 4);

    for (int k0 = 0; k0 < K; k0 += BKK) {
        // stage regs -> smem (transposed)
        As[ac0*4+0][ar0] = ra0.x; As[ac0*4+1][ar0] = ra0.y;
        As[ac0*4+2][ar0] = ra0.z; As[ac0*4+3][ar0] = ra0.w;
        As[ac1*4+0][ar1] = ra1.x; As[ac1*4+1][ar1] = ra1.y;
        As[ac1*4+2][ar1] = ra1.z; As[ac1*4+3][ar1] = ra1.w;
        Bs[ac0*4+0][ar0] = rb0.x; Bs[ac0*4+1][ar0] = rb0.y;
        Bs[ac0*4+2][ar0] = rb0.z; Bs[ac0*4+3][ar0] = rb0.w;
        Bs[ac1*4+0][ar1] = rb1.x; Bs[ac1*4+1][ar1] = rb1.y;
        Bs[ac1*4+2][ar1] = rb1.z; Bs[ac1*4+3][ar1] = rb1.w;
        __syncthreads();

        // prefetch next tile (overlaps compute)
        if (k0 + BKK < K) {
            int kn = k0 + BKK;
            ra0 = *(const float4*)(A  + (size_t)(bm + ar0) * K + kn + ac0 * 4);
            ra1 = *(const float4*)(A  + (size_t)(bm + ar1) * K + kn + ac1 * 4);
            rb0 = *(const float4*)(Bw + (size_t)(bn + ar0) * K + kn + ac0 * 4);
            rb1 = *(const float4*)(Bw + (size_t)(bn + ar1) * K + kn + ac1 * 4);
        }

#pragma unroll
        for (int kk = 0; kk < BKK; kk++) {
            float4 a0 = *(const float4*)&As[kk][ty * 8];
            float4 a1 = *(const float4*)&As[kk][ty * 8 + 4];
            float4 b0 = *(const float4*)&Bs[kk][tx * 8];
            float4 b1 = *(const float4*)&Bs[kk][tx * 8 + 4];
            float a[8] = {a0.x,a0.y,a0.z,a0.w,a1.x,a1.y,a1.z,a1.w};
            float b[8] = {b0.x,b0.y,b0.z,b0.w,b1.x,b1.y,b1.z,b1.w};
#pragma unroll
            for (int i = 0; i < 8; i++)
#pragma unroll
                for (int j = 0; j < 8; j++)
                    acc[i][j] += a[i] * b[j];
        }
        __syncthreads();
    }

    // epilogue
#pragma unroll
    for (int i = 0; i < 8; i++) {
        size_t row = (size_t)(bm + ty * 8 + i);
        float* crow = C + row * N + bn + tx * 8;
#pragma unroll
        for (int j = 0; j < 8; j += 4) {
            float4 v = make_float4(acc[i][j], acc[i][j+1], acc[i][j+2], acc[i][j+3]);
            if (bias) {
                int col = bn + tx * 8 + j;
                v.x += bias[col]; v.y += bias[col+1]; v.z += bias[col+2]; v.w += bias[col+3];
            }
            if (doRelu) {
                v.x = fmaxf(v.x, 0.f); v.y = fmaxf(v.y, 0.f);
                v.z = fmaxf(v.z, 0.f); v.w = fmaxf(v.w, 0.f);
            }
            *(float4*)(crow + j) = v;
        }
    }
}

// ---------------- banded attention: 64 queries/block, window 320 keys ----------------
#define QB   64
#define KW   320
#define ESTR 324
#define ATT_TILE_FLOATS (2 * 16 * 68)   // Qs + Ks (Vs = 16*132 = 2112 fits inside 2176)
#define ATT_SMEM_BYTES  ((QB * ESTR + ATT_TILE_FLOATS) * 4)

__global__ __launch_bounds__(256)
void attn_kernel(const float* __restrict__ Q, const float* __restrict__ Kk,
                 const float* __restrict__ V, float* __restrict__ O)
{
    extern __shared__ float sm[];
    float* E  = sm;                 // [QB][ESTR]
    float* T0 = sm + QB * ESTR;     // tile scratch

    const int qb = blockIdx.x;      // 0..63
    const int b  = blockIdx.y;      // 0..3
    const int s0 = qb * QB;
    const int ks0 = s0 - AP;        // may be negative
    const int tid = threadIdx.x;
    const float scale = 0.03125f;   // 1/sqrt(1024)
    const float NEG = -1e30f;

    // ---- scores: E[m][j] = scale * Q[s0+m] . K[ks0+j]  (masked) ----
    {
        float* Qs = T0;             // [16][68]
        float* Ks = T0 + 16 * 68;   // [16][68]
        const int ry = tid >> 4, rx = tid & 15;
        const int lrow = tid >> 2, lc4 = tid & 3;

        for (int kt = 0; kt < 5; kt++) {
            float acc[4][4];
#pragma unroll
            for (int i = 0; i < 4; i++)
#pragma unroll
                for (int j = 0; j < 4; j++) acc[i][j] = 0.f;

            for (int k0 = 0; k0 < DIM; k0 += 16) {
                float4 qv = *(const float4*)(Q + ((size_t)(b*SEQ + s0 + lrow))*DIM + k0 + lc4*4);
                int krow = ks0 + kt * 64 + lrow;
                float4 kv = make_float4(0.f, 0.f, 0.f, 0.f);
                if (krow >= 0 && krow < SEQ)
                    kv = *(const float4*)(Kk + ((size_t)(b*SEQ + krow))*DIM + k0 + lc4*4);
                Qs[(lc4*4+0)*68 + lrow] = qv.x; Qs[(lc4*4+1)*68 + lrow] = qv.y;
                Qs[(lc4*4+2)*68 + lrow] = qv.z; Qs[(lc4*4+3)*68 + lrow] = qv.w;
                Ks[(lc4*4+0)*68 + lrow] = kv.x; Ks[(lc4*4+1)*68 + lrow] = kv.y;
                Ks[(lc4*4+2)*68 + lrow] = kv.z; Ks[(lc4*4+3)*68 + lrow] = kv.w;
                __syncthreads();
#pragma unroll
                for (int kk = 0; kk < 16; kk++) {
                    float4 a4 = *(const float4*)&Qs[kk*68 + ry*4];
                    float4 b4 = *(const float4*)&Ks[kk*68 + rx*4];
                    float a[4] = {a4.x, a4.y, a4.z, a4.w};
                    float bb[4] = {b4.x, b4.y, b4.z, b4.w};
#pragma unroll
                    for (int i = 0; i < 4; i++)
#pragma unroll
                        for (int j = 0; j < 4; j++)
                            acc[i][j] += a[i] * bb[j];
                }
                __syncthreads();
            }
            // write with mask
#pragma unroll
            for (int i = 0; i < 4; i++) {
                int m = ry * 4 + i;
                int s = s0 + m;
#pragma unroll
                for (int j = 0; j < 4; j++) {
                    int cc = rx * 4 + j;
                    int t = ks0 + kt * 64 + cc;
                    bool valid = (t >= 0) && (t < SEQ) && (t != s) &&
                                 (t >= s - AP) && (t <= s + AP);
                    E[m * ESTR + kt * 64 + cc] = valid ? acc[i][j] * scale : NEG;
                }
            }
        }
    }
    __syncthreads();

    // ---- softmax per row (warp per row, 8 rows/warp) ----
    {
        const int w = tid >> 5, lane = tid & 31;
        for (int rr = 0; rr < 8; rr++) {
            int m = w * 8 + rr;
            float mx = NEG;
            for (int j = lane; j < KW; j += 32) mx = fmaxf(mx, E[m * ESTR + j]);
#pragma unroll
            for (int o = 16; o; o >>= 1) mx = fmaxf(mx, __shfl_xor_sync(0xffffffffu, mx, o));
            float ssum = 0.f;
            for (int j = lane; j < KW; j += 32) {
                float p = __expf(E[m * ESTR + j] - mx);
                E[m * ESTR + j] = p;
                ssum += p;
            }
#pragma unroll
            for (int o = 16; o; o >>= 1) ssum += __shfl_xor_sync(0xffffffffu, ssum, o);
            float inv = 1.f / ssum;
            for (int j = lane; j < KW; j += 32) E[m * ESTR + j] *= inv;
        }
    }
    __syncthreads();

    // ---- O[64][1024] = P[64][320] @ V[window][1024] ----
    {
        float* Vs = T0;             // [16][132]
        const int rowg = tid >> 5, colg = tid & 31;
        for (int nc = 0; nc < 8; nc++) {
            float acc[8][4];
#pragma unroll
            for (int i = 0; i < 8; i++)
#pragma unroll
                for (int j = 0; j < 4; j++) acc[i][j] = 0.f;

            for (int kc = 0; kc < 20; kc++) {
#pragma unroll
                for (int l = 0; l < 2; l++) {
                    int f = tid + l * 256;
                    int vrow = f >> 5, vc4 = f & 31;
                    int t = ks0 + kc * 16 + vrow;
                    float4 vv = make_float4(0.f, 0.f, 0.f, 0.f);
                    if (t >= 0 && t < SEQ)
                        vv = *(const float4*)(V + ((size_t)(b*SEQ + t))*DIM + nc*128 + vc4*4);
                    *(float4*)(Vs + vrow * 132 + vc4 * 4) = vv;
                }
                __syncthreads();
#pragma unroll
                for (int kk = 0; kk < 16; kk++) {
                    float4 v4 = *(const float4*)(Vs + kk * 132 + colg * 4);
#pragma unroll
                    for (int i = 0; i < 8; i++) {
                        float p = E[(rowg * 8 + i) * ESTR + kc * 16 + kk];
                        acc[i][0] += p * v4.x; acc[i][1] += p * v4.y;
                        acc[i][2] += p * v4.z; acc[i][3] += p * v4.w;
                    }
                }
                __syncthreads();
            }
#pragma unroll
            for (int i = 0; i < 8; i++) {
                int s = s0 + rowg * 8 + i;
                *(float4*)(O + ((size_t)(b*SEQ + s))*DIM + nc*128 + colg*4) =
                    make_float4(acc[i][0], acc[i][1], acc[i][2], acc[i][3]);
            }
        }
    }
}

// ---------------- residual + LayerNorm (two-pass) ----------------
__global__ __launch_bounds__(256)
void ln_kernel(const float* __restrict__ X, const float* __restrict__ R,
               const float* __restrict__ g, const float* __restrict__ bta,
               float* __restrict__ Y)
{
    const int r = blockIdx.x, tid = threadIdx.x;
    const size_t base = (size_t)r * DIM;
    float4 v = *(const float4*)(X + base + tid * 4);
    if (R) {
        float4 rv = *(const float4*)(R + base + tid * 4);
        v.x += rv.x; v.y += rv.y; v.z += rv.z; v.w += rv.w;
    }
    __shared__ float red[8];
    __shared__ float s_mu, s_inv;
    const int w = tid >> 5, lane = tid & 31;

    float s = v.x + v.y + v.z + v.w;
#pragma unroll
    for (int o = 16; o; o >>= 1) s += __shfl_xor_sync(0xffffffffu, s, o);
    if (lane == 0) red[w] = s;
    __syncthreads();
    if (tid == 0) {
        float t = 0.f;
#pragma unroll
        for (int i = 0; i < 8; i++) t += red[i];
        s_mu = t * (1.f / DIM);
    }
    __syncthreads();
    float mu = s_mu;

    float dx = v.x - mu, dy = v.y - mu, dz = v.z - mu, dw = v.w - mu;
    float ss = dx*dx + dy*dy + dz*dz + dw*dw;
#pragma unroll
    for (int o = 16; o; o >>= 1) ss += __shfl_xor_sync(0xffffffffu, ss, o);
    if (lane == 0) red[w] = ss;
    __syncthreads();
    if (tid == 0) {
        float t = 0.f;
#pragma unroll
        for (int i = 0; i < 8; i++) t += red[i];
        s_inv = rsqrtf(t * (1.f / DIM) + 1e-6f);
    }
    __syncthreads();
    float inv = s_inv;

    float4 gg = *(const float4*)(g + tid * 4);
    float4 bb = *(const float4*)(bta + tid * 4);
    float4 o;
    o.x = dx * inv * gg.x + bb.x;
    o.y = dy * inv * gg.y + bb.y;
    o.z = dz * inv * gg.z + bb.z;
    o.w = dw * inv * gg.w + bb.w;
    *(float4*)(Y + base + tid * 4) = o;
}

// ---------------- head: sigmoid(x . w + b) ----------------
__global__ __launch_bounds__(256)
void head_kernel(const float* __restrict__ X, const float* __restrict__ w,
                 const float* __restrict__ bias, float* __restrict__ out)
{
    const int r = blockIdx.x, tid = threadIdx.x;
    float4 v = *(const float4*)(X + (size_t)r * DIM + tid * 4);
    float4 ww = *(const float4*)(w + tid * 4);
    float s = v.x*ww.x + v.y*ww.y + v.z*ww.z + v.w*ww.w;
    __shared__ float red[8];
    const int wr = tid >> 5, lane = tid & 31;
#pragma unroll
    for (int o = 16; o; o >>= 1) s += __shfl_xor_sync(0xffffffffu, s, o);
    if (lane == 0) red[wr] = s;
    __syncthreads();
    if (tid == 0) {
        float t = 0.f;
#pragma unroll
        for (int i = 0; i < 8; i++) t += red[i];
        t += bias[0];
        out[r] = 1.f / (1.f + expf(-t));
    }
}

// ---------------- launch ----------------
extern "C" void kernel_launch(void* const* d_in, const int* in_sizes, int n_in,
                              void* d_out, int out_size)
{
    const float* x   = (const float*)d_in[0];
    const float* Wq  = (const float*)d_in[1];
    const float* Wk  = (const float*)d_in[2];
    const float* Wv  = (const float*)d_in[3];
    const float* Wo  = (const float*)d_in[4];
    const float* k1w = (const float*)d_in[5];
    const float* k1b = (const float*)d_in[6];
    const float* k2w = (const float*)d_in[7];
    const float* k2b = (const float*)d_in[8];
    const float* lng = (const float*)d_in[9];
    const float* lnb = (const float*)d_in[10];
    float* out = (float*)d_out;

    float *gq, *gk, *gv, *ga;
    cudaGetSymbolAddress((void**)&gq, g_q);
    cudaGetSymbolAddress((void**)&gk, g_k);
    cudaGetSymbolAddress((void**)&gv, g_v);
    cudaGetSymbolAddress((void**)&ga, g_a);

    cudaFuncSetAttribute(attn_kernel, cudaFuncAttributeMaxDynamicSharedMemorySize,
                         ATT_SMEM_BYTES);

    dim3 gg(DIM / BN, MTOT / BM);   // (8, 128)

    sgemm_nt<<<gg, 256>>>(x, Wq, nullptr, gq, MTOT, DIM, DIM, 0);
    sgemm_nt<<<gg, 256>>>(x, Wk, nullptr, gk, MTOT, DIM, DIM, 0);
    sgemm_nt<<<gg, 256>>>(x, Wv, nullptr, gv, MTOT, DIM, DIM, 0);

    attn_kernel<<<dim3(SEQ / QB, BATCH), 256, ATT_SMEM_BYTES>>>(gq, gk, gv, ga);

    sgemm_nt<<<gg, 256>>>(ga, Wo, nullptr, gq, MTOT, DIM, DIM, 0);
    ln_kernel<<<MTOT, 256>>>(gq, x, lng, lnb, gk);
    sgemm_nt<<<gg, 256>>>(gk, k1w, k1b, gv, MTOT, DIM, DIM, 1);
    ln_kernel<<<MTOT, 256>>>(gv, nullptr, lng, lnb, ga);
    head_kernel<<<MTOT, 256>>>(ga, k2w, k2b, out);
}

// round 3
// speedup vs baseline: 2.2365x; 2.2365x over previous
#include <cuda_runtime.h>
#include <math.h>
#include <stdint.h>

#define BATCH 4
#define SEQ   4096
#define DIM   1024
#define MTOT  (BATCH*SEQ)
#define AP    128

// ---------------- scratch (device globals: allowed) ----------------
__device__ float g_q[(size_t)MTOT*DIM];
__device__ float g_k[(size_t)MTOT*DIM];
__device__ float g_v[(size_t)MTOT*DIM];
__device__ float g_a[(size_t)MTOT*DIM];

// =================== PTX helpers (sm_80-class only) ===================
__device__ __forceinline__ uint32_t s2u(const void* p) {
    uint32_t a;
    asm("{ .reg .u64 t; cvta.to.shared.u64 t, %1; cvt.u32.u64 %0, t; }" : "=r"(a) : "l"(p));
    return a;
}
__device__ __forceinline__ void cp16(uint32_t s, const void* g) {
    asm volatile("cp.async.cg.shared.global [%0], [%1], 16;" :: "r"(s), "l"(g));
}
#define CP_COMMIT() asm volatile("cp.async.commit_group;" ::: "memory")
#define CP_WAIT1()  asm volatile("cp.async.wait_group 1;" ::: "memory")
#define CP_WAIT0()  asm volatile("cp.async.wait_group 0;" ::: "memory")

__device__ __forceinline__ uint32_t f2tf32(float f) {
    uint32_t r;
    asm("cvt.rna.tf32.f32 %0, %1;" : "=r"(r) : "f"(f));
    return r;
}
__device__ __forceinline__ void mma8(float* c, uint32_t a0, uint32_t a1, uint32_t a2,
                                     uint32_t a3, uint32_t b0, uint32_t b1) {
    asm volatile(
        "mma.sync.aligned.m16n8k8.row.col.f32.tf32.tf32.f32 "
        "{%0,%1,%2,%3}, {%4,%5,%6,%7}, {%8,%9}, {%0,%1,%2,%3};"
        : "+f"(c[0]), "+f"(c[1]), "+f"(c[2]), "+f"(c[3])
        : "r"(a0), "r"(a1), "r"(a2), "r"(a3), "r"(b0), "r"(b1));
}

// =================== tf32 mma.sync GEMM ===================
// C[M,1024] = A[M,1024] @ B[1024,1024]^T (+bias, +relu)
// CTA tile 128x128, 8 warps -> warp tile 64x32. BK=32, double-buffered cp.async.
#define BM 128
#define BN 128
#define BK 32
#define KPITCH 36                    // floats per row in smem (pad: conflict-free frags)
#define STG_FLOATS (BM * KPITCH)     // 4608 floats per operand per stage
#define GEMM_SMEM (4 * STG_FLOATS * 4)   // A0,A1,B0,B1 = 73728 bytes
#define NSTAGE (DIM / BK)            // 32

__global__ __launch_bounds__(256)
void gemm_mma(const float* __restrict__ A, const float* __restrict__ Bw,
              const float* __restrict__ bias, float* __restrict__ C, int doRelu)
{
    extern __shared__ float sm[];
    float* As = sm;                        // [2][128][36]
    float* Bs = sm + 2 * STG_FLOATS;       // [2][128][36]
    const uint32_t As_u = s2u(As);
    const uint32_t Bs_u = s2u(Bs);

    const int tid  = threadIdx.x;
    const int warp = tid >> 5, lane = tid & 31;
    const int wm = warp >> 2;              // 0..1 : 64-row slice
    const int wn = warp & 3;               // 0..3 : 32-col slice
    const int gid = lane >> 2;             // group id 0..7
    const int tig = lane & 3;              // thread in group 0..3
    const int bm = blockIdx.y * BM;
    const int bn = blockIdx.x * BN;

    float acc[4][4][4];
#pragma unroll
    for (int i = 0; i < 4; i++)
#pragma unroll
        for (int j = 0; j < 4; j++)
#pragma unroll
            for (int k = 0; k < 4; k++) acc[i][j][k] = 0.f;

    // ---- async copy helpers: 1024 float4 per operand per stage, 4/thread ----
    // slot = tid + l*256 ; row = slot>>3 ; c4 = slot&7
    // smem byte addr within stage: row*144 + c4*16
#define LOAD_STAGE(stage, buf)                                                   \
    {                                                                            \
        const int k0 = (stage) * BK;                                             \
        _Pragma("unroll")                                                        \
        for (int l = 0; l < 4; l++) {                                            \
            int slot = tid + l * 256;                                            \
            int row = slot >> 3, c4 = slot & 7;                                  \
            uint32_t so = (uint32_t)(buf) * (STG_FLOATS * 4) + row * 144 + c4 * 16; \
            cp16(As_u + so, A  + (size_t)(bm + row) * DIM + k0 + c4 * 4);        \
            cp16(Bs_u + so, Bw + (size_t)(bn + row) * DIM + k0 + c4 * 4);        \
        }                                                                        \
        CP_COMMIT();                                                             \
    }

    LOAD_STAGE(0, 0);
    LOAD_STAGE(1, 1);

#pragma unroll 1
    for (int s = 0; s < NSTAGE; s++) {
        const int buf = s & 1;
        if (s + 1 < NSTAGE) { CP_WAIT1(); } else { CP_WAIT0(); }
        __syncthreads();

        const float* Ab = As + buf * STG_FLOATS;
        const float* Bb = Bs + buf * STG_FLOATS;

#pragma unroll
        for (int ks = 0; ks < 4; ks++) {
            const int kc = ks * 8 + tig;
            uint32_t af[4][4], bf[4][2];
#pragma unroll
            for (int mt = 0; mt < 4; mt++) {
                const int r = wm * 64 + mt * 16 + gid;
                af[mt][0] = f2tf32(Ab[r * KPITCH + kc]);
                af[mt][1] = f2tf32(Ab[(r + 8) * KPITCH + kc]);
                af[mt][2] = f2tf32(Ab[r * KPITCH + kc + 4]);
                af[mt][3] = f2tf32(Ab[(r + 8) * KPITCH + kc + 4]);
            }
#pragma unroll
            for (int nt = 0; nt < 4; nt++) {
                const int r = wn * 32 + nt * 8 + gid;
                bf[nt][0] = f2tf32(Bb[r * KPITCH + kc]);
                bf[nt][1] = f2tf32(Bb[r * KPITCH + kc + 4]);
            }
#pragma unroll
            for (int mt = 0; mt < 4; mt++)
#pragma unroll
                for (int nt = 0; nt < 4; nt++)
                    mma8(acc[mt][nt], af[mt][0], af[mt][1], af[mt][2], af[mt][3],
                         bf[nt][0], bf[nt][1]);
        }
        __syncthreads();
        if (s + 2 < NSTAGE) LOAD_STAGE(s + 2, buf);
    }

    // ---- epilogue: c0,c1 @ (row=gid, col=2*tig), c2,c3 @ (row=gid+8) ----
#pragma unroll
    for (int mt = 0; mt < 4; mt++) {
#pragma unroll
        for (int nt = 0; nt < 4; nt++) {
            const int col = bn + wn * 32 + nt * 8 + tig * 2;
            float bx = 0.f, by = 0.f;
            if (bias) { bx = bias[col]; by = bias[col + 1]; }
            const int r0 = bm + wm * 64 + mt * 16 + gid;
            float2 v0 = make_float2(acc[mt][nt][0] + bx, acc[mt][nt][1] + by);
            float2 v1 = make_float2(acc[mt][nt][2] + bx, acc[mt][nt][3] + by);
            if (doRelu) {
                v0.x = fmaxf(v0.x, 0.f); v0.y = fmaxf(v0.y, 0.f);
                v1.x = fmaxf(v1.x, 0.f); v1.y = fmaxf(v1.y, 0.f);
            }
            *(float2*)(C + (size_t)r0 * DIM + col)       = v0;
            *(float2*)(C + (size_t)(r0 + 8) * DIM + col) = v1;
        }
    }
}

// ---------------- banded attention: 64 queries/block, window 320 keys ----------------
#define QB   64
#define KW   320
#define ESTR 324
#define ATT_TILE_FLOATS (2 * 16 * 68)
#define ATT_SMEM_BYTES  ((QB * ESTR + ATT_TILE_FLOATS) * 4)

__global__ __launch_bounds__(256)
void attn_kernel(const float* __restrict__ Q, const float* __restrict__ Kk,
                 const float* __restrict__ V, float* __restrict__ O)
{
    extern __shared__ float smf[];
    float* E  = smf;
    float* T0 = smf + QB * ESTR;

    const int qb = blockIdx.x;
    const int b  = blockIdx.y;
    const int s0 = qb * QB;
    const int ks0 = s0 - AP;
    const int tid = threadIdx.x;
    const float scale = 0.03125f;
    const float NEG = -1e30f;

    {
        float* Qs = T0;
        float* Ks = T0 + 16 * 68;
        const int ry = tid >> 4, rx = tid & 15;
        const int lrow = tid >> 2, lc4 = tid & 3;

        for (int kt = 0; kt < 5; kt++) {
            float acc[4][4];
#pragma unroll
            for (int i = 0; i < 4; i++)
#pragma unroll
                for (int j = 0; j < 4; j++) acc[i][j] = 0.f;

            for (int k0 = 0; k0 < DIM; k0 += 16) {
                float4 qv = *(const float4*)(Q + ((size_t)(b*SEQ + s0 + lrow))*DIM + k0 + lc4*4);
                int krow = ks0 + kt * 64 + lrow;
                float4 kv = make_float4(0.f, 0.f, 0.f, 0.f);
                if (krow >= 0 && krow < SEQ)
                    kv = *(const float4*)(Kk + ((size_t)(b*SEQ + krow))*DIM + k0 + lc4*4);
                Qs[(lc4*4+0)*68 + lrow] = qv.x; Qs[(lc4*4+1)*68 + lrow] = qv.y;
                Qs[(lc4*4+2)*68 + lrow] = qv.z; Qs[(lc4*4+3)*68 + lrow] = qv.w;
                Ks[(lc4*4+0)*68 + lrow] = kv.x; Ks[(lc4*4+1)*68 + lrow] = kv.y;
                Ks[(lc4*4+2)*68 + lrow] = kv.z; Ks[(lc4*4+3)*68 + lrow] = kv.w;
                __syncthreads();
#pragma unroll
                for (int kk = 0; kk < 16; kk++) {
                    float4 a4 = *(const float4*)&Qs[kk*68 + ry*4];
                    float4 b4 = *(const float4*)&Ks[kk*68 + rx*4];
                    float a[4] = {a4.x, a4.y, a4.z, a4.w};
                    float bb[4] = {b4.x, b4.y, b4.z, b4.w};
#pragma unroll
                    for (int i = 0; i < 4; i++)
#pragma unroll
                        for (int j = 0; j < 4; j++)
                            acc[i][j] += a[i] * bb[j];
                }
                __syncthreads();
            }
#pragma unroll
            for (int i = 0; i < 4; i++) {
                int m = ry * 4 + i;
                int s = s0 + m;
#pragma unroll
                for (int j = 0; j < 4; j++) {
                    int cc = rx * 4 + j;
                    int t = ks0 + kt * 64 + cc;
                    bool valid = (t >= 0) && (t < SEQ) && (t != s) &&
                                 (t >= s - AP) && (t <= s + AP);
                    E[m * ESTR + kt * 64 + cc] = valid ? acc[i][j] * scale : NEG;
                }
            }
        }
    }
    __syncthreads();

    {
        const int w = tid >> 5, lane = tid & 31;
        for (int rr = 0; rr < 8; rr++) {
            int m = w * 8 + rr;
            float mx = NEG;
            for (int j = lane; j < KW; j += 32) mx = fmaxf(mx, E[m * ESTR + j]);
#pragma unroll
            for (int o = 16; o; o >>= 1) mx = fmaxf(mx, __shfl_xor_sync(0xffffffffu, mx, o));
            float ssum = 0.f;
            for (int j = lane; j < KW; j += 32) {
                float p = __expf(E[m * ESTR + j] - mx);
                E[m * ESTR + j] = p;
                ssum += p;
            }
#pragma unroll
            for (int o = 16; o; o >>= 1) ssum += __shfl_xor_sync(0xffffffffu, ssum, o);
            float inv = 1.f / ssum;
            for (int j = lane; j < KW; j += 32) E[m * ESTR + j] *= inv;
        }
    }
    __syncthreads();

    {
        float* Vs = T0;
        const int rowg = tid >> 5, colg = tid & 31;
        for (int nc = 0; nc < 8; nc++) {
            float acc[8][4];
#pragma unroll
            for (int i = 0; i < 8; i++)
#pragma unroll
                for (int j = 0; j < 4; j++) acc[i][j] = 0.f;

            for (int kc = 0; kc < 20; kc++) {
#pragma unroll
                for (int l = 0; l < 2; l++) {
                    int f = tid + l * 256;
                    int vrow = f >> 5, vc4 = f & 31;
                    int t = ks0 + kc * 16 + vrow;
                    float4 vv = make_float4(0.f, 0.f, 0.f, 0.f);
                    if (t >= 0 && t < SEQ)
                        vv = *(const float4*)(V + ((size_t)(b*SEQ + t))*DIM + nc*128 + vc4*4);
                    *(float4*)(Vs + vrow * 132 + vc4 * 4) = vv;
                }
                __syncthreads();
#pragma unroll
                for (int kk = 0; kk < 16; kk++) {
                    float4 v4 = *(const float4*)(Vs + kk * 132 + colg * 4);
#pragma unroll
                    for (int i = 0; i < 8; i++) {
                        float p = E[(rowg * 8 + i) * ESTR + kc * 16 + kk];
                        acc[i][0] += p * v4.x; acc[i][1] += p * v4.y;
                        acc[i][2] += p * v4.z; acc[i][3] += p * v4.w;
                    }
                }
                __syncthreads();
            }
#pragma unroll
            for (int i = 0; i < 8; i++) {
                int s = s0 + rowg * 8 + i;
                *(float4*)(O + ((size_t)(b*SEQ + s))*DIM + nc*128 + colg*4) =
                    make_float4(acc[i][0], acc[i][1], acc[i][2], acc[i][3]);
            }
        }
    }
}

// ---------------- residual + LayerNorm (two-pass) ----------------
__global__ __launch_bounds__(256)
void ln_kernel(const float* __restrict__ X, const float* __restrict__ R,
               const float* __restrict__ g, const float* __restrict__ bta,
               float* __restrict__ Y)
{
    const int r = blockIdx.x, tid = threadIdx.x;
    const size_t base = (size_t)r * DIM;
    float4 v = *(const float4*)(X + base + tid * 4);
    if (R) {
        float4 rv = *(const float4*)(R + base + tid * 4);
        v.x += rv.x; v.y += rv.y; v.z += rv.z; v.w += rv.w;
    }
    __shared__ float red[8];
    __shared__ float s_mu, s_inv;
    const int w = tid >> 5, lane = tid & 31;

    float s = v.x + v.y + v.z + v.w;
#pragma unroll
    for (int o = 16; o; o >>= 1) s += __shfl_xor_sync(0xffffffffu, s, o);
    if (lane == 0) red[w] = s;
    __syncthreads();
    if (tid == 0) {
        float t = 0.f;
#pragma unroll
        for (int i = 0; i < 8; i++) t += red[i];
        s_mu = t * (1.f / DIM);
    }
    __syncthreads();
    float mu = s_mu;

    float dx = v.x - mu, dy = v.y - mu, dz = v.z - mu, dw = v.w - mu;
    float ss = dx*dx + dy*dy + dz*dz + dw*dw;
#pragma unroll
    for (int o = 16; o; o >>= 1) ss += __shfl_xor_sync(0xffffffffu, ss, o);
    if (lane == 0) red[w] = ss;
    __syncthreads();
    if (tid == 0) {
        float t = 0.f;
#pragma unroll
        for (int i = 0; i < 8; i++) t += red[i];
        s_inv = rsqrtf(t * (1.f / DIM) + 1e-6f);
    }
    __syncthreads();
    float inv = s_inv;

    float4 gg = *(const float4*)(g + tid * 4);
    float4 bb = *(const float4*)(bta + tid * 4);
    float4 o;
    o.x = dx * inv * gg.x + bb.x;
    o.y = dy * inv * gg.y + bb.y;
    o.z = dz * inv * gg.z + bb.z;
    o.w = dw * inv * gg.w + bb.w;
    *(float4*)(Y + base + tid * 4) = o;
}

// ---------------- head: sigmoid(x . w + b) ----------------
__global__ __launch_bounds__(256)
void head_kernel(const float* __restrict__ X, const float* __restrict__ w,
                 const float* __restrict__ bias, float* __restrict__ out)
{
    const int r = blockIdx.x, tid = threadIdx.x;
    float4 v = *(const float4*)(X + (size_t)r * DIM + tid * 4);
    float4 ww = *(const float4*)(w + tid * 4);
    float s = v.x*ww.x + v.y*ww.y + v.z*ww.z + v.w*ww.w;
    __shared__ float red[8];
    const int wr = tid >> 5, lane = tid & 31;
#pragma unroll
    for (int o = 16; o; o >>= 1) s += __shfl_xor_sync(0xffffffffu, s, o);
    if (lane == 0) red[wr] = s;
    __syncthreads();
    if (tid == 0) {
        float t = 0.f;
#pragma unroll
        for (int i = 0; i < 8; i++) t += red[i];
        t += bias[0];
        out[r] = 1.f / (1.f + expf(-t));
    }
}

// ---------------- launch ----------------
extern "C" void kernel_launch(void* const* d_in, const int* in_sizes, int n_in,
                              void* d_out, int out_size)
{
    const float* x   = (const float*)d_in[0];
    const float* Wq  = (const float*)d_in[1];
    const float* Wk  = (const float*)d_in[2];
    const float* Wv  = (const float*)d_in[3];
    const float* Wo  = (const float*)d_in[4];
    const float* k1w = (const float*)d_in[5];
    const float* k1b = (const float*)d_in[6];
    const float* k2w = (const float*)d_in[7];
    const float* k2b = (const float*)d_in[8];
    const float* lng = (const float*)d_in[9];
    const float* lnb = (const float*)d_in[10];
    float* out = (float*)d_out;

    float *gq, *gk, *gv, *ga;
    cudaGetSymbolAddress((void**)&gq, g_q);
    cudaGetSymbolAddress((void**)&gk, g_k);
    cudaGetSymbolAddress((void**)&gv, g_v);
    cudaGetSymbolAddress((void**)&ga, g_a);

    cudaFuncSetAttribute(attn_kernel, cudaFuncAttributeMaxDynamicSharedMemorySize,
                         ATT_SMEM_BYTES);
    cudaFuncSetAttribute(gemm_mma, cudaFuncAttributeMaxDynamicSharedMemorySize,
                         GEMM_SMEM);

    dim3 gg(DIM / BN, MTOT / BM);   // (8, 128)

    gemm_mma<<<gg, 256, GEMM_SMEM>>>(x, Wq, nullptr, gq, 0);
    gemm_mma<<<gg, 256, GEMM_SMEM>>>(x, Wk, nullptr, gk, 0);
    gemm_mma<<<gg, 256, GEMM_SMEM>>>(x, Wv, nullptr, gv, 0);

    attn_kernel<<<dim3(SEQ / QB, BATCH), 256, ATT_SMEM_BYTES>>>(gq, gk, gv, ga);

    gemm_mma<<<gg, 256, GEMM_SMEM>>>(ga, Wo, nullptr, gq, 0);
    ln_kernel<<<MTOT, 256>>>(gq, x, lng, lnb, gk);
    gemm_mma<<<gg, 256, GEMM_SMEM>>>(gk, k1w, k1b, gv, 1);
    ln_kernel<<<MTOT, 256>>>(gv, nullptr, lng, lnb, ga);
    head_kernel<<<MTOT, 256>>>(ga, k2w, k2b, out);
}

// round 5
// speedup vs baseline: 2.9857x; 1.3350x over previous
#include <cuda_runtime.h>
#include <math.h>
#include <stdint.h>

#define BATCH 4
#define SEQ   4096
#define DIM   1024
#define MTOT  (BATCH*SEQ)
#define AP    128

// ---------------- scratch (device globals: allowed) ----------------
__device__ float g_q[(size_t)MTOT*DIM];
__device__ float g_k[(size_t)MTOT*DIM];
__device__ float g_v[(size_t)MTOT*DIM];
__device__ float g_a[(size_t)MTOT*DIM];

// =================== PTX helpers (sm_80-class only) ===================
__device__ __forceinline__ uint32_t s2u(const void* p) {
    uint32_t a;
    asm("{ .reg .u64 t; cvta.to.shared.u64 t, %1; cvt.u32.u64 %0, t; }" : "=r"(a) : "l"(p));
    return a;
}
__device__ __forceinline__ void cp16(uint32_t s, const void* g) {
    asm volatile("cp.async.cg.shared.global [%0], [%1], 16;" :: "r"(s), "l"(g));
}
#define CP_COMMIT() asm volatile("cp.async.commit_group;" ::: "memory")
#define CP_WAIT1()  asm volatile("cp.async.wait_group 1;" ::: "memory")
#define CP_WAIT0()  asm volatile("cp.async.wait_group 0;" ::: "memory")

__device__ __forceinline__ uint32_t f2tf32(float f) {
    uint32_t r;
    asm("cvt.rna.tf32.f32 %0, %1;" : "=r"(r) : "f"(f));
    return r;
}
__device__ __forceinline__ void mma8(float* c, uint32_t a0, uint32_t a1, uint32_t a2,
                                     uint32_t a3, uint32_t b0, uint32_t b1) {
    asm volatile(
        "mma.sync.aligned.m16n8k8.row.col.f32.tf32.tf32.f32 "
        "{%0,%1,%2,%3}, {%4,%5,%6,%7}, {%8,%9}, {%0,%1,%2,%3};"
        : "+f"(c[0]), "+f"(c[1]), "+f"(c[2]), "+f"(c[3])
        : "r"(a0), "r"(a1), "r"(a2), "r"(a3), "r"(b0), "r"(b1));
}

// =================== tf32 mma.sync GEMM ===================
#define BM 128
#define BN 128
#define BK 32
#define KPITCH 36
#define STG_FLOATS (BM * KPITCH)
#define GEMM_SMEM (4 * STG_FLOATS * 4)
#define NSTAGE (DIM / BK)

__global__ __launch_bounds__(256)
void gemm_mma(const float* __restrict__ A, const float* __restrict__ Bw,
              const float* __restrict__ bias, float* __restrict__ C, int doRelu)
{
    extern __shared__ float sm[];
    float* As = sm;
    float* Bs = sm + 2 * STG_FLOATS;
    const uint32_t As_u = s2u(As);
    const uint32_t Bs_u = s2u(Bs);

    const int tid  = threadIdx.x;
    const int warp = tid >> 5, lane = tid & 31;
    const int wm = warp >> 2;
    const int wn = warp & 3;
    const int gid = lane >> 2;
    const int tig = lane & 3;
    const int bm = blockIdx.y * BM;
    const int bn = blockIdx.x * BN;

    float acc[4][4][4];
#pragma unroll
    for (int i = 0; i < 4; i++)
#pragma unroll
        for (int j = 0; j < 4; j++)
#pragma unroll
            for (int k = 0; k < 4; k++) acc[i][j][k] = 0.f;

#define LOAD_STAGE(stage, buf)                                                   \
    {                                                                            \
        const int k0 = (stage) * BK;                                             \
        _Pragma("unroll")                                                        \
        for (int l = 0; l < 4; l++) {                                            \
            int slot = tid + l * 256;                                            \
            int row = slot >> 3, c4 = slot & 7;                                  \
            uint32_t so = (uint32_t)(buf) * (STG_FLOATS * 4) + row * 144 + c4 * 16; \
            cp16(As_u + so, A  + (size_t)(bm + row) * DIM + k0 + c4 * 4);        \
            cp16(Bs_u + so, Bw + (size_t)(bn + row) * DIM + k0 + c4 * 4);        \
        }                                                                        \
        CP_COMMIT();                                                             \
    }

    LOAD_STAGE(0, 0);
    LOAD_STAGE(1, 1);

#pragma unroll 1
    for (int s = 0; s < NSTAGE; s++) {
        const int buf = s & 1;
        if (s + 1 < NSTAGE) { CP_WAIT1(); } else { CP_WAIT0(); }
        __syncthreads();

        const float* Ab = As + buf * STG_FLOATS;
        const float* Bb = Bs + buf * STG_FLOATS;

#pragma unroll
        for (int ks = 0; ks < 4; ks++) {
            const int kc = ks * 8 + tig;
            uint32_t af[4][4], bf[4][2];
#pragma unroll
            for (int mt = 0; mt < 4; mt++) {
                const int r = wm * 64 + mt * 16 + gid;
                af[mt][0] = f2tf32(Ab[r * KPITCH + kc]);
                af[mt][1] = f2tf32(Ab[(r + 8) * KPITCH + kc]);
                af[mt][2] = f2tf32(Ab[r * KPITCH + kc + 4]);
                af[mt][3] = f2tf32(Ab[(r + 8) * KPITCH + kc + 4]);
            }
#pragma unroll
            for (int nt = 0; nt < 4; nt++) {
                const int r = wn * 32 + nt * 8 + gid;
                bf[nt][0] = f2tf32(Bb[r * KPITCH + kc]);
                bf[nt][1] = f2tf32(Bb[r * KPITCH + kc + 4]);
            }
#pragma unroll
            for (int mt = 0; mt < 4; mt++)
#pragma unroll
                for (int nt = 0; nt < 4; nt++)
                    mma8(acc[mt][nt], af[mt][0], af[mt][1], af[mt][2], af[mt][3],
                         bf[nt][0], bf[nt][1]);
        }
        __syncthreads();
        if (s + 2 < NSTAGE) LOAD_STAGE(s + 2, buf);
    }

#pragma unroll
    for (int mt = 0; mt < 4; mt++) {
#pragma unroll
        for (int nt = 0; nt < 4; nt++) {
            const int col = bn + wn * 32 + nt * 8 + tig * 2;
            float bx = 0.f, by = 0.f;
            if (bias) { bx = bias[col]; by = bias[col + 1]; }
            const int r0 = bm + wm * 64 + mt * 16 + gid;
            float2 v0 = make_float2(acc[mt][nt][0] + bx, acc[mt][nt][1] + by);
            float2 v1 = make_float2(acc[mt][nt][2] + bx, acc[mt][nt][3] + by);
            if (doRelu) {
                v0.x = fmaxf(v0.x, 0.f); v0.y = fmaxf(v0.y, 0.f);
                v1.x = fmaxf(v1.x, 0.f); v1.y = fmaxf(v1.y, 0.f);
            }
            *(float2*)(C + (size_t)r0 * DIM + col)       = v0;
            *(float2*)(C + (size_t)(r0 + 8) * DIM + col) = v1;
        }
    }
}

// =================== tensor-core banded attention ===================
// Per block: 64 queries, key window 320 (ks0 = s0-128), full softmax in smem.
#define QB   64
#define KW   320
#define ESTR 324
// smem float offsets
#define E_OFF  0
#define E_FLOATS (QB * ESTR)            // 20736
#define QS_OFF E_FLOATS                  // 20736
#define QS_STG (64 * 36)                 // 2304
#define KS_OFF (QS_OFF + 2 * QS_STG)     // 25344
#define KS_STG (320 * 36)                // 11520
#define VS_OFF QS_OFF                    // reuse Q/K region in phase 3
#define VS_STG (32 * 132)                // 4224
#define ATT_SMEM_BYTES ((KS_OFF + 2 * KS_STG) * 4)   // 193536

__global__ __launch_bounds__(256, 1)
void attn_tc(const float* __restrict__ Q, const float* __restrict__ Kk,
             const float* __restrict__ V, float* __restrict__ O)
{
    extern __shared__ float smf[];
    float* E = smf + E_OFF;
    const uint32_t smb = s2u(smf);

    const int tid = threadIdx.x;
    const int warp = tid >> 5, lane = tid & 31;
    const int wm = warp >> 2;            // 0..1
    const int wn = warp & 3;             // 0..3
    const int gid = lane >> 2;           // 0..7
    const int tig = lane & 3;            // 0..3
    const int qb = blockIdx.x;
    const int b  = blockIdx.y;
    const int s0 = qb * QB;
    const int ks0 = s0 - AP;
    const size_t brow = (size_t)b * SEQ;
    const float scale = 0.03125f;
    const float NEG = -1e30f;

    // ---------- phase 1: E[64][320] = Q @ K^T ----------
#define LOAD_QK(stage, buf)                                                         \
    {                                                                               \
        const int k0 = (stage) * 32;                                                \
        _Pragma("unroll")                                                           \
        for (int l = 0; l < 2; l++) {                                               \
            int slot = tid + l * 256;                                               \
            int row = slot >> 3, c4 = slot & 7;                                     \
            cp16(smb + (QS_OFF + (buf) * QS_STG) * 4 + row * 144 + c4 * 16,         \
                 Q + (brow + s0 + row) * DIM + k0 + c4 * 4);                        \
        }                                                                           \
        _Pragma("unroll")                                                           \
        for (int l = 0; l < 10; l++) {                                              \
            int slot = tid + l * 256;                                               \
            int row = slot >> 3, c4 = slot & 7;                                     \
            int kr = ks0 + row;                                                     \
            kr = kr < 0 ? 0 : (kr > SEQ - 1 ? SEQ - 1 : kr);                        \
            cp16(smb + (KS_OFF + (buf) * KS_STG) * 4 + row * 144 + c4 * 16,         \
                 Kk + (brow + kr) * DIM + k0 + c4 * 4);                             \
        }                                                                           \
        CP_COMMIT();                                                                \
    }

    {
        float acc[2][10][4];
#pragma unroll
        for (int i = 0; i < 2; i++)
#pragma unroll
            for (int j = 0; j < 10; j++)
#pragma unroll
                for (int k = 0; k < 4; k++) acc[i][j][k] = 0.f;

        LOAD_QK(0, 0);
        LOAD_QK(1, 1);

#pragma unroll 1
        for (int s = 0; s < 32; s++) {
            const int buf = s & 1;
            if (s + 1 < 32) { CP_WAIT1(); } else { CP_WAIT0(); }
            __syncthreads();
            const float* Qb = smf + QS_OFF + buf * QS_STG;
            const float* Kb = smf + KS_OFF + buf * KS_STG;
#pragma unroll
            for (int ks = 0; ks < 4; ks++) {
                const int kc = ks * 8 + tig;
                uint32_t af[2][4];
#pragma unroll
                for (int mt = 0; mt < 2; mt++) {
                    const int r = wm * 32 + mt * 16 + gid;
                    af[mt][0] = f2tf32(Qb[r * 36 + kc]);
                    af[mt][1] = f2tf32(Qb[(r + 8) * 36 + kc]);
                    af[mt][2] = f2tf32(Qb[r * 36 + kc + 4]);
                    af[mt][3] = f2tf32(Qb[(r + 8) * 36 + kc + 4]);
                }
#pragma unroll
                for (int nt = 0; nt < 10; nt++) {
                    const int r = wn * 80 + nt * 8 + gid;
                    uint32_t b0 = f2tf32(Kb[r * 36 + kc]);
                    uint32_t b1 = f2tf32(Kb[r * 36 + kc + 4]);
                    mma8(acc[0][nt], af[0][0], af[0][1], af[0][2], af[0][3], b0, b1);
                    mma8(acc[1][nt], af[1][0], af[1][1], af[1][2], af[1][3], b0, b1);
                }
            }
            __syncthreads();
            if (s + 2 < 32) LOAD_QK(s + 2, buf);
        }

        // write E with scale + mask
#pragma unroll
        for (int mt = 0; mt < 2; mt++) {
            const int m0 = wm * 32 + mt * 16 + gid;
#pragma unroll
            for (int nt = 0; nt < 10; nt++) {
                const int n0 = wn * 80 + nt * 8 + tig * 2;
#pragma unroll
                for (int e = 0; e < 4; e++) {
                    const int m = m0 + (e >> 1) * 8;
                    const int n = n0 + (e & 1);
                    const int s = s0 + m;
                    const int t = ks0 + n;
                    bool valid = (t >= 0) && (t < SEQ) && (t != s) &&
                                 (t >= s - AP) && (t <= s + AP);
                    E[m * ESTR + n] = valid ? acc[mt][nt][e] * scale : NEG;
                }
            }
        }
    }
    __syncthreads();

    // ---------- phase 2: softmax over 320 keys per row ----------
    {
        for (int rr = 0; rr < 8; rr++) {
            const int m = warp * 8 + rr;
            float mx = NEG;
            for (int j = lane; j < KW; j += 32) mx = fmaxf(mx, E[m * ESTR + j]);
#pragma unroll
            for (int o = 16; o; o >>= 1) mx = fmaxf(mx, __shfl_xor_sync(0xffffffffu, mx, o));
            float ssum = 0.f;
            for (int j = lane; j < KW; j += 32) {
                float p = __expf(E[m * ESTR + j] - mx);
                E[m * ESTR + j] = p;
                ssum += p;
            }
#pragma unroll
            for (int o = 16; o; o >>= 1) ssum += __shfl_xor_sync(0xffffffffu, ssum, o);
            float inv = 1.f / ssum;
            for (int j = lane; j < KW; j += 32) E[m * ESTR + j] *= inv;
        }
    }
    __syncthreads();

    // ---------- phase 3: O[64][1024] = P[64][320] @ V[320][1024] ----------
#define LOAD_V(tstage, buf, d0v)                                                    \
    {                                                                               \
        const int t0 = (tstage) * 32;                                               \
        _Pragma("unroll")                                                           \
        for (int l = 0; l < 4; l++) {                                               \
            int slot = tid + l * 256;                                               \
            int trow = slot >> 5, c4 = slot & 31;                                   \
            int tr = ks0 + t0 + trow;                                               \
            tr = tr < 0 ? 0 : (tr > SEQ - 1 ? SEQ - 1 : tr);                        \
            cp16(smb + (VS_OFF + (buf) * VS_STG) * 4 + trow * 528 + c4 * 16,        \
                 V + (brow + tr) * DIM + (d0v) + c4 * 4);                           \
        }                                                                           \
        CP_COMMIT();                                                                \
    }

#pragma unroll 1
    for (int nc = 0; nc < 8; nc++) {
        const int d0 = nc * 128;
        float acc[2][4][4];
#pragma unroll
        for (int i = 0; i < 2; i++)
#pragma unroll
            for (int j = 0; j < 4; j++)
#pragma unroll
                for (int k = 0; k < 4; k++) acc[i][j][k] = 0.f;

        LOAD_V(0, 0, d0);
        LOAD_V(1, 1, d0);

#pragma unroll 1
        for (int s = 0; s < 10; s++) {
            const int buf = s & 1;
            if (s + 1 < 10) { CP_WAIT1(); } else { CP_WAIT0(); }
            __syncthreads();
            const float* Vb = smf + VS_OFF + buf * VS_STG;
            const int tg = s * 32;
#pragma unroll
            for (int ks = 0; ks < 4; ks++) {
                const int kc = ks * 8 + tig;
                uint32_t af[2][4];
#pragma unroll
                for (int mt = 0; mt < 2; mt++) {
                    const int r = wm * 32 + mt * 16 + gid;
                    af[mt][0] = f2tf32(E[r * ESTR + tg + kc]);
                    af[mt][1] = f2tf32(E[(r + 8) * ESTR + tg + kc]);
                    af[mt][2] = f2tf32(E[r * ESTR + tg + kc + 4]);
                    af[mt][3] = f2tf32(E[(r + 8) * ESTR + tg + kc + 4]);
                }
#pragma unroll
                for (int nt = 0; nt < 4; nt++) {
                    const int r = wn * 32 + nt * 8 + gid;
                    uint32_t b0 = f2tf32(Vb[kc * 132 + r]);
                    uint32_t b1 = f2tf32(Vb[(kc + 4) * 132 + r]);
                    mma8(acc[0][nt], af[0][0], af[0][1], af[0][2], af[0][3], b0, b1);
                    mma8(acc[1][nt], af[1][0], af[1][1], af[1][2], af[1][3], b0, b1);
                }
            }
            __syncthreads();
            if (s + 2 < 10) LOAD_V(s + 2, buf, d0);
        }

        // epilogue for this d-chunk
#pragma unroll
        for (int mt = 0; mt < 2; mt++) {
            const int m0 = wm * 32 + mt * 16 + gid;
#pragma unroll
            for (int nt = 0; nt < 4; nt++) {
                const int col = d0 + wn * 32 + nt * 8 + tig * 2;
                *(float2*)(O + (brow + s0 + m0) * DIM + col) =
                    make_float2(acc[mt][nt][0], acc[mt][nt][1]);
                *(float2*)(O + (brow + s0 + m0 + 8) * DIM + col) =
                    make_float2(acc[mt][nt][2], acc[mt][nt][3]);
            }
        }
    }
}

// ---------------- residual + LayerNorm (two-pass) ----------------
__global__ __launch_bounds__(256)
void ln_kernel(const float* __restrict__ X, const float* __restrict__ R,
               const float* __restrict__ g, const float* __restrict__ bta,
               float* __restrict__ Y)
{
    const int r = blockIdx.x, tid = threadIdx.x;
    const size_t base = (size_t)r * DIM;
    float4 v = *(const float4*)(X + base + tid * 4);
    if (R) {
        float4 rv = *(const float4*)(R + base + tid * 4);
        v.x += rv.x; v.y += rv.y; v.z += rv.z; v.w += rv.w;
    }
    __shared__ float red[8];
    __shared__ float s_mu, s_inv;
    const int w = tid >> 5, lane = tid & 31;

    float s = v.x + v.y + v.z + v.w;
#pragma unroll
    for (int o = 16; o; o >>= 1) s += __shfl_xor_sync(0xffffffffu, s, o);
    if (lane == 0) red[w] = s;
    __syncthreads();
    if (tid == 0) {
        float t = 0.f;
#pragma unroll
        for (int i = 0; i < 8; i++) t += red[i];
        s_mu = t * (1.f / DIM);
    }
    __syncthreads();
    float mu = s_mu;

    float dx = v.x - mu, dy = v.y - mu, dz = v.z - mu, dw = v.w - mu;
    float ss = dx*dx + dy*dy + dz*dz + dw*dw;
#pragma unroll
    for (int o = 16; o; o >>= 1) ss += __shfl_xor_sync(0xffffffffu, ss, o);
    if (lane == 0) red[w] = ss;
    __syncthreads();
    if (tid == 0) {
        float t = 0.f;
#pragma unroll
        for (int i = 0; i < 8; i++) t += red[i];
        s_inv = rsqrtf(t * (1.f / DIM) + 1e-6f);
    }
    __syncthreads();
    float inv = s_inv;

    float4 gg = *(const float4*)(g + tid * 4);
    float4 bb = *(const float4*)(bta + tid * 4);
    float4 o;
    o.x = dx * inv * gg.x + bb.x;
    o.y = dy * inv * gg.y + bb.y;
    o.z = dz * inv * gg.z + bb.z;
    o.w = dw * inv * gg.w + bb.w;
    *(float4*)(Y + base + tid * 4) = o;
}

// ---------------- head: sigmoid(x . w + b) ----------------
__global__ __launch_bounds__(256)
void head_kernel(const float* __restrict__ X, const float* __restrict__ w,
                 const float* __restrict__ bias, float* __restrict__ out)
{
    const int r = blockIdx.x, tid = threadIdx.x;
    float4 v = *(const float4*)(X + (size_t)r * DIM + tid * 4);
    float4 ww = *(const float4*)(w + tid * 4);
    float s = v.x*ww.x + v.y*ww.y + v.z*ww.z + v.w*ww.w;
    __shared__ float red[8];
    const int wr = tid >> 5, lane = tid & 31;
#pragma unroll
    for (int o = 16; o; o >>= 1) s += __shfl_xor_sync(0xffffffffu, s, o);
    if (lane == 0) red[wr] = s;
    __syncthreads();
    if (tid == 0) {
        float t = 0.f;
#pragma unroll
        for (int i = 0; i < 8; i++) t += red[i];
        t += bias[0];
        out[r] = 1.f / (1.f + expf(-t));
    }
}

// ---------------- launch ----------------
extern "C" void kernel_launch(void* const* d_in, const int* in_sizes, int n_in,
                              void* d_out, int out_size)
{
    const float* x   = (const float*)d_in[0];
    const float* Wq  = (const float*)d_in[1];
    const float* Wk  = (const float*)d_in[2];
    const float* Wv  = (const float*)d_in[3];
    const float* Wo  = (const float*)d_in[4];
    const float* k1w = (const float*)d_in[5];
    const float* k1b = (const float*)d_in[6];
    const float* k2w = (const float*)d_in[7];
    const float* k2b = (const float*)d_in[8];
    const float* lng = (const float*)d_in[9];
    const float* lnb = (const float*)d_in[10];
    float* out = (float*)d_out;

    float *gq, *gk, *gv, *ga;
    cudaGetSymbolAddress((void**)&gq, g_q);
    cudaGetSymbolAddress((void**)&gk, g_k);
    cudaGetSymbolAddress((void**)&gv, g_v);
    cudaGetSymbolAddress((void**)&ga, g_a);

    cudaFuncSetAttribute(attn_tc, cudaFuncAttributeMaxDynamicSharedMemorySize,
                         ATT_SMEM_BYTES);
    cudaFuncSetAttribute(gemm_mma, cudaFuncAttributeMaxDynamicSharedMemorySize,
                         GEMM_SMEM);

    dim3 gg(DIM / BN, MTOT / BM);   // (8, 128)

    gemm_mma<<<gg, 256, GEMM_SMEM>>>(x, Wq, nullptr, gq, 0);
    gemm_mma<<<gg, 256, GEMM_SMEM>>>(x, Wk, nullptr, gk, 0);
    gemm_mma<<<gg, 256, GEMM_SMEM>>>(x, Wv, nullptr, gv, 0);

    attn_tc<<<dim3(SEQ / QB, BATCH), 256, ATT_SMEM_BYTES>>>(gq, gk, gv, ga);

    gemm_mma<<<gg, 256, GEMM_SMEM>>>(ga, Wo, nullptr, gq, 0);
    ln_kernel<<<MTOT, 256>>>(gq, x, lng, lnb, gk);
    gemm_mma<<<gg, 256, GEMM_SMEM>>>(gk, k1w, k1b, gv, 1);
    ln_kernel<<<MTOT, 256>>>(gv, nullptr, lng, lnb, ga);
    head_kernel<<<MTOT, 256>>>(ga, k2w, k2b, out);
}

// round 6
// speedup vs baseline: 5.0707x; 1.6984x over previous
#include <cuda_runtime.h>
#include <cuda_fp16.h>
#include <math.h>
#include <stdint.h>

#define BATCH 4
#define SEQ   4096
#define DIM   1024
#define MTOT  (BATCH*SEQ)
#define AP    128

// ---------------- scratch (device globals: allowed) ----------------
__device__ float  g_v [(size_t)MTOT*DIM];     // V (fp32, attn phase3)
__device__ float  g_c [(size_t)MTOT*DIM];     // Wo out
__device__ float  g_h [(size_t)MTOT*DIM];     // k1 out
__device__ float  g_y [(size_t)MTOT*DIM];     // ln2 out
__device__ __half g_x16[(size_t)MTOT*DIM];
__device__ __half g_q16[(size_t)MTOT*DIM];
__device__ __half g_k16[(size_t)MTOT*DIM];
__device__ __half g_a16[(size_t)MTOT*DIM];    // attn out
__device__ __half g_y16[(size_t)MTOT*DIM];    // ln1 out
__device__ __half g_wq16[DIM*DIM], g_wk16[DIM*DIM], g_wv16[DIM*DIM];
__device__ __half g_wo16[DIM*DIM], g_w116[DIM*DIM];

// =================== PTX helpers ===================
__device__ __forceinline__ uint32_t s2u(const void* p) {
    uint32_t a;
    asm("{ .reg .u64 t; cvta.to.shared.u64 t, %1; cvt.u32.u64 %0, t; }" : "=r"(a) : "l"(p));
    return a;
}
__device__ __forceinline__ void cp16(uint32_t s, const void* g) {
    asm volatile("cp.async.cg.shared.global [%0], [%1], 16;" :: "r"(s), "l"(g));
}
#define CP_COMMIT() asm volatile("cp.async.commit_group;" ::: "memory")
#define CP_WAIT1()  asm volatile("cp.async.wait_group 1;" ::: "memory")
#define CP_WAIT0()  asm volatile("cp.async.wait_group 0;" ::: "memory")

__device__ __forceinline__ uint32_t f2tf32(float f) {
    uint32_t r;
    asm("cvt.rna.tf32.f32 %0, %1;" : "=r"(r) : "f"(f));
    return r;
}
__device__ __forceinline__ void mma8(float* c, uint32_t a0, uint32_t a1, uint32_t a2,
                                     uint32_t a3, uint32_t b0, uint32_t b1) {
    asm volatile(
        "mma.sync.aligned.m16n8k8.row.col.f32.tf32.tf32.f32 "
        "{%0,%1,%2,%3}, {%4,%5,%6,%7}, {%8,%9}, {%0,%1,%2,%3};"
        : "+f"(c[0]), "+f"(c[1]), "+f"(c[2]), "+f"(c[3])
        : "r"(a0), "r"(a1), "r"(a2), "r"(a3), "r"(b0), "r"(b1));
}
__device__ __forceinline__ void mma16(float* c, uint32_t a0, uint32_t a1, uint32_t a2,
                                      uint32_t a3, uint32_t b0, uint32_t b1) {
    asm volatile(
        "mma.sync.aligned.m16n8k16.row.col.f32.f16.f16.f32 "
        "{%0,%1,%2,%3}, {%4,%5,%6,%7}, {%8,%9}, {%0,%1,%2,%3};"
        : "+f"(c[0]), "+f"(c[1]), "+f"(c[2]), "+f"(c[3])
        : "r"(a0), "r"(a1), "r"(a2), "r"(a3), "r"(b0), "r"(b1));
}

// =================== fp32 -> fp16 conversion ===================
__global__ __launch_bounds__(256)
void conv16(const float* __restrict__ in, __half* __restrict__ out) {
    const size_t i = ((size_t)blockIdx.x * 256 + threadIdx.x) * 4;
    float4 v = *(const float4*)(in + i);
    __half2 h0 = __floats2half2_rn(v.x, v.y);
    __half2 h1 = __floats2half2_rn(v.z, v.w);
    uint2 u;
    u.x = *(uint32_t*)&h0; u.y = *(uint32_t*)&h1;
    *(uint2*)(out + i) = u;
}

// =================== fp16 mma.sync GEMM ===================
// C[M,1024] = A[M,1024] @ B[1024,1024]^T (+bias, +relu). fp32 or fp16 output.
// CTA tile 128x128, 8 warps (warp 64x32), BK=64 halves, double-buffered.
#define HBK 64
#define HPITCH 72                         // halves per smem row (144 B)
#define HSTG_BYTES (128 * 144)            // 18432 per operand per stage
#define GEMMH_SMEM (4 * HSTG_BYTES)       // 73728
#define HNSTAGE (DIM / HBK)               // 16

__global__ __launch_bounds__(256)
void gemm_h(const __half* __restrict__ A, const __half* __restrict__ Bw,
            const float* __restrict__ bias, float* __restrict__ C32,
            __half* __restrict__ C16, int doRelu)
{
    extern __shared__ char smc[];
    const uint32_t As_u = s2u(smc);
    const uint32_t Bs_u = As_u + 2 * HSTG_BYTES;

    const int tid  = threadIdx.x;
    const int warp = tid >> 5, lane = tid & 31;
    const int wm = warp >> 2;             // 0..1
    const int wn = warp & 3;              // 0..3
    const int gid = lane >> 2;            // 0..7
    const int tig = lane & 3;             // 0..3
    const int bm = blockIdx.y * 128;
    const int bn = blockIdx.x * 128;

    float acc[4][4][4];
#pragma unroll
    for (int i = 0; i < 4; i++)
#pragma unroll
        for (int j = 0; j < 4; j++)
#pragma unroll
            for (int k = 0; k < 4; k++) acc[i][j][k] = 0.f;

#define LOADH(stage, buf)                                                        \
    {                                                                            \
        const int k0 = (stage) * HBK;                                            \
        _Pragma("unroll")                                                        \
        for (int l = 0; l < 4; l++) {                                            \
            int slot = tid + l * 256;                                            \
            int row = slot >> 3, c8 = slot & 7;                                  \
            uint32_t so = (uint32_t)(buf) * HSTG_BYTES + row * 144 + c8 * 16;    \
            cp16(As_u + so, A  + (size_t)(bm + row) * DIM + k0 + c8 * 8);        \
            cp16(Bs_u + so, Bw + (size_t)(bn + row) * DIM + k0 + c8 * 8);        \
        }                                                                        \
        CP_COMMIT();                                                             \
    }

    LOADH(0, 0);
    LOADH(1, 1);

#pragma unroll 1
    for (int s = 0; s < HNSTAGE; s++) {
        const int buf = s & 1;
        if (s + 1 < HNSTAGE) { CP_WAIT1(); } else { CP_WAIT0(); }
        __syncthreads();

        const __half* Ab = (const __half*)(smc + buf * HSTG_BYTES);
        const __half* Bb = (const __half*)(smc + 2 * HSTG_BYTES + buf * HSTG_BYTES);

#pragma unroll
        for (int ks = 0; ks < 4; ks++) {
            const int kb = ks * 16 + 2 * tig;
            uint32_t af[4][4], bf[4][2];
#pragma unroll
            for (int mt = 0; mt < 4; mt++) {
                const int r = wm * 64 + mt * 16 + gid;
                af[mt][0] = *(const uint32_t*)&Ab[r * HPITCH + kb];
                af[mt][1] = *(const uint32_t*)&Ab[(r + 8) * HPITCH + kb];
                af[mt][2] = *(const uint32_t*)&Ab[r * HPITCH + kb + 8];
                af[mt][3] = *(const uint32_t*)&Ab[(r + 8) * HPITCH + kb + 8];
            }
#pragma unroll
            for (int nt = 0; nt < 4; nt++) {
                const int r = wn * 32 + nt * 8 + gid;
                bf[nt][0] = *(const uint32_t*)&Bb[r * HPITCH + kb];
                bf[nt][1] = *(const uint32_t*)&Bb[r * HPITCH + kb + 8];
            }
#pragma unroll
            for (int mt = 0; mt < 4; mt++)
#pragma unroll
                for (int nt = 0; nt < 4; nt++)
                    mma16(acc[mt][nt], af[mt][0], af[mt][1], af[mt][2], af[mt][3],
                          bf[nt][0], bf[nt][1]);
        }
        __syncthreads();
        if (s + 2 < HNSTAGE) LOADH(s + 2, buf);
    }

#pragma unroll
    for (int mt = 0; mt < 4; mt++) {
#pragma unroll
        for (int nt = 0; nt < 4; nt++) {
            const int col = bn + wn * 32 + nt * 8 + tig * 2;
            float bx = 0.f, by = 0.f;
            if (bias) { bx = bias[col]; by = bias[col + 1]; }
            const int r0 = bm + wm * 64 + mt * 16 + gid;
            float2 v0 = make_float2(acc[mt][nt][0] + bx, acc[mt][nt][1] + by);
            float2 v1 = make_float2(acc[mt][nt][2] + bx, acc[mt][nt][3] + by);
            if (doRelu) {
                v0.x = fmaxf(v0.x, 0.f); v0.y = fmaxf(v0.y, 0.f);
                v1.x = fmaxf(v1.x, 0.f); v1.y = fmaxf(v1.y, 0.f);
            }
            if (C32) {
                *(float2*)(C32 + (size_t)r0 * DIM + col)       = v0;
                *(float2*)(C32 + (size_t)(r0 + 8) * DIM + col) = v1;
            }
            if (C16) {
                __half2 h0 = __floats2half2_rn(v0.x, v0.y);
                __half2 h1 = __floats2half2_rn(v1.x, v1.y);
                *(uint32_t*)(C16 + (size_t)r0 * DIM + col)       = *(uint32_t*)&h0;
                *(uint32_t*)(C16 + (size_t)(r0 + 8) * DIM + col) = *(uint32_t*)&h1;
            }
        }
    }
}

// =================== tensor-core banded attention ===================
// Phase1 fp16 QK^T, fp32 softmax, phase3 tf32 PV. 64 queries/block, window 320.
#define QB   64
#define KW   320
#define ESTR 324
// byte offsets in dynamic smem
#define E_BYTES   (QB * ESTR * 4)              // 82944
#define AQS_OFF   E_BYTES                      // fp16 Q tiles: 2 x 9216
#define AQS_STG   (64 * 144)                   // 9216
#define AKS_OFF   (AQS_OFF + 2 * AQS_STG)      // 101376 ; fp16 K tiles: 2 x 46080
#define AKS_STG   (320 * 144)                  // 46080
#define AVS_OFF   AQS_OFF                      // phase3 fp32 V tiles reuse: 2 x 16896
#define AVS_STG   (32 * 528)                   // 16896
#define ATT_SMEM_BYTES (AKS_OFF + 2 * AKS_STG) // 193536

__global__ __launch_bounds__(256, 1)
void attn_tc(const __half* __restrict__ Q, const __half* __restrict__ Kk,
             const float* __restrict__ V, __half* __restrict__ O)
{
    extern __shared__ char smc[];
    float* E = (float*)smc;
    const uint32_t smb = s2u(smc);

    const int tid = threadIdx.x;
    const int warp = tid >> 5, lane = tid & 31;
    const int wm = warp >> 2;            // 0..1
    const int wn = warp & 3;             // 0..3
    const int gid = lane >> 2;           // 0..7
    const int tig = lane & 3;            // 0..3
    const int qb = blockIdx.x;
    const int b  = blockIdx.y;
    const int s0 = qb * QB;
    const int ks0 = s0 - AP;
    const size_t brow = (size_t)b * SEQ;
    const float scale = 0.03125f;
    const float NEG = -1e30f;

    // ---------- phase 1: E[64][320] = Q @ K^T (fp16, BK=64) ----------
#define LOAD_QK(stage, buf)                                                         \
    {                                                                               \
        const int k0 = (stage) * HBK;                                               \
        _Pragma("unroll")                                                           \
        for (int l = 0; l < 2; l++) {                                               \
            int slot = tid + l * 256;                                               \
            int row = slot >> 3, c8 = slot & 7;                                     \
            cp16(smb + AQS_OFF + (buf) * AQS_STG + row * 144 + c8 * 16,             \
                 Q + (brow + s0 + row) * DIM + k0 + c8 * 8);                        \
        }                                                                           \
        _Pragma("unroll")                                                           \
        for (int l = 0; l < 10; l++) {                                              \
            int slot = tid + l * 256;                                               \
            int row = slot >> 3, c8 = slot & 7;                                     \
            int kr = ks0 + row;                                                     \
            kr = kr < 0 ? 0 : (kr > SEQ - 1 ? SEQ - 1 : kr);                        \
            cp16(smb + AKS_OFF + (buf) * AKS_STG + row * 144 + c8 * 16,             \
                 Kk + (brow + kr) * DIM + k0 + c8 * 8);                             \
        }                                                                           \
        CP_COMMIT();                                                                \
    }

    {
        float acc[2][10][4];
#pragma unroll
        for (int i = 0; i < 2; i++)
#pragma unroll
            for (int j = 0; j < 10; j++)
#pragma unroll
                for (int k = 0; k < 4; k++) acc[i][j][k] = 0.f;

        LOAD_QK(0, 0);
        LOAD_QK(1, 1);

#pragma unroll 1
        for (int s = 0; s < HNSTAGE; s++) {
            const int buf = s & 1;
            if (s + 1 < HNSTAGE) { CP_WAIT1(); } else { CP_WAIT0(); }
            __syncthreads();
            const __half* Qb = (const __half*)(smc + AQS_OFF + buf * AQS_STG);
            const __half* Kb = (const __half*)(smc + AKS_OFF + buf * AKS_STG);
#pragma unroll
            for (int ks = 0; ks < 4; ks++) {
                const int kb = ks * 16 + 2 * tig;
                uint32_t af[2][4];
#pragma unroll
                for (int mt = 0; mt < 2; mt++) {
                    const int r = wm * 32 + mt * 16 + gid;
                    af[mt][0] = *(const uint32_t*)&Qb[r * HPITCH + kb];
                    af[mt][1] = *(const uint32_t*)&Qb[(r + 8) * HPITCH + kb];
                    af[mt][2] = *(const uint32_t*)&Qb[r * HPITCH + kb + 8];
                    af[mt][3] = *(const uint32_t*)&Qb[(r + 8) * HPITCH + kb + 8];
                }
#pragma unroll
                for (int nt = 0; nt < 10; nt++) {
                    const int r = wn * 80 + nt * 8 + gid;
                    uint32_t b0 = *(const uint32_t*)&Kb[r * HPITCH + kb];
                    uint32_t b1 = *(const uint32_t*)&Kb[r * HPITCH + kb + 8];
                    mma16(acc[0][nt], af[0][0], af[0][1], af[0][2], af[0][3], b0, b1);
                    mma16(acc[1][nt], af[1][0], af[1][1], af[1][2], af[1][3], b0, b1);
                }
            }
            __syncthreads();
            if (s + 2 < HNSTAGE) LOAD_QK(s + 2, buf);
        }

        // write E with scale + mask
#pragma unroll
        for (int mt = 0; mt < 2; mt++) {
            const int m0 = wm * 32 + mt * 16 + gid;
#pragma unroll
            for (int nt = 0; nt < 10; nt++) {
                const int n0 = wn * 80 + nt * 8 + tig * 2;
#pragma unroll
                for (int e = 0; e < 4; e++) {
                    const int m = m0 + (e >> 1) * 8;
                    const int n = n0 + (e & 1);
                    const int s = s0 + m;
                    const int t = ks0 + n;
                    bool valid = (t >= 0) && (t < SEQ) && (t != s) &&
                                 (t >= s - AP) && (t <= s + AP);
                    E[m * ESTR + n] = valid ? acc[mt][nt][e] * scale : NEG;
                }
            }
        }
    }
    __syncthreads();

    // ---------- phase 2: softmax over 320 keys per row ----------
    {
        for (int rr = 0; rr < 8; rr++) {
            const int m = warp * 8 + rr;
            float mx = NEG;
            for (int j = lane; j < KW; j += 32) mx = fmaxf(mx, E[m * ESTR + j]);
#pragma unroll
            for (int o = 16; o; o >>= 1) mx = fmaxf(mx, __shfl_xor_sync(0xffffffffu, mx, o));
            float ssum = 0.f;
            for (int j = lane; j < KW; j += 32) {
                float p = __expf(E[m * ESTR + j] - mx);
                E[m * ESTR + j] = p;
                ssum += p;
            }
#pragma unroll
            for (int o = 16; o; o >>= 1) ssum += __shfl_xor_sync(0xffffffffu, ssum, o);
            float inv = 1.f / ssum;
            for (int j = lane; j < KW; j += 32) E[m * ESTR + j] *= inv;
        }
    }
    __syncthreads();

    // ---------- phase 3: O[64][1024] = P[64][320] @ V[320][1024] (tf32) ----------
#define LOAD_V(tstage, buf, d0v)                                                    \
    {                                                                               \
        const int t0 = (tstage) * 32;                                               \
        _Pragma("unroll")                                                           \
        for (int l = 0; l < 4; l++) {                                               \
            int slot = tid + l * 256;                                               \
            int trow = slot >> 5, c4 = slot & 31;                                   \
            int tr = ks0 + t0 + trow;                                               \
            tr = tr < 0 ? 0 : (tr > SEQ - 1 ? SEQ - 1 : tr);                        \
            cp16(smb + AVS_OFF + (buf) * AVS_STG + trow * 528 + c4 * 16,            \
                 V + (brow + tr) * DIM + (d0v) + c4 * 4);                           \
        }                                                                           \
        CP_COMMIT();                                                                \
    }

#pragma unroll 1
    for (int nc = 0; nc < 8; nc++) {
        const int d0 = nc * 128;
        float acc[2][4][4];
#pragma unroll
        for (int i = 0; i < 2; i++)
#pragma unroll
            for (int j = 0; j < 4; j++)
#pragma unroll
                for (int k = 0; k < 4; k++) acc[i][j][k] = 0.f;

        LOAD_V(0, 0, d0);
        LOAD_V(1, 1, d0);

#pragma unroll 1
        for (int s = 0; s < 10; s++) {
            const int buf = s & 1;
            if (s + 1 < 10) { CP_WAIT1(); } else { CP_WAIT0(); }
            __syncthreads();
            const float* Vb = (const float*)(smc + AVS_OFF + buf * AVS_STG);
            const int tg = s * 32;
#pragma unroll
            for (int ks = 0; ks < 4; ks++) {
                const int kc = ks * 8 + tig;
                uint32_t af[2][4];
#pragma unroll
                for (int mt = 0; mt < 2; mt++) {
                    const int r = wm * 32 + mt * 16 + gid;
                    af[mt][0] = f2tf32(E[r * ESTR + tg + kc]);
                    af[mt][1] = f2tf32(E[(r + 8) * ESTR + tg + kc]);
                    af[mt][2] = f2tf32(E[r * ESTR + tg + kc + 4]);
                    af[mt][3] = f2tf32(E[(r + 8) * ESTR + tg + kc + 4]);
                }
#pragma unroll
                for (int nt = 0; nt < 4; nt++) {
                    const int r = wn * 32 + nt * 8 + gid;
                    uint32_t b0 = f2tf32(Vb[kc * 132 + r]);
                    uint32_t b1 = f2tf32(Vb[(kc + 4) * 132 + r]);
                    mma8(acc[0][nt], af[0][0], af[0][1], af[0][2], af[0][3], b0, b1);
                    mma8(acc[1][nt], af[1][0], af[1][1], af[1][2], af[1][3], b0, b1);
                }
            }
            __syncthreads();
            if (s + 2 < 10) LOAD_V(s + 2, buf, d0);
        }

        // epilogue: fp16 out
#pragma unroll
        for (int mt = 0; mt < 2; mt++) {
            const int m0 = wm * 32 + mt * 16 + gid;
#pragma unroll
            for (int nt = 0; nt < 4; nt++) {
                const int col = d0 + wn * 32 + nt * 8 + tig * 2;
                __half2 h0 = __floats2half2_rn(acc[mt][nt][0], acc[mt][nt][1]);
                __half2 h1 = __floats2half2_rn(acc[mt][nt][2], acc[mt][nt][3]);
                *(uint32_t*)(O + (brow + s0 + m0) * DIM + col)       = *(uint32_t*)&h0;
                *(uint32_t*)(O + (brow + s0 + m0 + 8) * DIM + col)   = *(uint32_t*)&h1;
            }
        }
    }
}

// ---------------- residual + LayerNorm (two-pass, fp32 or fp16 out) ----------------
__global__ __launch_bounds__(256)
void ln_kernel(const float* __restrict__ X, const float* __restrict__ R,
               const float* __restrict__ g, const float* __restrict__ bta,
               float* __restrict__ Yf, __half* __restrict__ Yh)
{
    const int r = blockIdx.x, tid = threadIdx.x;
    const size_t base = (size_t)r * DIM;
    float4 v = *(const float4*)(X + base + tid * 4);
    if (R) {
        float4 rv = *(const float4*)(R + base + tid * 4);
        v.x += rv.x; v.y += rv.y; v.z += rv.z; v.w += rv.w;
    }
    __shared__ float red[8];
    __shared__ float s_mu, s_inv;
    const int w = tid >> 5, lane = tid & 31;

    float s = v.x + v.y + v.z + v.w;
#pragma unroll
    for (int o = 16; o; o >>= 1) s += __shfl_xor_sync(0xffffffffu, s, o);
    if (lane == 0) red[w] = s;
    __syncthreads();
    if (tid == 0) {
        float t = 0.f;
#pragma unroll
        for (int i = 0; i < 8; i++) t += red[i];
        s_mu = t * (1.f / DIM);
    }
    __syncthreads();
    float mu = s_mu;

    float dx = v.x - mu, dy = v.y - mu, dz = v.z - mu, dw = v.w - mu;
    float ss = dx*dx + dy*dy + dz*dz + dw*dw;
#pragma unroll
    for (int o = 16; o; o >>= 1) ss += __shfl_xor_sync(0xffffffffu, ss, o);
    if (lane == 0) red[w] = ss;
    __syncthreads();
    if (tid == 0) {
        float t = 0.f;
#pragma unroll
        for (int i = 0; i < 8; i++) t += red[i];
        s_inv = rsqrtf(t * (1.f / DIM) + 1e-6f);
    }
    __syncthreads();
    float inv = s_inv;

    float4 gg = *(const float4*)(g + tid * 4);
    float4 bb = *(const float4*)(bta + tid * 4);
    float4 o;
    o.x = dx * inv * gg.x + bb.x;
    o.y = dy * inv * gg.y + bb.y;
    o.z = dz * inv * gg.z + bb.z;
    o.w = dw * inv * gg.w + bb.w;
    if (Yf) *(float4*)(Yf + base + tid * 4) = o;
    if (Yh) {
        __half2 h0 = __floats2half2_rn(o.x, o.y);
        __half2 h1 = __floats2half2_rn(o.z, o.w);
        uint2 u; u.x = *(uint32_t*)&h0; u.y = *(uint32_t*)&h1;
        *(uint2*)(Yh + base + tid * 4) = u;
    }
}

// ---------------- head: sigmoid(x . w + b) ----------------
__global__ __launch_bounds__(256)
void head_kernel(const float* __restrict__ X, const float* __restrict__ w,
                 const float* __restrict__ bias, float* __restrict__ out)
{
    const int r = blockIdx.x, tid = threadIdx.x;
    float4 v = *(const float4*)(X + (size_t)r * DIM + tid * 4);
    float4 ww = *(const float4*)(w + tid * 4);
    float s = v.x*ww.x + v.y*ww.y + v.z*ww.z + v.w*ww.w;
    __shared__ float red[8];
    const int wr = tid >> 5, lane = tid & 31;
#pragma unroll
    for (int o = 16; o; o >>= 1) s += __shfl_xor_sync(0xffffffffu, s, o);
    if (lane == 0) red[wr] = s;
    __syncthreads();
    if (tid == 0) {
        float t = 0.f;
#pragma unroll
        for (int i = 0; i < 8; i++) t += red[i];
        t += bias[0];
        out[r] = 1.f / (1.f + expf(-t));
    }
}

// ---------------- launch ----------------
extern "C" void kernel_launch(void* const* d_in, const int* in_sizes, int n_in,
                              void* d_out, int out_size)
{
    const float* x   = (const float*)d_in[0];
    const float* Wq  = (const float*)d_in[1];
    const float* Wk  = (const float*)d_in[2];
    const float* Wv  = (const float*)d_in[3];
    const float* Wo  = (const float*)d_in[4];
    const float* k1w = (const float*)d_in[5];
    const float* k1b = (const float*)d_in[6];
    const float* k2w = (const float*)d_in[7];
    const float* k2b = (const float*)d_in[8];
    const float* lng = (const float*)d_in[9];
    const float* lnb = (const float*)d_in[10];
    float* out = (float*)d_out;

    float  *gv, *gc, *gh, *gy;
    __half *x16, *q16, *k16, *a16, *y16;
    __half *wq16, *wk16, *wv16, *wo16, *w116;
    cudaGetSymbolAddress((void**)&gv,  g_v);
    cudaGetSymbolAddress((void**)&gc,  g_c);
    cudaGetSymbolAddress((void**)&gh,  g_h);
    cudaGetSymbolAddress((void**)&gy,  g_y);
    cudaGetSymbolAddress((void**)&x16, g_x16);
    cudaGetSymbolAddress((void**)&q16, g_q16);
    cudaGetSymbolAddress((void**)&k16, g_k16);
    cudaGetSymbolAddress((void**)&a16, g_a16);
    cudaGetSymbolAddress((void**)&y16, g_y16);
    cudaGetSymbolAddress((void**)&wq16, g_wq16);
    cudaGetSymbolAddress((void**)&wk16, g_wk16);
    cudaGetSymbolAddress((void**)&wv16, g_wv16);
    cudaGetSymbolAddress((void**)&wo16, g_wo16);
    cudaGetSymbolAddress((void**)&w116, g_w116);

    cudaFuncSetAttribute(attn_tc, cudaFuncAttributeMaxDynamicSharedMemorySize,
                         ATT_SMEM_BYTES);
    cudaFuncSetAttribute(gemm_h, cudaFuncAttributeMaxDynamicSharedMemorySize,
                         GEMMH_SMEM);

    const int WBLK = (DIM * DIM) / 1024;       // 1024 blocks per weight
    conv16<<<(MTOT * DIM) / 1024, 256>>>(x, x16);
    conv16<<<WBLK, 256>>>(Wq,  wq16);
    conv16<<<WBLK, 256>>>(Wk,  wk16);
    conv16<<<WBLK, 256>>>(Wv,  wv16);
    conv16<<<WBLK, 256>>>(Wo,  wo16);
    conv16<<<WBLK, 256>>>(k1w, w116);

    dim3 gg(DIM / 128, MTOT / 128);   // (8, 128)

    gemm_h<<<gg, 256, GEMMH_SMEM>>>(x16, wq16, nullptr, nullptr, q16, 0);
    gemm_h<<<gg, 256, GEMMH_SMEM>>>(x16, wk16, nullptr, nullptr, k16, 0);
    gemm_h<<<gg, 256, GEMMH_SMEM>>>(x16, wv16, nullptr, gv, nullptr, 0);

    attn_tc<<<dim3(SEQ / QB, BATCH), 256, ATT_SMEM_BYTES>>>(q16, k16, gv, a16);

    gemm_h<<<gg, 256, GEMMH_SMEM>>>(a16, wo16, nullptr, gc, nullptr, 0);
    ln_kernel<<<MTOT, 256>>>(gc, x, lng, lnb, nullptr, y16);
    gemm_h<<<gg, 256, GEMMH_SMEM>>>(y16, w116, k1b, gh, nullptr, 1);
    ln_kernel<<<MTOT, 256>>>(gh, nullptr, lng, lnb, gy, nullptr);
    head_kernel<<<MTOT, 256>>>(gy, k2w, k2b, out);
}

// round 7
// speedup vs baseline: 5.4722x; 1.0792x over previous
#include <cuda_runtime.h>
#include <cuda_fp16.h>
#include <math.h>
#include <stdint.h>

#define BATCH 4
#define SEQ   4096
#define DIM   1024
#define MTOT  (BATCH*SEQ)
#define AP    128

// ---------------- scratch (device globals: allowed) ----------------
__device__ float  g_c [(size_t)MTOT*DIM];     // Wo out (fp32)
__device__ float  g_h [(size_t)MTOT*DIM];     // k1 out (fp32)
__device__ __half g_x16[(size_t)MTOT*DIM];
__device__ __half g_q16[(size_t)MTOT*DIM];
__device__ __half g_k16[(size_t)MTOT*DIM];
__device__ __half g_v16[(size_t)MTOT*DIM];
__device__ __half g_a16[(size_t)MTOT*DIM];    // attn out
__device__ __half g_y16[(size_t)MTOT*DIM];    // ln1 out
__device__ __half g_wq16[DIM*DIM], g_wk16[DIM*DIM], g_wv16[DIM*DIM];
__device__ __half g_wo16[DIM*DIM], g_w116[DIM*DIM];

// =================== PTX helpers ===================
__device__ __forceinline__ uint32_t s2u(const void* p) {
    uint32_t a;
    asm("{ .reg .u64 t; cvta.to.shared.u64 t, %1; cvt.u32.u64 %0, t; }" : "=r"(a) : "l"(p));
    return a;
}
__device__ __forceinline__ void cp16(uint32_t s, const void* g) {
    asm volatile("cp.async.cg.shared.global [%0], [%1], 16;" :: "r"(s), "l"(g));
}
#define CP_COMMIT() asm volatile("cp.async.commit_group;" ::: "memory")
#define CP_WAIT1()  asm volatile("cp.async.wait_group 1;" ::: "memory")
#define CP_WAIT0()  asm volatile("cp.async.wait_group 0;" ::: "memory")

__device__ __forceinline__ void mma16(float* c, uint32_t a0, uint32_t a1, uint32_t a2,
                                      uint32_t a3, uint32_t b0, uint32_t b1) {
    asm volatile(
        "mma.sync.aligned.m16n8k16.row.col.f32.f16.f16.f32 "
        "{%0,%1,%2,%3}, {%4,%5,%6,%7}, {%8,%9}, {%0,%1,%2,%3};"
        : "+f"(c[0]), "+f"(c[1]), "+f"(c[2]), "+f"(c[3])
        : "r"(a0), "r"(a1), "r"(a2), "r"(a3), "r"(b0), "r"(b1));
}
__device__ __forceinline__ void ldsm4t(uint32_t& r0, uint32_t& r1, uint32_t& r2,
                                       uint32_t& r3, uint32_t addr) {
    asm volatile("ldmatrix.sync.aligned.m8n8.x4.trans.shared.b16 {%0,%1,%2,%3}, [%4];"
                 : "=r"(r0), "=r"(r1), "=r"(r2), "=r"(r3) : "r"(addr));
}

// =================== fp32 -> fp16 conversion ===================
__global__ __launch_bounds__(256)
void conv16(const float* __restrict__ in, __half* __restrict__ out) {
    const size_t i = ((size_t)blockIdx.x * 256 + threadIdx.x) * 4;
    float4 v = *(const float4*)(in + i);
    __half2 h0 = __floats2half2_rn(v.x, v.y);
    __half2 h1 = __floats2half2_rn(v.z, v.w);
    uint2 u;
    u.x = *(uint32_t*)&h0; u.y = *(uint32_t*)&h1;
    *(uint2*)(out + i) = u;
}

// =================== fp16 mma.sync GEMM ===================
#define HBK 64
#define HPITCH 72
#define HSTG_BYTES (128 * 144)
#define GEMMH_SMEM (4 * HSTG_BYTES)
#define HNSTAGE (DIM / HBK)

__global__ __launch_bounds__(256)
void gemm_h(const __half* __restrict__ A, const __half* __restrict__ Bw,
            const float* __restrict__ bias, float* __restrict__ C32,
            __half* __restrict__ C16, int doRelu)
{
    extern __shared__ char smc[];
    const uint32_t As_u = s2u(smc);
    const uint32_t Bs_u = As_u + 2 * HSTG_BYTES;

    const int tid  = threadIdx.x;
    const int warp = tid >> 5, lane = tid & 31;
    const int wm = warp >> 2;
    const int wn = warp & 3;
    const int gid = lane >> 2;
    const int tig = lane & 3;
    const int bm = blockIdx.y * 128;
    const int bn = blockIdx.x * 128;

    float acc[4][4][4];
#pragma unroll
    for (int i = 0; i < 4; i++)
#pragma unroll
        for (int j = 0; j < 4; j++)
#pragma unroll
            for (int k = 0; k < 4; k++) acc[i][j][k] = 0.f;

#define LOADH(stage, buf)                                                        \
    {                                                                            \
        const int k0 = (stage) * HBK;                                            \
        _Pragma("unroll")                                                        \
        for (int l = 0; l < 4; l++) {                                            \
            int slot = tid + l * 256;                                            \
            int row = slot >> 3, c8 = slot & 7;                                  \
            uint32_t so = (uint32_t)(buf) * HSTG_BYTES + row * 144 + c8 * 16;    \
            cp16(As_u + so, A  + (size_t)(bm + row) * DIM + k0 + c8 * 8);        \
            cp16(Bs_u + so, Bw + (size_t)(bn + row) * DIM + k0 + c8 * 8);        \
        }                                                                        \
        CP_COMMIT();                                                             \
    }

    LOADH(0, 0);
    LOADH(1, 1);

#pragma unroll 1
    for (int s = 0; s < HNSTAGE; s++) {
        const int buf = s & 1;
        if (s + 1 < HNSTAGE) { CP_WAIT1(); } else { CP_WAIT0(); }
        __syncthreads();

        const __half* Ab = (const __half*)(smc + buf * HSTG_BYTES);
        const __half* Bb = (const __half*)(smc + 2 * HSTG_BYTES + buf * HSTG_BYTES);

#pragma unroll
        for (int ks = 0; ks < 4; ks++) {
            const int kb = ks * 16 + 2 * tig;
            uint32_t af[4][4], bf[4][2];
#pragma unroll
            for (int mt = 0; mt < 4; mt++) {
                const int r = wm * 64 + mt * 16 + gid;
                af[mt][0] = *(const uint32_t*)&Ab[r * HPITCH + kb];
                af[mt][1] = *(const uint32_t*)&Ab[(r + 8) * HPITCH + kb];
                af[mt][2] = *(const uint32_t*)&Ab[r * HPITCH + kb + 8];
                af[mt][3] = *(const uint32_t*)&Ab[(r + 8) * HPITCH + kb + 8];
            }
#pragma unroll
            for (int nt = 0; nt < 4; nt++) {
                const int r = wn * 32 + nt * 8 + gid;
                bf[nt][0] = *(const uint32_t*)&Bb[r * HPITCH + kb];
                bf[nt][1] = *(const uint32_t*)&Bb[r * HPITCH + kb + 8];
            }
#pragma unroll
            for (int mt = 0; mt < 4; mt++)
#pragma unroll
                for (int nt = 0; nt < 4; nt++)
                    mma16(acc[mt][nt], af[mt][0], af[mt][1], af[mt][2], af[mt][3],
                          bf[nt][0], bf[nt][1]);
        }
        __syncthreads();
        if (s + 2 < HNSTAGE) LOADH(s + 2, buf);
    }

#pragma unroll
    for (int mt = 0; mt < 4; mt++) {
#pragma unroll
        for (int nt = 0; nt < 4; nt++) {
            const int col = bn + wn * 32 + nt * 8 + tig * 2;
            float bx = 0.f, by = 0.f;
            if (bias) { bx = bias[col]; by = bias[col + 1]; }
            const int r0 = bm + wm * 64 + mt * 16 + gid;
            float2 v0 = make_float2(acc[mt][nt][0] + bx, acc[mt][nt][1] + by);
            float2 v1 = make_float2(acc[mt][nt][2] + bx, acc[mt][nt][3] + by);
            if (doRelu) {
                v0.x = fmaxf(v0.x, 0.f); v0.y = fmaxf(v0.y, 0.f);
                v1.x = fmaxf(v1.x, 0.f); v1.y = fmaxf(v1.y, 0.f);
            }
            if (C32) {
                *(float2*)(C32 + (size_t)r0 * DIM + col)       = v0;
                *(float2*)(C32 + (size_t)(r0 + 8) * DIM + col) = v1;
            }
            if (C16) {
                __half2 h0 = __floats2half2_rn(v0.x, v0.y);
                __half2 h1 = __floats2half2_rn(v1.x, v1.y);
                *(uint32_t*)(C16 + (size_t)r0 * DIM + col)       = *(uint32_t*)&h0;
                *(uint32_t*)(C16 + (size_t)(r0 + 8) * DIM + col) = *(uint32_t*)&h1;
            }
        }
    }
}

// =================== tensor-core banded attention (full fp16 MMA) ===================
// Phase1 fp16 QK^T, fp32 softmax -> fp16 P, phase3 fp16 PV via ldmatrix.trans.
#define QB   64
#define KW   320
#define ESTR 324
#define PESTR 330                               // fp16 P pitch (conflict-free A frags)
#define VPITCH 136                              // fp16 V pitch (conflict-free ldmatrix)
// byte offsets in dynamic smem
#define E_BYTES   (QB * ESTR * 4)               // 82944 : fp32 scores
#define AQS_OFF   E_BYTES                       // phase1 fp16 Q tiles: 2 x 9216
#define AQS_STG   (64 * 144)
#define AKS_OFF   (AQS_OFF + 2 * AQS_STG)       // phase1 fp16 K tiles: 2 x 46080
#define AKS_STG   (320 * 144)
#define PS_OFF    E_BYTES                       // phase2/3: fp16 P (reuses QK region)
#define PS_BYTES  (QB * PESTR * 2)              // 42240
#define AVS_OFF   (PS_OFF + PS_BYTES)           // phase3 fp16 V tiles: 2 x 8704
#define AVS_STG   (32 * VPITCH * 2)             // 8704
#define ATT_SMEM_BYTES (AKS_OFF + 2 * AKS_STG)  // 193536

__global__ __launch_bounds__(256, 1)
void attn_tc(const __half* __restrict__ Q, const __half* __restrict__ Kk,
             const __half* __restrict__ V, __half* __restrict__ O)
{
    extern __shared__ char smc[];
    float*  E  = (float*)smc;
    __half* Ph = (__half*)(smc + PS_OFF);
    const uint32_t smb = s2u(smc);

    const int tid = threadIdx.x;
    const int warp = tid >> 5, lane = tid & 31;
    const int wm = warp >> 2;            // 0..1
    const int wn = warp & 3;             // 0..3
    const int gid = lane >> 2;           // 0..7
    const int tig = lane & 3;            // 0..3
    const int qb = blockIdx.x;
    const int b  = blockIdx.y;
    const int s0 = qb * QB;
    const int ks0 = s0 - AP;
    const size_t brow = (size_t)b * SEQ;
    const float scale = 0.03125f;
    const float NEG = -1e30f;

    // ---------- phase 1: E[64][320] = Q @ K^T (fp16, BK=64) ----------
#define LOAD_QK(stage, buf)                                                         \
    {                                                                               \
        const int k0 = (stage) * HBK;                                               \
        _Pragma("unroll")                                                           \
        for (int l = 0; l < 2; l++) {                                               \
            int slot = tid + l * 256;                                               \
            int row = slot >> 3, c8 = slot & 7;                                     \
            cp16(smb + AQS_OFF + (buf) * AQS_STG + row * 144 + c8 * 16,             \
                 Q + (brow + s0 + row) * DIM + k0 + c8 * 8);                        \
        }                                                                           \
        _Pragma("unroll")                                                           \
        for (int l = 0; l < 10; l++) {                                              \
            int slot = tid + l * 256;                                               \
            int row = slot >> 3, c8 = slot & 7;                                     \
            int kr = ks0 + row;                                                     \
            kr = kr < 0 ? 0 : (kr > SEQ - 1 ? SEQ - 1 : kr);                        \
            cp16(smb + AKS_OFF + (buf) * AKS_STG + row * 144 + c8 * 16,             \
                 Kk + (brow + kr) * DIM + k0 + c8 * 8);                             \
        }                                                                           \
        CP_COMMIT();                                                                \
    }

    {
        float acc[2][10][4];
#pragma unroll
        for (int i = 0; i < 2; i++)
#pragma unroll
            for (int j = 0; j < 10; j++)
#pragma unroll
                for (int k = 0; k < 4; k++) acc[i][j][k] = 0.f;

        LOAD_QK(0, 0);
        LOAD_QK(1, 1);

#pragma unroll 1
        for (int s = 0; s < HNSTAGE; s++) {
            const int buf = s & 1;
            if (s + 1 < HNSTAGE) { CP_WAIT1(); } else { CP_WAIT0(); }
            __syncthreads();
            const __half* Qb = (const __half*)(smc + AQS_OFF + buf * AQS_STG);
            const __half* Kb = (const __half*)(smc + AKS_OFF + buf * AKS_STG);
#pragma unroll
            for (int ks = 0; ks < 4; ks++) {
                const int kb = ks * 16 + 2 * tig;
                uint32_t af[2][4];
#pragma unroll
                for (int mt = 0; mt < 2; mt++) {
                    const int r = wm * 32 + mt * 16 + gid;
                    af[mt][0] = *(const uint32_t*)&Qb[r * HPITCH + kb];
                    af[mt][1] = *(const uint32_t*)&Qb[(r + 8) * HPITCH + kb];
                    af[mt][2] = *(const uint32_t*)&Qb[r * HPITCH + kb + 8];
                    af[mt][3] = *(const uint32_t*)&Qb[(r + 8) * HPITCH + kb + 8];
                }
#pragma unroll
                for (int nt = 0; nt < 10; nt++) {
                    const int r = wn * 80 + nt * 8 + gid;
                    uint32_t b0 = *(const uint32_t*)&Kb[r * HPITCH + kb];
                    uint32_t b1 = *(const uint32_t*)&Kb[r * HPITCH + kb + 8];
                    mma16(acc[0][nt], af[0][0], af[0][1], af[0][2], af[0][3], b0, b1);
                    mma16(acc[1][nt], af[1][0], af[1][1], af[1][2], af[1][3], b0, b1);
                }
            }
            __syncthreads();
            if (s + 2 < HNSTAGE) LOAD_QK(s + 2, buf);
        }

        // write E with scale + mask
#pragma unroll
        for (int mt = 0; mt < 2; mt++) {
            const int m0 = wm * 32 + mt * 16 + gid;
#pragma unroll
            for (int nt = 0; nt < 10; nt++) {
                const int n0 = wn * 80 + nt * 8 + tig * 2;
#pragma unroll
                for (int e = 0; e < 4; e++) {
                    const int m = m0 + (e >> 1) * 8;
                    const int n = n0 + (e & 1);
                    const int s = s0 + m;
                    const int t = ks0 + n;
                    bool valid = (t >= 0) && (t < SEQ) && (t != s) &&
                                 (t >= s - AP) && (t <= s + AP);
                    E[m * ESTR + n] = valid ? acc[mt][nt][e] * scale : NEG;
                }
            }
        }
    }
    __syncthreads();

    // ---------- phase 2: softmax, P emitted as fp16 ----------
    {
        for (int rr = 0; rr < 8; rr++) {
            const int m = warp * 8 + rr;
            float mx = NEG;
            for (int j = lane; j < KW; j += 32) mx = fmaxf(mx, E[m * ESTR + j]);
#pragma unroll
            for (int o = 16; o; o >>= 1) mx = fmaxf(mx, __shfl_xor_sync(0xffffffffu, mx, o));
            float ssum = 0.f;
            float pv[10];
#pragma unroll
            for (int l = 0; l < 10; l++) {
                const int j = lane + l * 32;
                float p = __expf(E[m * ESTR + j] - mx);
                pv[l] = p;
                ssum += p;
            }
#pragma unroll
            for (int o = 16; o; o >>= 1) ssum += __shfl_xor_sync(0xffffffffu, ssum, o);
            float inv = 1.f / ssum;
#pragma unroll
            for (int l = 0; l < 10; l++)
                Ph[m * PESTR + lane + l * 32] = __float2half(pv[l] * inv);
        }
    }
    __syncthreads();

    // ---------- phase 3: O[64][1024] = P[64][320] @ V[320][1024] (fp16) ----------
#define LOAD_V16(tstage, buf, d0v)                                                  \
    {                                                                               \
        const int t0 = (tstage) * 32;                                               \
        _Pragma("unroll")                                                           \
        for (int l = 0; l < 2; l++) {                                               \
            int slot = tid + l * 256;                                               \
            int trow = slot >> 4, c = slot & 15;                                    \
            int tr = ks0 + t0 + trow;                                               \
            tr = tr < 0 ? 0 : (tr > SEQ - 1 ? SEQ - 1 : tr);                        \
            cp16(smb + AVS_OFF + (buf) * AVS_STG + trow * (VPITCH * 2) + c * 16,    \
                 V + (brow + tr) * DIM + (d0v) + c * 8);                            \
        }                                                                           \
        CP_COMMIT();                                                                \
    }

    const int lj   = lane >> 3;                 // ldmatrix matrix index 0..3
    const int lrow = lane & 7;
    const int t_add = (lj & 1) * 8 + lrow;
    const int d_add = (lj >> 1) * 8;

#pragma unroll 1
    for (int nc = 0; nc < 8; nc++) {
        const int d0 = nc * 128;
        float acc[2][4][4];
#pragma unroll
        for (int i = 0; i < 2; i++)
#pragma unroll
            for (int j = 0; j < 4; j++)
#pragma unroll
                for (int k = 0; k < 4; k++) acc[i][j][k] = 0.f;

        LOAD_V16(0, 0, d0);
        LOAD_V16(1, 1, d0);

#pragma unroll 1
        for (int s = 0; s < 10; s++) {
            const int buf = s & 1;
            if (s + 1 < 10) { CP_WAIT1(); } else { CP_WAIT0(); }
            __syncthreads();
            const uint32_t Vb = smb + AVS_OFF + buf * AVS_STG;
#pragma unroll
            for (int ks = 0; ks < 2; ks++) {
                const int tg = s * 32 + ks * 16;
                uint32_t af[2][4];
#pragma unroll
                for (int mt = 0; mt < 2; mt++) {
                    const int r = wm * 32 + mt * 16 + gid;
                    af[mt][0] = *(const uint32_t*)&Ph[r * PESTR + tg + 2 * tig];
                    af[mt][1] = *(const uint32_t*)&Ph[(r + 8) * PESTR + tg + 2 * tig];
                    af[mt][2] = *(const uint32_t*)&Ph[r * PESTR + tg + 2 * tig + 8];
                    af[mt][3] = *(const uint32_t*)&Ph[(r + 8) * PESTR + tg + 2 * tig + 8];
                }
#pragma unroll
                for (int np = 0; np < 2; np++) {
                    const uint32_t addr = Vb +
                        (uint32_t)(ks * 16 + t_add) * (VPITCH * 2) +
                        (uint32_t)(wn * 32 + np * 16 + d_add) * 2;
                    uint32_t r0, r1, r2, r3;
                    ldsm4t(r0, r1, r2, r3, addr);
                    mma16(acc[0][np * 2 + 0], af[0][0], af[0][1], af[0][2], af[0][3], r0, r1);
                    mma16(acc[1][np * 2 + 0], af[1][0], af[1][1], af[1][2], af[1][3], r0, r1);
                    mma16(acc[0][np * 2 + 1], af[0][0], af[0][1], af[0][2], af[0][3], r2, r3);
                    mma16(acc[1][np * 2 + 1], af[1][0], af[1][1], af[1][2], af[1][3], r2, r3);
                }
            }
            __syncthreads();
            if (s + 2 < 10) LOAD_V16(s + 2, buf, d0);
        }

        // epilogue: fp16 out
#pragma unroll
        for (int mt = 0; mt < 2; mt++) {
            const int m0 = wm * 32 + mt * 16 + gid;
#pragma unroll
            for (int nt = 0; nt < 4; nt++) {
                const int col = d0 + wn * 32 + nt * 8 + tig * 2;
                __half2 h0 = __floats2half2_rn(acc[mt][nt][0], acc[mt][nt][1]);
                __half2 h1 = __floats2half2_rn(acc[mt][nt][2], acc[mt][nt][3]);
                *(uint32_t*)(O + (brow + s0 + m0) * DIM + col)     = *(uint32_t*)&h0;
                *(uint32_t*)(O + (brow + s0 + m0 + 8) * DIM + col) = *(uint32_t*)&h1;
            }
        }
    }
}

// ---------------- residual + LayerNorm (fp16 out) ----------------
__global__ __launch_bounds__(256)
void ln_kernel(const float* __restrict__ X, const float* __restrict__ R,
               const float* __restrict__ g, const float* __restrict__ bta,
               __half* __restrict__ Yh)
{
    const int r = blockIdx.x, tid = threadIdx.x;
    const size_t base = (size_t)r * DIM;
    float4 v = *(const float4*)(X + base + tid * 4);
    if (R) {
        float4 rv = *(const float4*)(R + base + tid * 4);
        v.x += rv.x; v.y += rv.y; v.z += rv.z; v.w += rv.w;
    }
    __shared__ float red[8];
    __shared__ float s_mu, s_inv;
    const int w = tid >> 5, lane = tid & 31;

    float s = v.x + v.y + v.z + v.w;
#pragma unroll
    for (int o = 16; o; o >>= 1) s += __shfl_xor_sync(0xffffffffu, s, o);
    if (lane == 0) red[w] = s;
    __syncthreads();
    if (tid == 0) {
        float t = 0.f;
#pragma unroll
        for (int i = 0; i < 8; i++) t += red[i];
        s_mu = t * (1.f / DIM);
    }
    __syncthreads();
    float mu = s_mu;

    float dx = v.x - mu, dy = v.y - mu, dz = v.z - mu, dw = v.w - mu;
    float ss = dx*dx + dy*dy + dz*dz + dw*dw;
#pragma unroll
    for (int o = 16; o; o >>= 1) ss += __shfl_xor_sync(0xffffffffu, ss, o);
    if (lane == 0) red[w] = ss;
    __syncthreads();
    if (tid == 0) {
        float t = 0.f;
#pragma unroll
        for (int i = 0; i < 8; i++) t += red[i];
        s_inv = rsqrtf(t * (1.f / DIM) + 1e-6f);
    }
    __syncthreads();
    float inv = s_inv;

    float4 gg = *(const float4*)(g + tid * 4);
    float4 bb = *(const float4*)(bta + tid * 4);
    float ox = dx * inv * gg.x + bb.x;
    float oy = dy * inv * gg.y + bb.y;
    float oz = dz * inv * gg.z + bb.z;
    float ow = dw * inv * gg.w + bb.w;
    __half2 h0 = __floats2half2_rn(ox, oy);
    __half2 h1 = __floats2half2_rn(oz, ow);
    uint2 u; u.x = *(uint32_t*)&h0; u.y = *(uint32_t*)&h1;
    *(uint2*)(Yh + base + tid * 4) = u;
}

// ---------------- fused LayerNorm + head: sigmoid(LN(x) . w + b) ----------------
__global__ __launch_bounds__(256)
void ln_head(const float* __restrict__ X,
             const float* __restrict__ g, const float* __restrict__ bta,
             const float* __restrict__ w, const float* __restrict__ bias,
             float* __restrict__ out)
{
    const int r = blockIdx.x, tid = threadIdx.x;
    const size_t base = (size_t)r * DIM;
    float4 v = *(const float4*)(X + base + tid * 4);
    __shared__ float red[8];
    __shared__ float s_mu, s_inv;
    const int wr = tid >> 5, lane = tid & 31;

    float s = v.x + v.y + v.z + v.w;
#pragma unroll
    for (int o = 16; o; o >>= 1) s += __shfl_xor_sync(0xffffffffu, s, o);
    if (lane == 0) red[wr] = s;
    __syncthreads();
    if (tid == 0) {
        float t = 0.f;
#pragma unroll
        for (int i = 0; i < 8; i++) t += red[i];
        s_mu = t * (1.f / DIM);
    }
    __syncthreads();
    float mu = s_mu;

    float dx = v.x - mu, dy = v.y - mu, dz = v.z - mu, dw = v.w - mu;
    float ss = dx*dx + dy*dy + dz*dz + dw*dw;
#pragma unroll
    for (int o = 16; o; o >>= 1) ss += __shfl_xor_sync(0xffffffffu, ss, o);
    if (lane == 0) red[wr] = ss;
    __syncthreads();
    if (tid == 0) {
        float t = 0.f;
#pragma unroll
        for (int i = 0; i < 8; i++) t += red[i];
        s_inv = rsqrtf(t * (1.f / DIM) + 1e-6f);
    }
    __syncthreads();
    float inv = s_inv;

    float4 gg = *(const float4*)(g + tid * 4);
    float4 bb = *(const float4*)(bta + tid * 4);
    float4 ww = *(const float4*)(w + tid * 4);
    float dot = (dx * inv * gg.x + bb.x) * ww.x
              + (dy * inv * gg.y + bb.y) * ww.y
              + (dz * inv * gg.z + bb.z) * ww.z
              + (dw * inv * gg.w + bb.w) * ww.w;
#pragma unroll
    for (int o = 16; o; o >>= 1) dot += __shfl_xor_sync(0xffffffffu, dot, o);
    if (lane == 0) red[wr] = dot;
    __syncthreads();
    if (tid == 0) {
        float t = 0.f;
#pragma unroll
        for (int i = 0; i < 8; i++) t += red[i];
        t += bias[0];
        out[r] = 1.f / (1.f + expf(-t));
    }
}

// ---------------- launch ----------------
extern "C" void kernel_launch(void* const* d_in, const int* in_sizes, int n_in,
                              void* d_out, int out_size)
{
    const float* x   = (const float*)d_in[0];
    const float* Wq  = (const float*)d_in[1];
    const float* Wk  = (const float*)d_in[2];
    const float* Wv  = (const float*)d_in[3];
    const float* Wo  = (const float*)d_in[4];
    const float* k1w = (const float*)d_in[5];
    const float* k1b = (const float*)d_in[6];
    const float* k2w = (const float*)d_in[7];
    const float* k2b = (const float*)d_in[8];
    const float* lng = (const float*)d_in[9];
    const float* lnb = (const float*)d_in[10];
    float* out = (float*)d_out;

    float  *gc, *gh;
    __half *x16, *q16, *k16, *v16, *a16, *y16;
    __half *wq16, *wk16, *wv16, *wo16, *w116;
    cudaGetSymbolAddress((void**)&gc,  g_c);
    cudaGetSymbolAddress((void**)&gh,  g_h);
    cudaGetSymbolAddress((void**)&x16, g_x16);
    cudaGetSymbolAddress((void**)&q16, g_q16);
    cudaGetSymbolAddress((void**)&k16, g_k16);
    cudaGetSymbolAddress((void**)&v16, g_v16);
    cudaGetSymbolAddress((void**)&a16, g_a16);
    cudaGetSymbolAddress((void**)&y16, g_y16);
    cudaGetSymbolAddress((void**)&wq16, g_wq16);
    cudaGetSymbolAddress((void**)&wk16, g_wk16);
    cudaGetSymbolAddress((void**)&wv16, g_wv16);
    cudaGetSymbolAddress((void**)&wo16, g_wo16);
    cudaGetSymbolAddress((void**)&w116, g_w116);

    cudaFuncSetAttribute(attn_tc, cudaFuncAttributeMaxDynamicSharedMemorySize,
                         ATT_SMEM_BYTES);
    cudaFuncSetAttribute(gemm_h, cudaFuncAttributeMaxDynamicSharedMemorySize,
                         GEMMH_SMEM);

    const int WBLK = (DIM * DIM) / 1024;
    conv16<<<(MTOT * DIM) / 1024, 256>>>(x, x16);
    conv16<<<WBLK, 256>>>(Wq,  wq16);
    conv16<<<WBLK, 256>>>(Wk,  wk16);
    conv16<<<WBLK, 256>>>(Wv,  wv16);
    conv16<<<WBLK, 256>>>(Wo,  wo16);
    conv16<<<WBLK, 256>>>(k1w, w116);

    dim3 gg(DIM / 128, MTOT / 128);   // (8, 128)

    gemm_h<<<gg, 256, GEMMH_SMEM>>>(x16, wq16, nullptr, nullptr, q16, 0);
    gemm_h<<<gg, 256, GEMMH_SMEM>>>(x16, wk16, nullptr, nullptr, k16, 0);
    gemm_h<<<gg, 256, GEMMH_SMEM>>>(x16, wv16, nullptr, nullptr, v16, 0);

    attn_tc<<<dim3(SEQ / QB, BATCH), 256, ATT_SMEM_BYTES>>>(q16, k16, v16, a16);

    gemm_h<<<gg, 256, GEMMH_SMEM>>>(a16, wo16, nullptr, gc, nullptr, 0);
    ln_kernel<<<MTOT, 256>>>(gc, x, lng, lnb, y16);
    gemm_h<<<gg, 256, GEMMH_SMEM>>>(y16, w116, k1b, gh, nullptr, 1);
    ln_head<<<MTOT, 256>>>(gh, lng, lnb, k2w, k2b, out);
}

// round 8
// speedup vs baseline: 5.7232x; 1.0459x over previous
#include <cuda_runtime.h>
#include <cuda_fp16.h>
#include <math.h>
#include <stdint.h>

#define BATCH 4
#define SEQ   4096
#define DIM   1024
#define MTOT  (BATCH*SEQ)
#define AP    128

// ---------------- scratch (device globals: allowed) ----------------
__device__ __half g_x16[(size_t)MTOT*DIM];
__device__ __half g_q16[(size_t)MTOT*DIM];
__device__ __half g_k16[(size_t)MTOT*DIM];
__device__ __half g_v16[(size_t)MTOT*DIM];
__device__ __half g_a16[(size_t)MTOT*DIM];    // attn out
__device__ __half g_y16[(size_t)MTOT*DIM];    // ln1 out
__device__ __half g_c16[(size_t)MTOT*DIM];    // Wo out
__device__ __half g_h16[(size_t)MTOT*DIM];    // k1 out
__device__ __half g_wq16[DIM*DIM], g_wk16[DIM*DIM], g_wv16[DIM*DIM];
__device__ __half g_wo16[DIM*DIM], g_w116[DIM*DIM];

// =================== PTX helpers ===================
__device__ __forceinline__ uint32_t s2u(const void* p) {
    uint32_t a;
    asm("{ .reg .u64 t; cvta.to.shared.u64 t, %1; cvt.u32.u64 %0, t; }" : "=r"(a) : "l"(p));
    return a;
}
__device__ __forceinline__ void cp16(uint32_t s, const void* g) {
    asm volatile("cp.async.cg.shared.global [%0], [%1], 16;" :: "r"(s), "l"(g));
}
#define CP_COMMIT() asm volatile("cp.async.commit_group;" ::: "memory")
#define CP_WAIT1()  asm volatile("cp.async.wait_group 1;" ::: "memory")
#define CP_WAIT0()  asm volatile("cp.async.wait_group 0;" ::: "memory")

__device__ __forceinline__ void mma16(float* c, uint32_t a0, uint32_t a1, uint32_t a2,
                                      uint32_t a3, uint32_t b0, uint32_t b1) {
    asm volatile(
        "mma.sync.aligned.m16n8k16.row.col.f32.f16.f16.f32 "
        "{%0,%1,%2,%3}, {%4,%5,%6,%7}, {%8,%9}, {%0,%1,%2,%3};"
        : "+f"(c[0]), "+f"(c[1]), "+f"(c[2]), "+f"(c[3])
        : "r"(a0), "r"(a1), "r"(a2), "r"(a3), "r"(b0), "r"(b1));
}
__device__ __forceinline__ void ldsm4t(uint32_t& r0, uint32_t& r1, uint32_t& r2,
                                       uint32_t& r3, uint32_t addr) {
    asm volatile("ldmatrix.sync.aligned.m8n8.x4.trans.shared.b16 {%0,%1,%2,%3}, [%4];"
                 : "=r"(r0), "=r"(r1), "=r"(r2), "=r"(r3) : "r"(addr));
}

// =================== fp32 -> fp16 conversion ===================
__global__ __launch_bounds__(256)
void conv16(const float* __restrict__ in, __half* __restrict__ out) {
    const size_t i = ((size_t)blockIdx.x * 256 + threadIdx.x) * 4;
    float4 v = *(const float4*)(in + i);
    __half2 h0 = __floats2half2_rn(v.x, v.y);
    __half2 h1 = __floats2half2_rn(v.z, v.w);
    uint2 u;
    u.x = *(uint32_t*)&h0; u.y = *(uint32_t*)&h1;
    *(uint2*)(out + i) = u;
}

// fused conversion of the 5 weight matrices (1024 blocks each)
__global__ __launch_bounds__(256)
void conv16w(const float* __restrict__ w0, const float* __restrict__ w1,
             const float* __restrict__ w2, const float* __restrict__ w3,
             const float* __restrict__ w4,
             __half* __restrict__ o0, __half* __restrict__ o1,
             __half* __restrict__ o2, __half* __restrict__ o3,
             __half* __restrict__ o4)
{
    const int wsel = blockIdx.x >> 10;
    const int blk  = blockIdx.x & 1023;
    const float* in; __half* out;
    switch (wsel) {
        case 0: in = w0; out = o0; break;
        case 1: in = w1; out = o1; break;
        case 2: in = w2; out = o2; break;
        case 3: in = w3; out = o3; break;
        default: in = w4; out = o4; break;
    }
    const size_t i = ((size_t)blk * 256 + threadIdx.x) * 4;
    float4 v = *(const float4*)(in + i);
    __half2 h0 = __floats2half2_rn(v.x, v.y);
    __half2 h1 = __floats2half2_rn(v.z, v.w);
    uint2 u;
    u.x = *(uint32_t*)&h0; u.y = *(uint32_t*)&h1;
    *(uint2*)(out + i) = u;
}

// =================== fp16 mma.sync GEMM ===================
#define HBK 64
#define HPITCH 72
#define HSTG_BYTES (128 * 144)
#define GEMMH_SMEM (4 * HSTG_BYTES)
#define HNSTAGE (DIM / HBK)

__global__ __launch_bounds__(256)
void gemm_h(const __half* __restrict__ A, const __half* __restrict__ Bw,
            const float* __restrict__ bias, __half* __restrict__ C16, int doRelu)
{
    extern __shared__ char smc[];
    const uint32_t As_u = s2u(smc);
    const uint32_t Bs_u = As_u + 2 * HSTG_BYTES;

    const int tid  = threadIdx.x;
    const int warp = tid >> 5, lane = tid & 31;
    const int wm = warp >> 2;
    const int wn = warp & 3;
    const int gid = lane >> 2;
    const int tig = lane & 3;
    const int bm = blockIdx.y * 128;
    const int bn = blockIdx.x * 128;

    float acc[4][4][4];
#pragma unroll
    for (int i = 0; i < 4; i++)
#pragma unroll
        for (int j = 0; j < 4; j++)
#pragma unroll
            for (int k = 0; k < 4; k++) acc[i][j][k] = 0.f;

#define LOADH(stage, buf)                                                        \
    {                                                                            \
        const int k0 = (stage) * HBK;                                            \
        _Pragma("unroll")                                                        \
        for (int l = 0; l < 4; l++) {                                            \
            int slot = tid + l * 256;                                            \
            int row = slot >> 3, c8 = slot & 7;                                  \
            uint32_t so = (uint32_t)(buf) * HSTG_BYTES + row * 144 + c8 * 16;    \
            cp16(As_u + so, A  + (size_t)(bm + row) * DIM + k0 + c8 * 8);        \
            cp16(Bs_u + so, Bw + (size_t)(bn + row) * DIM + k0 + c8 * 8);        \
        }                                                                        \
        CP_COMMIT();                                                             \
    }

    LOADH(0, 0);
    LOADH(1, 1);

#pragma unroll 1
    for (int s = 0; s < HNSTAGE; s++) {
        const int buf = s & 1;
        if (s + 1 < HNSTAGE) { CP_WAIT1(); } else { CP_WAIT0(); }
        __syncthreads();

        const __half* Ab = (const __half*)(smc + buf * HSTG_BYTES);
        const __half* Bb = (const __half*)(smc + 2 * HSTG_BYTES + buf * HSTG_BYTES);

#pragma unroll
        for (int ks = 0; ks < 4; ks++) {
            const int kb = ks * 16 + 2 * tig;
            uint32_t af[4][4], bf[4][2];
#pragma unroll
            for (int mt = 0; mt < 4; mt++) {
                const int r = wm * 64 + mt * 16 + gid;
                af[mt][0] = *(const uint32_t*)&Ab[r * HPITCH + kb];
                af[mt][1] = *(const uint32_t*)&Ab[(r + 8) * HPITCH + kb];
                af[mt][2] = *(const uint32_t*)&Ab[r * HPITCH + kb + 8];
                af[mt][3] = *(const uint32_t*)&Ab[(r + 8) * HPITCH + kb + 8];
            }
#pragma unroll
            for (int nt = 0; nt < 4; nt++) {
                const int r = wn * 32 + nt * 8 + gid;
                bf[nt][0] = *(const uint32_t*)&Bb[r * HPITCH + kb];
                bf[nt][1] = *(const uint32_t*)&Bb[r * HPITCH + kb + 8];
            }
#pragma unroll
            for (int mt = 0; mt < 4; mt++)
#pragma unroll
                for (int nt = 0; nt < 4; nt++)
                    mma16(acc[mt][nt], af[mt][0], af[mt][1], af[mt][2], af[mt][3],
                          bf[nt][0], bf[nt][1]);
        }
        __syncthreads();
        if (s + 2 < HNSTAGE) LOADH(s + 2, buf);
    }

#pragma unroll
    for (int mt = 0; mt < 4; mt++) {
#pragma unroll
        for (int nt = 0; nt < 4; nt++) {
            const int col = bn + wn * 32 + nt * 8 + tig * 2;
            float bx = 0.f, by = 0.f;
            if (bias) { bx = bias[col]; by = bias[col + 1]; }
            const int r0 = bm + wm * 64 + mt * 16 + gid;
            float2 v0 = make_float2(acc[mt][nt][0] + bx, acc[mt][nt][1] + by);
            float2 v1 = make_float2(acc[mt][nt][2] + bx, acc[mt][nt][3] + by);
            if (doRelu) {
                v0.x = fmaxf(v0.x, 0.f); v0.y = fmaxf(v0.y, 0.f);
                v1.x = fmaxf(v1.x, 0.f); v1.y = fmaxf(v1.y, 0.f);
            }
            __half2 h0 = __floats2half2_rn(v0.x, v0.y);
            __half2 h1 = __floats2half2_rn(v1.x, v1.y);
            *(uint32_t*)(C16 + (size_t)r0 * DIM + col)       = *(uint32_t*)&h0;
            *(uint32_t*)(C16 + (size_t)(r0 + 8) * DIM + col) = *(uint32_t*)&h1;
        }
    }
}

// =================== tensor-core banded attention (fp16 scores, 2 CTA/SM) ===================
// Scores computed in two 160-key passes (acc 40 regs), stored fp16 in P buffer.
#define QB    64
#define KW    320
#define KHALF 160
#define PESTR 330                               // fp16 score/P pitch
#define VPITCH 136                              // fp16 V pitch (ldmatrix)
// byte offsets in dynamic smem
#define PS_OFF    0
#define PS_BYTES  (QB * PESTR * 2)              // 42240
#define AQS_OFF   PS_BYTES                      // fp16 Q tiles: 2 x 9216
#define AQS_STG   (64 * 144)
#define AKS_OFF   (AQS_OFF + 2 * AQS_STG)       // fp16 K half tiles: 2 x 23040
#define AKS_STG   (KHALF * 144)
#define AVS_OFF   AQS_OFF                       // phase3 fp16 V tiles: 2 x 8704
#define AVS_STG   (32 * VPITCH * 2)
#define ATT_SMEM_BYTES (AKS_OFF + 2 * AKS_STG)  // 106752

__global__ __launch_bounds__(256, 2)
void attn_tc(const __half* __restrict__ Q, const __half* __restrict__ Kk,
             const __half* __restrict__ V, __half* __restrict__ O)
{
    extern __shared__ char smc[];
    __half* Ph = (__half*)(smc + PS_OFF);
    const uint32_t smb = s2u(smc);

    const int tid = threadIdx.x;
    const int warp = tid >> 5, lane = tid & 31;
    const int wm = warp >> 2;            // 0..1
    const int wn = warp & 3;             // 0..3
    const int gid = lane >> 2;           // 0..7
    const int tig = lane & 3;            // 0..3
    const int qb = blockIdx.x;
    const int b  = blockIdx.y;
    const int s0 = qb * QB;
    const int ks0 = s0 - AP;
    const size_t brow = (size_t)b * SEQ;
    const float scale = 0.03125f;
    const __half HNEG = __float2half(-60000.f);

    // ---------- phase 1: scores in two 160-key passes ----------
#define LOAD_QK(stage, buf, nbase)                                                  \
    {                                                                               \
        const int k0 = (stage) * HBK;                                               \
        _Pragma("unroll")                                                           \
        for (int l = 0; l < 2; l++) {                                               \
            int slot = tid + l * 256;                                               \
            int row = slot >> 3, c8 = slot & 7;                                     \
            cp16(smb + AQS_OFF + (buf) * AQS_STG + row * 144 + c8 * 16,             \
                 Q + (brow + s0 + row) * DIM + k0 + c8 * 8);                        \
        }                                                                           \
        _Pragma("unroll")                                                           \
        for (int l = 0; l < 5; l++) {                                               \
            int slot = tid + l * 256;                                               \
            int row = slot >> 3, c8 = slot & 7;                                     \
            int kr = ks0 + (nbase) + row;                                           \
            kr = kr < 0 ? 0 : (kr > SEQ - 1 ? SEQ - 1 : kr);                        \
            cp16(smb + AKS_OFF + (buf) * AKS_STG + row * 144 + c8 * 16,             \
                 Kk + (brow + kr) * DIM + k0 + c8 * 8);                             \
        }                                                                           \
        CP_COMMIT();                                                                \
    }

#pragma unroll 1
    for (int hf = 0; hf < 2; hf++) {
        const int nbase = hf * KHALF;
        float acc[2][5][4];
#pragma unroll
        for (int i = 0; i < 2; i++)
#pragma unroll
            for (int j = 0; j < 5; j++)
#pragma unroll
                for (int k = 0; k < 4; k++) acc[i][j][k] = 0.f;

        LOAD_QK(0, 0, nbase);
        LOAD_QK(1, 1, nbase);

#pragma unroll 1
        for (int s = 0; s < HNSTAGE; s++) {
            const int buf = s & 1;
            if (s + 1 < HNSTAGE) { CP_WAIT1(); } else { CP_WAIT0(); }
            __syncthreads();
            const __half* Qb = (const __half*)(smc + AQS_OFF + buf * AQS_STG);
            const __half* Kb = (const __half*)(smc + AKS_OFF + buf * AKS_STG);
#pragma unroll
            for (int ks = 0; ks < 4; ks++) {
                const int kb = ks * 16 + 2 * tig;
                uint32_t af[2][4];
#pragma unroll
                for (int mt = 0; mt < 2; mt++) {
                    const int r = wm * 32 + mt * 16 + gid;
                    af[mt][0] = *(const uint32_t*)&Qb[r * HPITCH + kb];
                    af[mt][1] = *(const uint32_t*)&Qb[(r + 8) * HPITCH + kb];
                    af[mt][2] = *(const uint32_t*)&Qb[r * HPITCH + kb + 8];
                    af[mt][3] = *(const uint32_t*)&Qb[(r + 8) * HPITCH + kb + 8];
                }
#pragma unroll
                for (int nt = 0; nt < 5; nt++) {
                    const int r = wn * 40 + nt * 8 + gid;
                    uint32_t b0 = *(const uint32_t*)&Kb[r * HPITCH + kb];
                    uint32_t b1 = *(const uint32_t*)&Kb[r * HPITCH + kb + 8];
                    mma16(acc[0][nt], af[0][0], af[0][1], af[0][2], af[0][3], b0, b1);
                    mma16(acc[1][nt], af[1][0], af[1][1], af[1][2], af[1][3], b0, b1);
                }
            }
            __syncthreads();
            if (s + 2 < HNSTAGE) LOAD_QK(s + 2, buf, nbase);
        }

        // write scores fp16 with scale + mask
#pragma unroll
        for (int mt = 0; mt < 2; mt++) {
            const int m0 = wm * 32 + mt * 16 + gid;
#pragma unroll
            for (int nt = 0; nt < 5; nt++) {
                const int n0 = nbase + wn * 40 + nt * 8 + tig * 2;
#pragma unroll
                for (int eh = 0; eh < 2; eh++) {
                    const int m = m0 + eh * 8;
                    const int s = s0 + m;
                    __half hv[2];
#pragma unroll
                    for (int e = 0; e < 2; e++) {
                        const int n = n0 + e;
                        const int t = ks0 + n;
                        bool valid = (t >= 0) && (t < SEQ) && (t != s) &&
                                     (t >= s - AP) && (t <= s + AP);
                        hv[e] = valid ? __float2half(acc[mt][nt][eh * 2 + e] * scale)
                                      : HNEG;
                    }
                    *(uint32_t*)&Ph[m * PESTR + n0] = *(uint32_t*)hv;
                }
            }
        }
        __syncthreads();
    }

    // ---------- phase 2: softmax (fp32 math on fp16 scores), P fp16 in place ----------
    {
        for (int rr = 0; rr < 8; rr++) {
            const int m = warp * 8 + rr;
            float pv[10];
            float mx = -1e30f;
#pragma unroll
            for (int l = 0; l < 10; l++) {
                pv[l] = __half2float(Ph[m * PESTR + lane + l * 32]);
                mx = fmaxf(mx, pv[l]);
            }
#pragma unroll
            for (int o = 16; o; o >>= 1) mx = fmaxf(mx, __shfl_xor_sync(0xffffffffu, mx, o));
            float ssum = 0.f;
#pragma unroll
            for (int l = 0; l < 10; l++) {
                float p = __expf(pv[l] - mx);
                pv[l] = p;
                ssum += p;
            }
#pragma unroll
            for (int o = 16; o; o >>= 1) ssum += __shfl_xor_sync(0xffffffffu, ssum, o);
            float inv = 1.f / ssum;
#pragma unroll
            for (int l = 0; l < 10; l++)
                Ph[m * PESTR + lane + l * 32] = __float2half(pv[l] * inv);
        }
    }
    __syncthreads();

    // ---------- phase 3: O[64][1024] = P[64][320] @ V[320][1024] (fp16) ----------
#define LOAD_V16(tstage, buf, d0v)                                                  \
    {                                                                               \
        const int t0 = (tstage) * 32;                                               \
        _Pragma("unroll")                                                           \
        for (int l = 0; l < 2; l++) {                                               \
            int slot = tid + l * 256;                                               \
            int trow = slot >> 4, c = slot & 15;                                    \
            int tr = ks0 + t0 + trow;                                               \
            tr = tr < 0 ? 0 : (tr > SEQ - 1 ? SEQ - 1 : tr);                        \
            cp16(smb + AVS_OFF + (buf) * AVS_STG + trow * (VPITCH * 2) + c * 16,    \
                 V + (brow + tr) * DIM + (d0v) + c * 8);                            \
        }                                                                           \
        CP_COMMIT();                                                                \
    }

    const int lj   = lane >> 3;
    const int lrow = lane & 7;
    const int t_add = (lj & 1) * 8 + lrow;
    const int d_add = (lj >> 1) * 8;

#pragma unroll 1
    for (int nc = 0; nc < 8; nc++) {
        const int d0 = nc * 128;
        float acc[2][4][4];
#pragma unroll
        for (int i = 0; i < 2; i++)
#pragma unroll
            for (int j = 0; j < 4; j++)
#pragma unroll
                for (int k = 0; k < 4; k++) acc[i][j][k] = 0.f;

        LOAD_V16(0, 0, d0);
        LOAD_V16(1, 1, d0);

#pragma unroll 1
        for (int s = 0; s < 10; s++) {
            const int buf = s & 1;
            if (s + 1 < 10) { CP_WAIT1(); } else { CP_WAIT0(); }
            __syncthreads();
            const uint32_t Vb = smb + AVS_OFF + buf * AVS_STG;
#pragma unroll
            for (int ks = 0; ks < 2; ks++) {
                const int tg = s * 32 + ks * 16;
                uint32_t af[2][4];
#pragma unroll
                for (int mt = 0; mt < 2; mt++) {
                    const int r = wm * 32 + mt * 16 + gid;
                    af[mt][0] = *(const uint32_t*)&Ph[r * PESTR + tg + 2 * tig];
                    af[mt][1] = *(const uint32_t*)&Ph[(r + 8) * PESTR + tg + 2 * tig];
                    af[mt][2] = *(const uint32_t*)&Ph[r * PESTR + tg + 2 * tig + 8];
                    af[mt][3] = *(const uint32_t*)&Ph[(r + 8) * PESTR + tg + 2 * tig + 8];
                }
#pragma unroll
                for (int np = 0; np < 2; np++) {
                    const uint32_t addr = Vb +
                        (uint32_t)(ks * 16 + t_add) * (VPITCH * 2) +
                        (uint32_t)(wn * 32 + np * 16 + d_add) * 2;
                    uint32_t r0, r1, r2, r3;
                    ldsm4t(r0, r1, r2, r3, addr);
                    mma16(acc[0][np * 2 + 0], af[0][0], af[0][1], af[0][2], af[0][3], r0, r1);
                    mma16(acc[1][np * 2 + 0], af[1][0], af[1][1], af[1][2], af[1][3], r0, r1);
                    mma16(acc[0][np * 2 + 1], af[0][0], af[0][1], af[0][2], af[0][3], r2, r3);
                    mma16(acc[1][np * 2 + 1], af[1][0], af[1][1], af[1][2], af[1][3], r2, r3);
                }
            }
            __syncthreads();
            if (s + 2 < 10) LOAD_V16(s + 2, buf, d0);
        }

#pragma unroll
        for (int mt = 0; mt < 2; mt++) {
            const int m0 = wm * 32 + mt * 16 + gid;
#pragma unroll
            for (int nt = 0; nt < 4; nt++) {
                const int col = d0 + wn * 32 + nt * 8 + tig * 2;
                __half2 h0 = __floats2half2_rn(acc[mt][nt][0], acc[mt][nt][1]);
                __half2 h1 = __floats2half2_rn(acc[mt][nt][2], acc[mt][nt][3]);
                *(uint32_t*)(O + (brow + s0 + m0) * DIM + col)     = *(uint32_t*)&h0;
                *(uint32_t*)(O + (brow + s0 + m0 + 8) * DIM + col) = *(uint32_t*)&h1;
            }
        }
    }
}

// ---------------- residual + LayerNorm (fp16 X, fp32 residual, fp16 out) ----------------
__global__ __launch_bounds__(256)
void ln_kernel(const __half* __restrict__ X, const float* __restrict__ R,
               const float* __restrict__ g, const float* __restrict__ bta,
               __half* __restrict__ Yh)
{
    const int r = blockIdx.x, tid = threadIdx.x;
    const size_t base = (size_t)r * DIM;
    uint2 xu = *(const uint2*)(X + base + tid * 4);
    __half2 xh0 = *(__half2*)&xu.x, xh1 = *(__half2*)&xu.y;
    float2 f0 = __half22float2(xh0), f1 = __half22float2(xh1);
    float4 v = make_float4(f0.x, f0.y, f1.x, f1.y);
    float4 rv = *(const float4*)(R + base + tid * 4);
    v.x += rv.x; v.y += rv.y; v.z += rv.z; v.w += rv.w;

    __shared__ float red[8];
    __shared__ float s_mu, s_inv;
    const int w = tid >> 5, lane = tid & 31;

    float s = v.x + v.y + v.z + v.w;
#pragma unroll
    for (int o = 16; o; o >>= 1) s += __shfl_xor_sync(0xffffffffu, s, o);
    if (lane == 0) red[w] = s;
    __syncthreads();
    if (tid == 0) {
        float t = 0.f;
#pragma unroll
        for (int i = 0; i < 8; i++) t += red[i];
        s_mu = t * (1.f / DIM);
    }
    __syncthreads();
    float mu = s_mu;

    float dx = v.x - mu, dy = v.y - mu, dz = v.z - mu, dw = v.w - mu;
    float ss = dx*dx + dy*dy + dz*dz + dw*dw;
#pragma unroll
    for (int o = 16; o; o >>= 1) ss += __shfl_xor_sync(0xffffffffu, ss, o);
    if (lane == 0) red[w] = ss;
    __syncthreads();
    if (tid == 0) {
        float t = 0.f;
#pragma unroll
        for (int i = 0; i < 8; i++) t += red[i];
        s_inv = rsqrtf(t * (1.f / DIM) + 1e-6f);
    }
    __syncthreads();
    float inv = s_inv;

    float4 gg = *(const float4*)(g + tid * 4);
    float4 bb = *(const float4*)(bta + tid * 4);
    float ox = dx * inv * gg.x + bb.x;
    float oy = dy * inv * gg.y + bb.y;
    float oz = dz * inv * gg.z + bb.z;
    float ow = dw * inv * gg.w + bb.w;
    __half2 h0 = __floats2half2_rn(ox, oy);
    __half2 h1 = __floats2half2_rn(oz, ow);
    uint2 u; u.x = *(uint32_t*)&h0; u.y = *(uint32_t*)&h1;
    *(uint2*)(Yh + base + tid * 4) = u;
}

// ---------------- fused LayerNorm + head (fp16 X) ----------------
__global__ __launch_bounds__(256)
void ln_head(const __half* __restrict__ X,
             const float* __restrict__ g, const float* __restrict__ bta,
             const float* __restrict__ w, const float* __restrict__ bias,
             float* __restrict__ out)
{
    const int r = blockIdx.x, tid = threadIdx.x;
    const size_t base = (size_t)r * DIM;
    uint2 xu = *(const uint2*)(X + base + tid * 4);
    __half2 xh0 = *(__half2*)&xu.x, xh1 = *(__half2*)&xu.y;
    float2 f0 = __half22float2(xh0), f1 = __half22float2(xh1);
    float4 v = make_float4(f0.x, f0.y, f1.x, f1.y);

    __shared__ float red[8];
    __shared__ float s_mu, s_inv;
    const int wr = tid >> 5, lane = tid & 31;

    float s = v.x + v.y + v.z + v.w;
#pragma unroll
    for (int o = 16; o; o >>= 1) s += __shfl_xor_sync(0xffffffffu, s, o);
    if (lane == 0) red[wr] = s;
    __syncthreads();
    if (tid == 0) {
        float t = 0.f;
#pragma unroll
        for (int i = 0; i < 8; i++) t += red[i];
        s_mu = t * (1.f / DIM);
    }
    __syncthreads();
    float mu = s_mu;

    float dx = v.x - mu, dy = v.y - mu, dz = v.z - mu, dw = v.w - mu;
    float ss = dx*dx + dy*dy + dz*dz + dw*dw;
#pragma unroll
    for (int o = 16; o; o >>= 1) ss += __shfl_xor_sync(0xffffffffu, ss, o);
    if (lane == 0) red[wr] = ss;
    __syncthreads();
    if (tid == 0) {
        float t = 0.f;
#pragma unroll
        for (int i = 0; i < 8; i++) t += red[i];
        s_inv = rsqrtf(t * (1.f / DIM) + 1e-6f);
    }
    __syncthreads();
    float inv = s_inv;

    float4 gg = *(const float4*)(g + tid * 4);
    float4 bb = *(const float4*)(bta + tid * 4);
    float4 ww = *(const float4*)(w + tid * 4);
    float dot = (dx * inv * gg.x + bb.x) * ww.x
              + (dy * inv * gg.y + bb.y) * ww.y
              + (dz * inv * gg.z + bb.z) * ww.z
              + (dw * inv * gg.w + bb.w) * ww.w;
#pragma unroll
    for (int o = 16; o; o >>= 1) dot += __shfl_xor_sync(0xffffffffu, dot, o);
    if (lane == 0) red[wr] = dot;
    __syncthreads();
    if (tid == 0) {
        float t = 0.f;
#pragma unroll
        for (int i = 0; i < 8; i++) t += red[i];
        t += bias[0];
        out[r] = 1.f / (1.f + expf(-t));
    }
}

// ---------------- launch ----------------
extern "C" void kernel_launch(void* const* d_in, const int* in_sizes, int n_in,
                              void* d_out, int out_size)
{
    const float* x   = (const float*)d_in[0];
    const float* Wq  = (const float*)d_in[1];
    const float* Wk  = (const float*)d_in[2];
    const float* Wv  = (const float*)d_in[3];
    const float* Wo  = (const float*)d_in[4];
    const float* k1w = (const float*)d_in[5];
    const float* k1b = (const float*)d_in[6];
    const float* k2w = (const float*)d_in[7];
    const float* k2b = (const float*)d_in[8];
    const float* lng = (const float*)d_in[9];
    const float* lnb = (const float*)d_in[10];
    float* out = (float*)d_out;

    __half *x16, *q16, *k16, *v16, *a16, *y16, *c16, *h16;
    __half *wq16, *wk16, *wv16, *wo16, *w116;
    cudaGetSymbolAddress((void**)&x16, g_x16);
    cudaGetSymbolAddress((void**)&q16, g_q16);
    cudaGetSymbolAddress((void**)&k16, g_k16);
    cudaGetSymbolAddress((void**)&v16, g_v16);
    cudaGetSymbolAddress((void**)&a16, g_a16);
    cudaGetSymbolAddress((void**)&y16, g_y16);
    cudaGetSymbolAddress((void**)&c16, g_c16);
    cudaGetSymbolAddress((void**)&h16, g_h16);
    cudaGetSymbolAddress((void**)&wq16, g_wq16);
    cudaGetSymbolAddress((void**)&wk16, g_wk16);
    cudaGetSymbolAddress((void**)&wv16, g_wv16);
    cudaGetSymbolAddress((void**)&wo16, g_wo16);
    cudaGetSymbolAddress((void**)&w116, g_w116);

    cudaFuncSetAttribute(attn_tc, cudaFuncAttributeMaxDynamicSharedMemorySize,
                         ATT_SMEM_BYTES);
    cudaFuncSetAttribute(gemm_h, cudaFuncAttributeMaxDynamicSharedMemorySize,
                         GEMMH_SMEM);

    conv16<<<(MTOT * DIM) / 1024, 256>>>(x, x16);
    conv16w<<<5 * 1024, 256>>>(Wq, Wk, Wv, Wo, k1w,
                               wq16, wk16, wv16, wo16, w116);

    dim3 gg(DIM / 128, MTOT / 128);   // (8, 128)

    gemm_h<<<gg, 256, GEMMH_SMEM>>>(x16, wq16, nullptr, q16, 0);
    gemm_h<<<gg, 256, GEMMH_SMEM>>>(x16, wk16, nullptr, k16, 0);
    gemm_h<<<gg, 256, GEMMH_SMEM>>>(x16, wv16, nullptr, v16, 0);

    attn_tc<<<dim3(SEQ / QB, BATCH), 256, ATT_SMEM_BYTES>>>(q16, k16, v16, a16);

    gemm_h<<<gg, 256, GEMMH_SMEM>>>(a16, wo16, nullptr, c16, 0);
    ln_kernel<<<MTOT, 256>>>(c16, x, lng, lnb, y16);
    gemm_h<<<gg, 256, GEMMH_SMEM>>>(y16, w116, k1b, h16, 1);
    ln_head<<<MTOT, 256>>>(h16, lng, lnb, k2w, k2b, out);
}

// round 10
// speedup vs baseline: 6.1580x; 1.0760x over previous
#include <cuda_runtime.h>
#include <cuda_fp16.h>
#include <math.h>
#include <stdint.h>

#define BATCH 4
#define SEQ   4096
#define DIM   1024
#define MTOT  (BATCH*SEQ)
#define AP    128

// ---------------- scratch (device globals: allowed) ----------------
__device__ __half g_x16[(size_t)MTOT*DIM];
__device__ __half g_q16[(size_t)MTOT*DIM];
__device__ __half g_k16[(size_t)MTOT*DIM];
__device__ __half g_v16[(size_t)MTOT*DIM];
__device__ __half g_a16[(size_t)MTOT*DIM];    // attn out
__device__ __half g_y16[(size_t)MTOT*DIM];    // ln1 out
__device__ __half g_c16[(size_t)MTOT*DIM];    // Wo out
__device__ __half g_h16[(size_t)MTOT*DIM];    // k1 out
__device__ __half g_wq16[DIM*DIM], g_wk16[DIM*DIM], g_wv16[DIM*DIM];
__device__ __half g_wo16[DIM*DIM], g_w116[DIM*DIM];

// =================== PTX helpers ===================
__device__ __forceinline__ uint32_t s2u(const void* p) {
    uint32_t a;
    asm("{ .reg .u64 t; cvta.to.shared.u64 t, %1; cvt.u32.u64 %0, t; }" : "=r"(a) : "l"(p));
    return a;
}
__device__ __forceinline__ void cp16(uint32_t s, const void* g) {
    asm volatile("cp.async.cg.shared.global [%0], [%1], 16;" :: "r"(s), "l"(g));
}
#define CP_COMMIT() asm volatile("cp.async.commit_group;" ::: "memory")
#define CP_WAIT1()  asm volatile("cp.async.wait_group 1;" ::: "memory")
#define CP_WAIT0()  asm volatile("cp.async.wait_group 0;" ::: "memory")

__device__ __forceinline__ void mma16(float* c, uint32_t a0, uint32_t a1, uint32_t a2,
                                      uint32_t a3, uint32_t b0, uint32_t b1) {
    asm volatile(
        "mma.sync.aligned.m16n8k16.row.col.f32.f16.f16.f32 "
        "{%0,%1,%2,%3}, {%4,%5,%6,%7}, {%8,%9}, {%0,%1,%2,%3};"
        : "+f"(c[0]), "+f"(c[1]), "+f"(c[2]), "+f"(c[3])
        : "r"(a0), "r"(a1), "r"(a2), "r"(a3), "r"(b0), "r"(b1));
}
__device__ __forceinline__ void ldsm4(uint32_t& r0, uint32_t& r1, uint32_t& r2,
                                      uint32_t& r3, uint32_t addr) {
    asm volatile("ldmatrix.sync.aligned.m8n8.x4.shared.b16 {%0,%1,%2,%3}, [%4];"
                 : "=r"(r0), "=r"(r1), "=r"(r2), "=r"(r3) : "r"(addr));
}
__device__ __forceinline__ void ldsm2(uint32_t& r0, uint32_t& r1, uint32_t addr) {
    asm volatile("ldmatrix.sync.aligned.m8n8.x2.shared.b16 {%0,%1}, [%2];"
                 : "=r"(r0), "=r"(r1) : "r"(addr));
}
__device__ __forceinline__ void ldsm4t(uint32_t& r0, uint32_t& r1, uint32_t& r2,
                                       uint32_t& r3, uint32_t addr) {
    asm volatile("ldmatrix.sync.aligned.m8n8.x4.trans.shared.b16 {%0,%1,%2,%3}, [%4];"
                 : "=r"(r0), "=r"(r1), "=r"(r2), "=r"(r3) : "r"(addr));
}

// =================== fp32 -> fp16 conversion ===================
__global__ __launch_bounds__(256)
void conv16(const float* __restrict__ in, __half* __restrict__ out) {
    const size_t i = ((size_t)blockIdx.x * 256 + threadIdx.x) * 4;
    float4 v = *(const float4*)(in + i);
    __half2 h0 = __floats2half2_rn(v.x, v.y);
    __half2 h1 = __floats2half2_rn(v.z, v.w);
    uint2 u;
    u.x = *(uint32_t*)&h0; u.y = *(uint32_t*)&h1;
    *(uint2*)(out + i) = u;
}

__global__ __launch_bounds__(256)
void conv16w(const float* __restrict__ w0, const float* __restrict__ w1,
             const float* __restrict__ w2, const float* __restrict__ w3,
             const float* __restrict__ w4,
             __half* __restrict__ o0, __half* __restrict__ o1,
             __half* __restrict__ o2, __half* __restrict__ o3,
             __half* __restrict__ o4)
{
    const int wsel = blockIdx.x >> 10;
    const int blk  = blockIdx.x & 1023;
    const float* in; __half* out;
    switch (wsel) {
        case 0: in = w0; out = o0; break;
        case 1: in = w1; out = o1; break;
        case 2: in = w2; out = o2; break;
        case 3: in = w3; out = o3; break;
        default: in = w4; out = o4; break;
    }
    const size_t i = ((size_t)blk * 256 + threadIdx.x) * 4;
    float4 v = *(const float4*)(in + i);
    __half2 h0 = __floats2half2_rn(v.x, v.y);
    __half2 h1 = __floats2half2_rn(v.z, v.w);
    uint2 u;
    u.x = *(uint32_t*)&h0; u.y = *(uint32_t*)&h1;
    *(uint2*)(out + i) = u;
}

// =================== fp16 mma.sync GEMM (ldmatrix fragments) ===================
#define HBK 64
#define HPITCH 72
#define HSTG_BYTES (128 * 144)
#define GEMMH_SMEM (4 * HSTG_BYTES)
#define HNSTAGE (DIM / HBK)

__global__ __launch_bounds__(256)
void gemm_h(const __half* __restrict__ A, const __half* __restrict__ Bw,
            const float* __restrict__ bias, __half* __restrict__ C16, int doRelu)
{
    extern __shared__ char smc[];
    const uint32_t As_u = s2u(smc);
    const uint32_t Bs_u = As_u + 2 * HSTG_BYTES;

    const int tid  = threadIdx.x;
    const int warp = tid >> 5, lane = tid & 31;
    const int wm = warp >> 2;
    const int wn = warp & 3;
    const int gid = lane >> 2;
    const int tig = lane & 3;
    const int bm = blockIdx.y * 128;
    const int bn = blockIdx.x * 128;

    // ldmatrix lane->address components
    const int aRow = (lane & 7) + ((lane >> 3) & 1) * 8;   // A row within m16
    const int aCol = (lane >> 4) * 8;                      // A k-half
    const int bRow = (lane & 7) + (lane >> 4) * 8;         // B row within nt-pair
    const int bCol = ((lane >> 3) & 1) * 8;                // B k-half

    float acc[4][4][4];
#pragma unroll
    for (int i = 0; i < 4; i++)
#pragma unroll
        for (int j = 0; j < 4; j++)
#pragma unroll
            for (int k = 0; k < 4; k++) acc[i][j][k] = 0.f;

#define LOADH(stage, buf)                                                        \
    {                                                                            \
        const int k0 = (stage) * HBK;                                            \
        _Pragma("unroll")                                                        \
        for (int l = 0; l < 4; l++) {                                            \
            int slot = tid + l * 256;                                            \
            int row = slot >> 3, c8 = slot & 7;                                  \
            uint32_t so = (uint32_t)(buf) * HSTG_BYTES + row * 144 + c8 * 16;    \
            cp16(As_u + so, A  + (size_t)(bm + row) * DIM + k0 + c8 * 8);        \
            cp16(Bs_u + so, Bw + (size_t)(bn + row) * DIM + k0 + c8 * 8);        \
        }                                                                        \
        CP_COMMIT();                                                             \
    }

    LOADH(0, 0);
    LOADH(1, 1);

#pragma unroll 1
    for (int s = 0; s < HNSTAGE; s++) {
        const int buf = s & 1;
        if (s + 1 < HNSTAGE) { CP_WAIT1(); } else { CP_WAIT0(); }
        __syncthreads();

        const uint32_t Ab_u = As_u + (uint32_t)buf * HSTG_BYTES;
        const uint32_t Bb_u = Bs_u + (uint32_t)buf * HSTG_BYTES;

#pragma unroll
        for (int ks = 0; ks < 4; ks++) {
            const int kb0 = ks * 16;
            uint32_t af[4][4], bf[4][2];
#pragma unroll
            for (int mt = 0; mt < 4; mt++) {
                uint32_t addr = Ab_u +
                    (uint32_t)((wm * 64 + mt * 16 + aRow) * HPITCH + kb0 + aCol) * 2;
                ldsm4(af[mt][0], af[mt][1], af[mt][2], af[mt][3], addr);
            }
#pragma unroll
            for (int p = 0; p < 2; p++) {
                uint32_t addr = Bb_u +
                    (uint32_t)((wn * 32 + p * 16 + bRow) * HPITCH + kb0 + bCol) * 2;
                ldsm4(bf[2*p][0], bf[2*p][1], bf[2*p+1][0], bf[2*p+1][1], addr);
            }
#pragma unroll
            for (int mt = 0; mt < 4; mt++)
#pragma unroll
                for (int nt = 0; nt < 4; nt++)
                    mma16(acc[mt][nt], af[mt][0], af[mt][1], af[mt][2], af[mt][3],
                          bf[nt][0], bf[nt][1]);
        }
        __syncthreads();
        if (s + 2 < HNSTAGE) LOADH(s + 2, buf);
    }

#pragma unroll
    for (int mt = 0; mt < 4; mt++) {
#pragma unroll
        for (int nt = 0; nt < 4; nt++) {
            const int col = bn + wn * 32 + nt * 8 + tig * 2;
            float bx = 0.f, by = 0.f;
            if (bias) { bx = bias[col]; by = bias[col + 1]; }
            const int r0 = bm + wm * 64 + mt * 16 + gid;
            float2 v0 = make_float2(acc[mt][nt][0] + bx, acc[mt][nt][1] + by);
            float2 v1 = make_float2(acc[mt][nt][2] + bx, acc[mt][nt][3] + by);
            if (doRelu) {
                v0.x = fmaxf(v0.x, 0.f); v0.y = fmaxf(v0.y, 0.f);
                v1.x = fmaxf(v1.x, 0.f); v1.y = fmaxf(v1.y, 0.f);
            }
            __half2 h0 = __floats2half2_rn(v0.x, v0.y);
            __half2 h1 = __floats2half2_rn(v1.x, v1.y);
            *(uint32_t*)(C16 + (size_t)r0 * DIM + col)       = *(uint32_t*)&h0;
            *(uint32_t*)(C16 + (size_t)(r0 + 8) * DIM + col) = *(uint32_t*)&h1;
        }
    }
}

// =================== tensor-core banded attention (fp16, ldmatrix, 2 CTA/SM) ===================
#define QB    64
#define KW    320
#define KHALF 160
#define PESTR 328                               // 656 B rows: 16B-aligned for ldmatrix
#define VPITCH 136
#define PS_OFF    0
#define PS_BYTES  (QB * PESTR * 2)              // 41984
#define AQS_OFF   PS_BYTES
#define AQS_STG   (64 * 144)
#define AKS_OFF   (AQS_OFF + 2 * AQS_STG)
#define AKS_STG   (KHALF * 144)
#define AVS_OFF   AQS_OFF
#define AVS_STG   (32 * VPITCH * 2)
#define ATT_SMEM_BYTES (AKS_OFF + 2 * AKS_STG)  // 106496

__global__ __launch_bounds__(256, 2)
void attn_tc(const __half* __restrict__ Q, const __half* __restrict__ Kk,
             const __half* __restrict__ V, __half* __restrict__ O)
{
    extern __shared__ char smc[];
    __half* Ph = (__half*)(smc + PS_OFF);
    const uint32_t smb = s2u(smc);

    const int tid = threadIdx.x;
    const int warp = tid >> 5, lane = tid & 31;
    const int wm = warp >> 2;
    const int wn = warp & 3;
    const int gid = lane >> 2;
    const int tig = lane & 3;
    const int qb = blockIdx.x;
    const int b  = blockIdx.y;
    const int s0 = qb * QB;
    const int ks0 = s0 - AP;
    const size_t brow = (size_t)b * SEQ;
    const float scale = 0.03125f;
    const __half HNEG = __float2half(-60000.f);

    const int aRow = (lane & 7) + ((lane >> 3) & 1) * 8;
    const int aCol = (lane >> 4) * 8;
    const int bRow = (lane & 7) + (lane >> 4) * 8;
    const int bCol = ((lane >> 3) & 1) * 8;
    const int b2Row = (lane & 7);
    const int b2Col = ((lane >> 3) & 1) * 8;

    // ---------- phase 1: scores in two 160-key passes ----------
#define LOAD_QK(stage, buf, nbase)                                                  \
    {                                                                               \
        const int k0 = (stage) * HBK;                                               \
        _Pragma("unroll")                                                           \
        for (int l = 0; l < 2; l++) {                                               \
            int slot = tid + l * 256;                                               \
            int row = slot >> 3, c8 = slot & 7;                                     \
            cp16(smb + AQS_OFF + (buf) * AQS_STG + row * 144 + c8 * 16,             \
                 Q + (brow + s0 + row) * DIM + k0 + c8 * 8);                        \
        }                                                                           \
        _Pragma("unroll")                                                           \
        for (int l = 0; l < 5; l++) {                                               \
            int slot = tid + l * 256;                                               \
            int row = slot >> 3, c8 = slot & 7;                                     \
            int kr = ks0 + (nbase) + row;                                           \
            kr = kr < 0 ? 0 : (kr > SEQ - 1 ? SEQ - 1 : kr);                        \
            cp16(smb + AKS_OFF + (buf) * AKS_STG + row * 144 + c8 * 16,             \
                 Kk + (brow + kr) * DIM + k0 + c8 * 8);                             \
        }                                                                           \
        CP_COMMIT();                                                                \
    }

#pragma unroll 1
    for (int hf = 0; hf < 2; hf++) {
        const int nbase = hf * KHALF;
        float acc[2][5][4];
#pragma unroll
        for (int i = 0; i < 2; i++)
#pragma unroll
            for (int j = 0; j < 5; j++)
#pragma unroll
                for (int k = 0; k < 4; k++) acc[i][j][k] = 0.f;

        LOAD_QK(0, 0, nbase);
        LOAD_QK(1, 1, nbase);

#pragma unroll 1
        for (int s = 0; s < HNSTAGE; s++) {
            const int buf = s & 1;
            if (s + 1 < HNSTAGE) { CP_WAIT1(); } else { CP_WAIT0(); }
            __syncthreads();
            const uint32_t Qb_u = smb + AQS_OFF + (uint32_t)buf * AQS_STG;
            const uint32_t Kb_u = smb + AKS_OFF + (uint32_t)buf * AKS_STG;
#pragma unroll
            for (int ks = 0; ks < 4; ks++) {
                const int kb0 = ks * 16;
                uint32_t af[2][4], bf[5][2];
#pragma unroll
                for (int mt = 0; mt < 2; mt++) {
                    uint32_t addr = Qb_u +
                        (uint32_t)((wm * 32 + mt * 16 + aRow) * HPITCH + kb0 + aCol) * 2;
                    ldsm4(af[mt][0], af[mt][1], af[mt][2], af[mt][3], addr);
                }
#pragma unroll
                for (int p = 0; p < 2; p++) {
                    uint32_t addr = Kb_u +
                        (uint32_t)((wn * 40 + p * 16 + bRow) * HPITCH + kb0 + bCol) * 2;
                    ldsm4(bf[2*p][0], bf[2*p][1], bf[2*p+1][0], bf[2*p+1][1], addr);
                }
                {
                    uint32_t addr = Kb_u +
                        (uint32_t)((wn * 40 + 32 + b2Row) * HPITCH + kb0 + b2Col) * 2;
                    ldsm2(bf[4][0], bf[4][1], addr);
                }
#pragma unroll
                for (int nt = 0; nt < 5; nt++) {
                    mma16(acc[0][nt], af[0][0], af[0][1], af[0][2], af[0][3],
                          bf[nt][0], bf[nt][1]);
                    mma16(acc[1][nt], af[1][0], af[1][1], af[1][2], af[1][3],
                          bf[nt][0], bf[nt][1]);
                }
            }
            __syncthreads();
            if (s + 2 < HNSTAGE) LOAD_QK(s + 2, buf, nbase);
        }

#pragma unroll
        for (int mt = 0; mt < 2; mt++) {
            const int m0 = wm * 32 + mt * 16 + gid;
#pragma unroll
            for (int nt = 0; nt < 5; nt++) {
                const int n0 = nbase + wn * 40 + nt * 8 + tig * 2;
#pragma unroll
                for (int eh = 0; eh < 2; eh++) {
                    const int m = m0 + eh * 8;
                    const int s = s0 + m;
                    __half hv[2];
#pragma unroll
                    for (int e = 0; e < 2; e++) {
                        const int n = n0 + e;
                        const int t = ks0 + n;
                        bool valid = (t >= 0) && (t < SEQ) && (t != s) &&
                                     (t >= s - AP) && (t <= s + AP);
                        hv[e] = valid ? __float2half(acc[mt][nt][eh * 2 + e] * scale)
                                      : HNEG;
                    }
                    *(uint32_t*)&Ph[m * PESTR + n0] = *(uint32_t*)hv;
                }
            }
        }
        __syncthreads();
    }

    // ---------- phase 2: softmax, P fp16 in place ----------
    {
        for (int rr = 0; rr < 8; rr++) {
            const int m = warp * 8 + rr;
            float pv[10];
            float mx = -1e30f;
#pragma unroll
            for (int l = 0; l < 10; l++) {
                pv[l] = __half2float(Ph[m * PESTR + lane + l * 32]);
                mx = fmaxf(mx, pv[l]);
            }
#pragma unroll
            for (int o = 16; o; o >>= 1) mx = fmaxf(mx, __shfl_xor_sync(0xffffffffu, mx, o));
            float ssum = 0.f;
#pragma unroll
            for (int l = 0; l < 10; l++) {
                float p = __expf(pv[l] - mx);
                pv[l] = p;
                ssum += p;
            }
#pragma unroll
            for (int o = 16; o; o >>= 1) ssum += __shfl_xor_sync(0xffffffffu, ssum, o);
            float inv = 1.f / ssum;
#pragma unroll
            for (int l = 0; l < 10; l++)
                Ph[m * PESTR + lane + l * 32] = __float2half(pv[l] * inv);
        }
    }
    __syncthreads();

    // ---------- phase 3: O = P @ V (fp16, ldmatrix both operands) ----------
#define LOAD_V16(tstage, buf, d0v)                                                  \
    {                                                                               \
        const int t0 = (tstage) * 32;                                               \
        _Pragma("unroll")                                                           \
        for (int l = 0; l < 2; l++) {                                               \
            int slot = tid + l * 256;                                               \
            int trow = slot >> 4, c = slot & 15;                                    \
            int tr = ks0 + t0 + trow;                                               \
            tr = tr < 0 ? 0 : (tr > SEQ - 1 ? SEQ - 1 : tr);                        \
            cp16(smb + AVS_OFF + (buf) * AVS_STG + trow * (VPITCH * 2) + c * 16,    \
                 V + (brow + tr) * DIM + (d0v) + c * 8);                            \
        }                                                                           \
        CP_COMMIT();                                                                \
    }

    const int lj   = lane >> 3;
    const int lrow = lane & 7;
    const int t_add = (lj & 1) * 8 + lrow;
    const int d_add = (lj >> 1) * 8;

#pragma unroll 1
    for (int nc = 0; nc < 8; nc++) {
        const int d0 = nc * 128;
        float acc[2][4][4];
#pragma unroll
        for (int i = 0; i < 2; i++)
#pragma unroll
            for (int j = 0; j < 4; j++)
#pragma unroll
                for (int k = 0; k < 4; k++) acc[i][j][k] = 0.f;

        LOAD_V16(0, 0, d0);
        LOAD_V16(1, 1, d0);

#pragma unroll 1
        for (int s = 0; s < 10; s++) {
            const int buf = s & 1;
            if (s + 1 < 10) { CP_WAIT1(); } else { CP_WAIT0(); }
            __syncthreads();
            const uint32_t Vb = smb + AVS_OFF + buf * AVS_STG;
#pragma unroll
            for (int ks = 0; ks < 2; ks++) {
                const int tg = s * 32 + ks * 16;
                uint32_t af[2][4];
#pragma unroll
                for (int mt = 0; mt < 2; mt++) {
                    uint32_t addr = smb +
                        (uint32_t)((wm * 32 + mt * 16 + aRow) * PESTR + tg + aCol) * 2;
                    ldsm4(af[mt][0], af[mt][1], af[mt][2], af[mt][3], addr);
                }
#pragma unroll
                for (int np = 0; np < 2; np++) {
                    const uint32_t addr = Vb +
                        (uint32_t)(ks * 16 + t_add) * (VPITCH * 2) +
                        (uint32_t)(wn * 32 + np * 16 + d_add) * 2;
                    uint32_t r0, r1, r2, r3;
                    ldsm4t(r0, r1, r2, r3, addr);
                    mma16(acc[0][np * 2 + 0], af[0][0], af[0][1], af[0][2], af[0][3], r0, r1);
                    mma16(acc[1][np * 2 + 0], af[1][0], af[1][1], af[1][2], af[1][3], r0, r1);
                    mma16(acc[0][np * 2 + 1], af[0][0], af[0][1], af[0][2], af[0][3], r2, r3);
                    mma16(acc[1][np * 2 + 1], af[1][0], af[1][1], af[1][2], af[1][3], r2, r3);
                }
            }
            __syncthreads();
            if (s + 2 < 10) LOAD_V16(s + 2, buf, d0);
        }

#pragma unroll
        for (int mt = 0; mt < 2; mt++) {
            const int m0 = wm * 32 + mt * 16 + gid;
#pragma unroll
            for (int nt = 0; nt < 4; nt++) {
                const int col = d0 + wn * 32 + nt * 8 + tig * 2;
                __half2 h0 = __floats2half2_rn(acc[mt][nt][0], acc[mt][nt][1]);
                __half2 h1 = __floats2half2_rn(acc[mt][nt][2], acc[mt][nt][3]);
                *(uint32_t*)(O + (brow + s0 + m0) * DIM + col)     = *(uint32_t*)&h0;
                *(uint32_t*)(O + (brow + s0 + m0 + 8) * DIM + col) = *(uint32_t*)&h1;
            }
        }
    }
}

// ---------------- residual + LayerNorm (fp16 X, fp32 residual, fp16 out) ----------------
__global__ __launch_bounds__(256)
void ln_kernel(const __half* __restrict__ X, const float* __restrict__ R,
               const float* __restrict__ g, const float* __restrict__ bta,
               __half* __restrict__ Yh)
{
    const int r = blockIdx.x, tid = threadIdx.x;
    const size_t base = (size_t)r * DIM;
    uint2 xu = *(const uint2*)(X + base + tid * 4);
    __half2 xh0 = *(__half2*)&xu.x, xh1 = *(__half2*)&xu.y;
    float2 f0 = __half22float2(xh0), f1 = __half22float2(xh1);
    float4 v = make_float4(f0.x, f0.y, f1.x, f1.y);
    float4 rv = *(const float4*)(R + base + tid * 4);
    v.x += rv.x; v.y += rv.y; v.z += rv.z; v.w += rv.w;

    __shared__ float red[8];
    __shared__ float s_mu, s_inv;
    const int w = tid >> 5, lane = tid & 31;

    float s = v.x + v.y + v.z + v.w;
#pragma unroll
    for (int o = 16; o; o >>= 1) s += __shfl_xor_sync(0xffffffffu, s, o);
    if (lane == 0) red[w] = s;
    __syncthreads();
    if (tid == 0) {
        float t = 0.f;
#pragma unroll
        for (int i = 0; i < 8; i++) t += red[i];
        s_mu = t * (1.f / DIM);
    }
    __syncthreads();
    float mu = s_mu;

    float dx = v.x - mu, dy = v.y - mu, dz = v.z - mu, dw = v.w - mu;
    float ss = dx*dx + dy*dy + dz*dz + dw*dw;
#pragma unroll
    for (int o = 16; o; o >>= 1) ss += __shfl_xor_sync(0xffffffffu, ss, o);
    if (lane == 0) red[w] = ss;
    __syncthreads();
    if (tid == 0) {
        float t = 0.f;
#pragma unroll
        for (int i = 0; i < 8; i++) t += red[i];
        s_inv = rsqrtf(t * (1.f / DIM) + 1e-6f);
    }
    __syncthreads();
    float inv = s_inv;

    float4 gg = *(const float4*)(g + tid * 4);
    float4 bb = *(const float4*)(bta + tid * 4);
    float ox = dx * inv * gg.x + bb.x;
    float oy = dy * inv * gg.y + bb.y;
    float oz = dz * inv * gg.z + bb.z;
    float ow = dw * inv * gg.w + bb.w;
    __half2 h0 = __floats2half2_rn(ox, oy);
    __half2 h1 = __floats2half2_rn(oz, ow);
    uint2 u; u.x = *(uint32_t*)&h0; u.y = *(uint32_t*)&h1;
    *(uint2*)(Yh + base + tid * 4) = u;
}

// ---------------- fused LayerNorm + head (fp16 X) ----------------
__global__ __launch_bounds__(256)
void ln_head(const __half* __restrict__ X,
             const float* __restrict__ g, const float* __restrict__ bta,
             const float* __restrict__ w, const float* __restrict__ bias,
             float* __restrict__ out)
{
    const int r = blockIdx.x, tid = threadIdx.x;
    const size_t base = (size_t)r * DIM;
    uint2 xu = *(const uint2*)(X + base + tid * 4);
    __half2 xh0 = *(__half2*)&xu.x, xh1 = *(__half2*)&xu.y;
    float2 f0 = __half22float2(xh0), f1 = __half22float2(xh1);
    float4 v = make_float4(f0.x, f0.y, f1.x, f1.y);

    __shared__ float red[8];
    __shared__ float s_mu, s_inv;
    const int wr = tid >> 5, lane = tid & 31;

    float s = v.x + v.y + v.z + v.w;
#pragma unroll
    for (int o = 16; o; o >>= 1) s += __shfl_xor_sync(0xffffffffu, s, o);
    if (lane == 0) red[wr] = s;
    __syncthreads();
    if (tid == 0) {
        float t = 0.f;
#pragma unroll
        for (int i = 0; i < 8; i++) t += red[i];
        s_mu = t * (1.f / DIM);
    }
    __syncthreads();
    float mu = s_mu;

    float dx = v.x - mu, dy = v.y - mu, dz = v.z - mu, dw = v.w - mu;
    float ss = dx*dx + dy*dy + dz*dz + dw*dw;
#pragma unroll
    for (int o = 16; o; o >>= 1) ss += __shfl_xor_sync(0xffffffffu, ss, o);
    if (lane == 0) red[wr] = ss;
    __syncthreads();
    if (tid == 0) {
        float t = 0.f;
#pragma unroll
        for (int i = 0; i < 8; i++) t += red[i];
        s_inv = rsqrtf(t * (1.f / DIM) + 1e-6f);
    }
    __syncthreads();
    float inv = s_inv;

    float4 gg = *(const float4*)(g + tid * 4);
    float4 bb = *(const float4*)(bta + tid * 4);
    float4 ww = *(const float4*)(w + tid * 4);
    float dot = (dx * inv * gg.x + bb.x) * ww.x
              + (dy * inv * gg.y + bb.y) * ww.y
              + (dz * inv * gg.z + bb.z) * ww.z
              + (dw * inv * gg.w + bb.w) * ww.w;
#pragma unroll
    for (int o = 16; o; o >>= 1) dot += __shfl_xor_sync(0xffffffffu, dot, o);
    if (lane == 0) red[wr] = dot;
    __syncthreads();
    if (tid == 0) {
        float t = 0.f;
#pragma unroll
        for (int i = 0; i < 8; i++) t += red[i];
        t += bias[0];
        out[r] = 1.f / (1.f + expf(-t));
    }
}

// ---------------- launch ----------------
extern "C" void kernel_launch(void* const* d_in, const int* in_sizes, int n_in,
                              void* d_out, int out_size)
{
    const float* x   = (const float*)d_in[0];
    const float* Wq  = (const float*)d_in[1];
    const float* Wk  = (const float*)d_in[2];
    const float* Wv  = (const float*)d_in[3];
    const float* Wo  = (const float*)d_in[4];
    const float* k1w = (const float*)d_in[5];
    const float* k1b = (const float*)d_in[6];
    const float* k2w = (const float*)d_in[7];
    const float* k2b = (const float*)d_in[8];
    const float* lng = (const float*)d_in[9];
    const float* lnb = (const float*)d_in[10];
    float* out = (float*)d_out;

    __half *x16, *q16, *k16, *v16, *a16, *y16, *c16, *h16;
    __half *wq16, *wk16, *wv16, *wo16, *w116;
    cudaGetSymbolAddress((void**)&x16, g_x16);
    cudaGetSymbolAddress((void**)&q16, g_q16);
    cudaGetSymbolAddress((void**)&k16, g_k16);
    cudaGetSymbolAddress((void**)&v16, g_v16);
    cudaGetSymbolAddress((void**)&a16, g_a16);
    cudaGetSymbolAddress((void**)&y16, g_y16);
    cudaGetSymbolAddress((void**)&c16, g_c16);
    cudaGetSymbolAddress((void**)&h16, g_h16);
    cudaGetSymbolAddress((void**)&wq16, g_wq16);
    cudaGetSymbolAddress((void**)&wk16, g_wk16);
    cudaGetSymbolAddress((void**)&wv16, g_wv16);
    cudaGetSymbolAddress((void**)&wo16, g_wo16);
    cudaGetSymbolAddress((void**)&w116, g_w116);

    cudaFuncSetAttribute(attn_tc, cudaFuncAttributeMaxDynamicSharedMemorySize,
                         ATT_SMEM_BYTES);
    cudaFuncSetAttribute(gemm_h, cudaFuncAttributeMaxDynamicSharedMemorySize,
                         GEMMH_SMEM);

    conv16<<<(MTOT * DIM) / 1024, 256>>>(x, x16);
    conv16w<<<5 * 1024, 256>>>(Wq, Wk, Wv, Wo, k1w,
                               wq16, wk16, wv16, wo16, w116);

    dim3 gg(DIM / 128, MTOT / 128);   // (8, 128)

    gemm_h<<<gg, 256, GEMMH_SMEM>>>(x16, wq16, nullptr, q16, 0);
    gemm_h<<<gg, 256, GEMMH_SMEM>>>(x16, wk16, nullptr, k16, 0);
    gemm_h<<<gg, 256, GEMMH_SMEM>>>(x16, wv16, nullptr, v16, 0);

    attn_tc<<<dim3(SEQ / QB, BATCH), 256, ATT_SMEM_BYTES>>>(q16, k16, v16, a16);

    gemm_h<<<gg, 256, GEMMH_SMEM>>>(a16, wo16, nullptr, c16, 0);
    ln_kernel<<<MTOT, 256>>>(c16, x, lng, lnb, y16);
    gemm_h<<<gg, 256, GEMMH_SMEM>>>(y16, w116, k1b, h16, 1);
    ln_head<<<MTOT, 256>>>(h16, lng, lnb, k2w, k2b, out);
}

// round 11
// speedup vs baseline: 6.4032x; 1.0398x over previous
#include <cuda_runtime.h>
#include <cuda_fp16.h>
#include <math.h>
#include <stdint.h>

#define BATCH 4
#define SEQ   4096
#define DIM   1024
#define MTOT  (BATCH*SEQ)
#define AP    128

// ---------------- scratch (device globals: allowed) ----------------
__device__ __half g_x16[(size_t)MTOT*DIM];
__device__ __half g_q16[(size_t)MTOT*DIM];
__device__ __half g_k16[(size_t)MTOT*DIM];
__device__ __half g_v16[(size_t)MTOT*DIM];
__device__ __half g_a16[(size_t)MTOT*DIM];    // attn out
__device__ __half g_y16[(size_t)MTOT*DIM];    // ln1 out
__device__ __half g_c16[(size_t)MTOT*DIM];    // Wo out
__device__ __half g_h16[(size_t)MTOT*DIM];    // k1 out
__device__ __half g_wq16[DIM*DIM], g_wk16[DIM*DIM], g_wv16[DIM*DIM];
__device__ __half g_wo16[DIM*DIM], g_w116[DIM*DIM];

// =================== PTX helpers ===================
__device__ __forceinline__ uint32_t s2u(const void* p) {
    uint32_t a;
    asm("{ .reg .u64 t; cvta.to.shared.u64 t, %1; cvt.u32.u64 %0, t; }" : "=r"(a) : "l"(p));
    return a;
}
__device__ __forceinline__ void cp16(uint32_t s, const void* g) {
    asm volatile("cp.async.cg.shared.global [%0], [%1], 16;" :: "r"(s), "l"(g));
}
#define CP_COMMIT() asm volatile("cp.async.commit_group;" ::: "memory")
#define CP_WAIT1()  asm volatile("cp.async.wait_group 1;" ::: "memory")
#define CP_WAIT0()  asm volatile("cp.async.wait_group 0;" ::: "memory")

__device__ __forceinline__ void mma16(float* c, uint32_t a0, uint32_t a1, uint32_t a2,
                                      uint32_t a3, uint32_t b0, uint32_t b1) {
    asm volatile(
        "mma.sync.aligned.m16n8k16.row.col.f32.f16.f16.f32 "
        "{%0,%1,%2,%3}, {%4,%5,%6,%7}, {%8,%9}, {%0,%1,%2,%3};"
        : "+f"(c[0]), "+f"(c[1]), "+f"(c[2]), "+f"(c[3])
        : "r"(a0), "r"(a1), "r"(a2), "r"(a3), "r"(b0), "r"(b1));
}
__device__ __forceinline__ void ldsm4(uint32_t& r0, uint32_t& r1, uint32_t& r2,
                                      uint32_t& r3, uint32_t addr) {
    asm volatile("ldmatrix.sync.aligned.m8n8.x4.shared.b16 {%0,%1,%2,%3}, [%4];"
                 : "=r"(r0), "=r"(r1), "=r"(r2), "=r"(r3) : "r"(addr));
}
__device__ __forceinline__ void ldsm2(uint32_t& r0, uint32_t& r1, uint32_t addr) {
    asm volatile("ldmatrix.sync.aligned.m8n8.x2.shared.b16 {%0,%1}, [%2];"
                 : "=r"(r0), "=r"(r1) : "r"(addr));
}
__device__ __forceinline__ void ldsm4t(uint32_t& r0, uint32_t& r1, uint32_t& r2,
                                       uint32_t& r3, uint32_t addr) {
    asm volatile("ldmatrix.sync.aligned.m8n8.x4.trans.shared.b16 {%0,%1,%2,%3}, [%4];"
                 : "=r"(r0), "=r"(r1), "=r"(r2), "=r"(r3) : "r"(addr));
}

// =================== fp32 -> fp16 conversion ===================
__global__ __launch_bounds__(256)
void conv16(const float* __restrict__ in, __half* __restrict__ out) {
    const size_t i = ((size_t)blockIdx.x * 256 + threadIdx.x) * 4;
    float4 v = *(const float4*)(in + i);
    __half2 h0 = __floats2half2_rn(v.x, v.y);
    __half2 h1 = __floats2half2_rn(v.z, v.w);
    uint2 u;
    u.x = *(uint32_t*)&h0; u.y = *(uint32_t*)&h1;
    *(uint2*)(out + i) = u;
}

__global__ __launch_bounds__(256)
void conv16w(const float* __restrict__ w0, const float* __restrict__ w1,
             const float* __restrict__ w2, const float* __restrict__ w3,
             const float* __restrict__ w4,
             __half* __restrict__ o0, __half* __restrict__ o1,
             __half* __restrict__ o2, __half* __restrict__ o3,
             __half* __restrict__ o4)
{
    const int wsel = blockIdx.x >> 10;
    const int blk  = blockIdx.x & 1023;
    const float* in; __half* out;
    switch (wsel) {
        case 0: in = w0; out = o0; break;
        case 1: in = w1; out = o1; break;
        case 2: in = w2; out = o2; break;
        case 3: in = w3; out = o3; break;
        default: in = w4; out = o4; break;
    }
    const size_t i = ((size_t)blk * 256 + threadIdx.x) * 4;
    float4 v = *(const float4*)(in + i);
    __half2 h0 = __floats2half2_rn(v.x, v.y);
    __half2 h1 = __floats2half2_rn(v.z, v.w);
    uint2 u;
    u.x = *(uint32_t*)&h0; u.y = *(uint32_t*)&h1;
    *(uint2*)(out + i) = u;
}

// =================== fp16 mma.sync GEMM (3-stage ring, 1 barrier/stage) ===================
#define HBK 64
#define HPITCH 72
#define HSTG_BYTES (128 * 144)
#define GSTAGES 3
#define GEMM_SMEM (2 * GSTAGES * HSTG_BYTES)    // 110592
#define HNSTAGE (DIM / HBK)                      // 16

__global__ __launch_bounds__(256)
void gemm_h(const __half* __restrict__ A, const __half* __restrict__ Bw,
            const float* __restrict__ bias, __half* __restrict__ C16, int doRelu)
{
    extern __shared__ char smc[];
    const uint32_t As_u = s2u(smc);
    const uint32_t Bs_u = As_u + GSTAGES * HSTG_BYTES;

    const int tid  = threadIdx.x;
    const int warp = tid >> 5, lane = tid & 31;
    const int wm = warp >> 2;
    const int wn = warp & 3;
    const int gid = lane >> 2;
    const int tig = lane & 3;
    const int bm = blockIdx.y * 128;
    const int bn = blockIdx.x * 128;

    // ldmatrix lane->address components
    const int aRow = (lane & 7) + ((lane >> 3) & 1) * 8;
    const int aCol = (lane >> 4) * 8;
    const int bRow = (lane & 7) + (lane >> 4) * 8;
    const int bCol = ((lane >> 3) & 1) * 8;

    float acc[4][4][4];
#pragma unroll
    for (int i = 0; i < 4; i++)
#pragma unroll
        for (int j = 0; j < 4; j++)
#pragma unroll
            for (int k = 0; k < 4; k++) acc[i][j][k] = 0.f;

#define LOADH(stage, buf)                                                        \
    {                                                                            \
        const int k0 = (stage) * HBK;                                            \
        _Pragma("unroll")                                                        \
        for (int l = 0; l < 4; l++) {                                            \
            int slot = tid + l * 256;                                            \
            int row = slot >> 3, c8 = slot & 7;                                  \
            uint32_t so = (uint32_t)(buf) * HSTG_BYTES + row * 144 + c8 * 16;    \
            cp16(As_u + so, A  + (size_t)(bm + row) * DIM + k0 + c8 * 8);        \
            cp16(Bs_u + so, Bw + (size_t)(bn + row) * DIM + k0 + c8 * 8);        \
        }                                                                        \
        CP_COMMIT();                                                             \
    }

    LOADH(0, 0);
    LOADH(1, 1);

    int buf = 0;              // buffer of current stage
    int nbuf = 2;             // buffer that the next prefetch writes
#pragma unroll 1
    for (int s = 0; s < HNSTAGE; s++) {
        if (s + 1 < HNSTAGE) { CP_WAIT1(); } else { CP_WAIT0(); }
        __syncthreads();
        // prefetch s+2 into buf (s+2)%3 == (s-1)%3: all warps finished reading it
        // before the barrier above.
        if (s + 2 < HNSTAGE) LOADH(s + 2, nbuf);

        const uint32_t Ab_u = As_u + (uint32_t)buf * HSTG_BYTES;
        const uint32_t Bb_u = Bs_u + (uint32_t)buf * HSTG_BYTES;

#pragma unroll
        for (int ks = 0; ks < 4; ks++) {
            const int kb0 = ks * 16;
            uint32_t af[4][4], bf[4][2];
#pragma unroll
            for (int mt = 0; mt < 4; mt++) {
                uint32_t addr = Ab_u +
                    (uint32_t)((wm * 64 + mt * 16 + aRow) * HPITCH + kb0 + aCol) * 2;
                ldsm4(af[mt][0], af[mt][1], af[mt][2], af[mt][3], addr);
            }
#pragma unroll
            for (int p = 0; p < 2; p++) {
                uint32_t addr = Bb_u +
                    (uint32_t)((wn * 32 + p * 16 + bRow) * HPITCH + kb0 + bCol) * 2;
                ldsm4(bf[2*p][0], bf[2*p][1], bf[2*p+1][0], bf[2*p+1][1], addr);
            }
#pragma unroll
            for (int mt = 0; mt < 4; mt++)
#pragma unroll
                for (int nt = 0; nt < 4; nt++)
                    mma16(acc[mt][nt], af[mt][0], af[mt][1], af[mt][2], af[mt][3],
                          bf[nt][0], bf[nt][1]);
        }
        buf  = (buf  == GSTAGES - 1) ? 0 : buf + 1;
        nbuf = (nbuf == GSTAGES - 1) ? 0 : nbuf + 1;
    }

#pragma unroll
    for (int mt = 0; mt < 4; mt++) {
#pragma unroll
        for (int nt = 0; nt < 4; nt++) {
            const int col = bn + wn * 32 + nt * 8 + tig * 2;
            float bx = 0.f, by = 0.f;
            if (bias) { bx = bias[col]; by = bias[col + 1]; }
            const int r0 = bm + wm * 64 + mt * 16 + gid;
            float2 v0 = make_float2(acc[mt][nt][0] + bx, acc[mt][nt][1] + by);
            float2 v1 = make_float2(acc[mt][nt][2] + bx, acc[mt][nt][3] + by);
            if (doRelu) {
                v0.x = fmaxf(v0.x, 0.f); v0.y = fmaxf(v0.y, 0.f);
                v1.x = fmaxf(v1.x, 0.f); v1.y = fmaxf(v1.y, 0.f);
            }
            __half2 h0 = __floats2half2_rn(v0.x, v0.y);
            __half2 h1 = __floats2half2_rn(v1.x, v1.y);
            *(uint32_t*)(C16 + (size_t)r0 * DIM + col)       = *(uint32_t*)&h0;
            *(uint32_t*)(C16 + (size_t)(r0 + 8) * DIM + col) = *(uint32_t*)&h1;
        }
    }
}

// =================== tensor-core banded attention (fp16, ldmatrix, 2 CTA/SM) ===================
#define QB    64
#define KW    320
#define KHALF 160
#define PESTR 328
#define VPITCH 136
#define PS_OFF    0
#define PS_BYTES  (QB * PESTR * 2)
#define AQS_OFF   PS_BYTES
#define AQS_STG   (64 * 144)
#define AKS_OFF   (AQS_OFF + 2 * AQS_STG)
#define AKS_STG   (KHALF * 144)
#define AVS_OFF   AQS_OFF
#define AVS_STG   (32 * VPITCH * 2)
#define ATT_SMEM_BYTES (AKS_OFF + 2 * AKS_STG)  // 106496

__global__ __launch_bounds__(256, 2)
void attn_tc(const __half* __restrict__ Q, const __half* __restrict__ Kk,
             const __half* __restrict__ V, __half* __restrict__ O)
{
    extern __shared__ char smc[];
    __half* Ph = (__half*)(smc + PS_OFF);
    const uint32_t smb = s2u(smc);

    const int tid = threadIdx.x;
    const int warp = tid >> 5, lane = tid & 31;
    const int wm = warp >> 2;
    const int wn = warp & 3;
    const int gid = lane >> 2;
    const int tig = lane & 3;
    const int qb = blockIdx.x;
    const int b  = blockIdx.y;
    const int s0 = qb * QB;
    const int ks0 = s0 - AP;
    const size_t brow = (size_t)b * SEQ;
    const float scale = 0.03125f;
    const __half HNEG = __float2half(-60000.f);

    const int aRow = (lane & 7) + ((lane >> 3) & 1) * 8;
    const int aCol = (lane >> 4) * 8;
    const int bRow = (lane & 7) + (lane >> 4) * 8;
    const int bCol = ((lane >> 3) & 1) * 8;
    const int b2Row = (lane & 7);
    const int b2Col = ((lane >> 3) & 1) * 8;

    // ---------- phase 1: scores in two 160-key passes ----------
#define LOAD_QK(stage, buf, nbase)                                                  \
    {                                                                               \
        const int k0 = (stage) * HBK;                                               \
        _Pragma("unroll")                                                           \
        for (int l = 0; l < 2; l++) {                                               \
            int slot = tid + l * 256;                                               \
            int row = slot >> 3, c8 = slot & 7;                                     \
            cp16(smb + AQS_OFF + (buf) * AQS_STG + row * 144 + c8 * 16,             \
                 Q + (brow + s0 + row) * DIM + k0 + c8 * 8);                        \
        }                                                                           \
        _Pragma("unroll")                                                           \
        for (int l = 0; l < 5; l++) {                                               \
            int slot = tid + l * 256;                                               \
            int row = slot >> 3, c8 = slot & 7;                                     \
            int kr = ks0 + (nbase) + row;                                           \
            kr = kr < 0 ? 0 : (kr > SEQ - 1 ? SEQ - 1 : kr);                        \
            cp16(smb + AKS_OFF + (buf) * AKS_STG + row * 144 + c8 * 16,             \
                 Kk + (brow + kr) * DIM + k0 + c8 * 8);                             \
        }                                                                           \
        CP_COMMIT();                                                                \
    }

#pragma unroll 1
    for (int hf = 0; hf < 2; hf++) {
        const int nbase = hf * KHALF;
        float acc[2][5][4];
#pragma unroll
        for (int i = 0; i < 2; i++)
#pragma unroll
            for (int j = 0; j < 5; j++)
#pragma unroll
                for (int k = 0; k < 4; k++) acc[i][j][k] = 0.f;

        LOAD_QK(0, 0, nbase);
        LOAD_QK(1, 1, nbase);

#pragma unroll 1
        for (int s = 0; s < HNSTAGE; s++) {
            const int buf = s & 1;
            if (s + 1 < HNSTAGE) { CP_WAIT1(); } else { CP_WAIT0(); }
            __syncthreads();
            const uint32_t Qb_u = smb + AQS_OFF + (uint32_t)buf * AQS_STG;
            const uint32_t Kb_u = smb + AKS_OFF + (uint32_t)buf * AKS_STG;
#pragma unroll
            for (int ks = 0; ks < 4; ks++) {
                const int kb0 = ks * 16;
                uint32_t af[2][4], bf[5][2];
#pragma unroll
                for (int mt = 0; mt < 2; mt++) {
                    uint32_t addr = Qb_u +
                        (uint32_t)((wm * 32 + mt * 16 + aRow) * HPITCH + kb0 + aCol) * 2;
                    ldsm4(af[mt][0], af[mt][1], af[mt][2], af[mt][3], addr);
                }
#pragma unroll
                for (int p = 0; p < 2; p++) {
                    uint32_t addr = Kb_u +
                        (uint32_t)((wn * 40 + p * 16 + bRow) * HPITCH + kb0 + bCol) * 2;
                    ldsm4(bf[2*p][0], bf[2*p][1], bf[2*p+1][0], bf[2*p+1][1], addr);
                }
                {
                    uint32_t addr = Kb_u +
                        (uint32_t)((wn * 40 + 32 + b2Row) * HPITCH + kb0 + b2Col) * 2;
                    ldsm2(bf[4][0], bf[4][1], addr);
                }
#pragma unroll
                for (int nt = 0; nt < 5; nt++) {
                    mma16(acc[0][nt], af[0][0], af[0][1], af[0][2], af[0][3],
                          bf[nt][0], bf[nt][1]);
                    mma16(acc[1][nt], af[1][0], af[1][1], af[1][2], af[1][3],
                          bf[nt][0], bf[nt][1]);
                }
            }
            __syncthreads();
            if (s + 2 < HNSTAGE) LOAD_QK(s + 2, buf, nbase);
        }

#pragma unroll
        for (int mt = 0; mt < 2; mt++) {
            const int m0 = wm * 32 + mt * 16 + gid;
#pragma unroll
            for (int nt = 0; nt < 5; nt++) {
                const int n0 = nbase + wn * 40 + nt * 8 + tig * 2;
#pragma unroll
                for (int eh = 0; eh < 2; eh++) {
                    const int m = m0 + eh * 8;
                    const int s = s0 + m;
                    __half hv[2];
#pragma unroll
                    for (int e = 0; e < 2; e++) {
                        const int n = n0 + e;
                        const int t = ks0 + n;
                        bool valid = (t >= 0) && (t < SEQ) && (t != s) &&
                                     (t >= s - AP) && (t <= s + AP);
                        hv[e] = valid ? __float2half(acc[mt][nt][eh * 2 + e] * scale)
                                      : HNEG;
                    }
                    *(uint32_t*)&Ph[m * PESTR + n0] = *(uint32_t*)hv;
                }
            }
        }
        __syncthreads();
    }

    // ---------- phase 2: softmax, P fp16 in place ----------
    {
        for (int rr = 0; rr < 8; rr++) {
            const int m = warp * 8 + rr;
            float pv[10];
            float mx = -1e30f;
#pragma unroll
            for (int l = 0; l < 10; l++) {
                pv[l] = __half2float(Ph[m * PESTR + lane + l * 32]);
                mx = fmaxf(mx, pv[l]);
            }
#pragma unroll
            for (int o = 16; o; o >>= 1) mx = fmaxf(mx, __shfl_xor_sync(0xffffffffu, mx, o));
            float ssum = 0.f;
#pragma unroll
            for (int l = 0; l < 10; l++) {
                float p = __expf(pv[l] - mx);
                pv[l] = p;
                ssum += p;
            }
#pragma unroll
            for (int o = 16; o; o >>= 1) ssum += __shfl_xor_sync(0xffffffffu, ssum, o);
            float inv = 1.f / ssum;
#pragma unroll
            for (int l = 0; l < 10; l++)
                Ph[m * PESTR + lane + l * 32] = __float2half(pv[l] * inv);
        }
    }
    __syncthreads();

    // ---------- phase 3: O = P @ V (fp16, ldmatrix both operands) ----------
#define LOAD_V16(tstage, buf, d0v)                                                  \
    {                                                                               \
        const int t0 = (tstage) * 32;                                               \
        _Pragma("unroll")                                                           \
        for (int l = 0; l < 2; l++) {                                               \
            int slot = tid + l * 256;                                               \
            int trow = slot >> 4, c = slot & 15;                                    \
            int tr = ks0 + t0 + trow;                                               \
            tr = tr < 0 ? 0 : (tr > SEQ - 1 ? SEQ - 1 : tr);                        \
            cp16(smb + AVS_OFF + (buf) * AVS_STG + trow * (VPITCH * 2) + c * 16,    \
                 V + (brow + tr) * DIM + (d0v) + c * 8);                            \
        }                                                                           \
        CP_COMMIT();                                                                \
    }

    const int lj   = lane >> 3;
    const int lrow = lane & 7;
    const int t_add = (lj & 1) * 8 + lrow;
    const int d_add = (lj >> 1) * 8;

#pragma unroll 1
    for (int nc = 0; nc < 8; nc++) {
        const int d0 = nc * 128;
        float acc[2][4][4];
#pragma unroll
        for (int i = 0; i < 2; i++)
#pragma unroll
            for (int j = 0; j < 4; j++)
#pragma unroll
                for (int k = 0; k < 4; k++) acc[i][j][k] = 0.f;

        LOAD_V16(0, 0, d0);
        LOAD_V16(1, 1, d0);

#pragma unroll 1
        for (int s = 0; s < 10; s++) {
            const int buf = s & 1;
            if (s + 1 < 10) { CP_WAIT1(); } else { CP_WAIT0(); }
            __syncthreads();
            const uint32_t Vb = smb + AVS_OFF + buf * AVS_STG;
#pragma unroll
            for (int ks = 0; ks < 2; ks++) {
                const int tg = s * 32 + ks * 16;
                uint32_t af[2][4];
#pragma unroll
                for (int mt = 0; mt < 2; mt++) {
                    uint32_t addr = smb +
                        (uint32_t)((wm * 32 + mt * 16 + aRow) * PESTR + tg + aCol) * 2;
                    ldsm4(af[mt][0], af[mt][1], af[mt][2], af[mt][3], addr);
                }
#pragma unroll
                for (int np = 0; np < 2; np++) {
                    const uint32_t addr = Vb +
                        (uint32_t)(ks * 16 + t_add) * (VPITCH * 2) +
                        (uint32_t)(wn * 32 + np * 16 + d_add) * 2;
                    uint32_t r0, r1, r2, r3;
                    ldsm4t(r0, r1, r2, r3, addr);
                    mma16(acc[0][np * 2 + 0], af[0][0], af[0][1], af[0][2], af[0][3], r0, r1);
                    mma16(acc[1][np * 2 + 0], af[1][0], af[1][1], af[1][2], af[1][3], r0, r1);
                    mma16(acc[0][np * 2 + 1], af[0][0], af[0][1], af[0][2], af[0][3], r2, r3);
                    mma16(acc[1][np * 2 + 1], af[1][0], af[1][1], af[1][2], af[1][3], r2, r3);
                }
            }
            __syncthreads();
            if (s + 2 < 10) LOAD_V16(s + 2, buf, d0);
        }

#pragma unroll
        for (int mt = 0; mt < 2; mt++) {
            const int m0 = wm * 32 + mt * 16 + gid;
#pragma unroll
            for (int nt = 0; nt < 4; nt++) {
                const int col = d0 + wn * 32 + nt * 8 + tig * 2;
                __half2 h0 = __floats2half2_rn(acc[mt][nt][0], acc[mt][nt][1]);
                __half2 h1 = __floats2half2_rn(acc[mt][nt][2], acc[mt][nt][3]);
                *(uint32_t*)(O + (brow + s0 + m0) * DIM + col)     = *(uint32_t*)&h0;
                *(uint32_t*)(O + (brow + s0 + m0 + 8) * DIM + col) = *(uint32_t*)&h1;
            }
        }
    }
}

// ---------------- residual + LayerNorm (fp16 X, fp32 residual, fp16 out) ----------------
__global__ __launch_bounds__(256)
void ln_kernel(const __half* __restrict__ X, const float* __restrict__ R,
               const float* __restrict__ g, const float* __restrict__ bta,
               __half* __restrict__ Yh)
{
    const int r = blockIdx.x, tid = threadIdx.x;
    const size_t base = (size_t)r * DIM;
    uint2 xu = *(const uint2*)(X + base + tid * 4);
    __half2 xh0 = *(__half2*)&xu.x, xh1 = *(__half2*)&xu.y;
    float2 f0 = __half22float2(xh0), f1 = __half22float2(xh1);
    float4 v = make_float4(f0.x, f0.y, f1.x, f1.y);
    float4 rv = *(const float4*)(R + base + tid * 4);
    v.x += rv.x; v.y += rv.y; v.z += rv.z; v.w += rv.w;

    __shared__ float red[8];
    __shared__ float s_mu, s_inv;
    const int w = tid >> 5, lane = tid & 31;

    float s = v.x + v.y + v.z + v.w;
#pragma unroll
    for (int o = 16; o; o >>= 1) s += __shfl_xor_sync(0xffffffffu, s, o);
    if (lane == 0) red[w] = s;
    __syncthreads();
    if (tid == 0) {
        float t = 0.f;
#pragma unroll
        for (int i = 0; i < 8; i++) t += red[i];
        s_mu = t * (1.f / DIM);
    }
    __syncthreads();
    float mu = s_mu;

    float dx = v.x - mu, dy = v.y - mu, dz = v.z - mu, dw = v.w - mu;
    float ss = dx*dx + dy*dy + dz*dz + dw*dw;
#pragma unroll
    for (int o = 16; o; o >>= 1) ss += __shfl_xor_sync(0xffffffffu, ss, o);
    if (lane == 0) red[w] = ss;
    __syncthreads();
    if (tid == 0) {
        float t = 0.f;
#pragma unroll
        for (int i = 0; i < 8; i++) t += red[i];
        s_inv = rsqrtf(t * (1.f / DIM) + 1e-6f);
    }
    __syncthreads();
    float inv = s_inv;

    float4 gg = *(const float4*)(g + tid * 4);
    float4 bb = *(const float4*)(bta + tid * 4);
    float ox = dx * inv * gg.x + bb.x;
    float oy = dy * inv * gg.y + bb.y;
    float oz = dz * inv * gg.z + bb.z;
    float ow = dw * inv * gg.w + bb.w;
    __half2 h0 = __floats2half2_rn(ox, oy);
    __half2 h1 = __floats2half2_rn(oz, ow);
    uint2 u; u.x = *(uint32_t*)&h0; u.y = *(uint32_t*)&h1;
    *(uint2*)(Yh + base + tid * 4) = u;
}

// ---------------- fused LayerNorm + head (fp16 X) ----------------
__global__ __launch_bounds__(256)
void ln_head(const __half* __restrict__ X,
             const float* __restrict__ g, const float* __restrict__ bta,
             const float* __restrict__ w, const float* __restrict__ bias,
             float* __restrict__ out)
{
    const int r = blockIdx.x, tid = threadIdx.x;
    const size_t base = (size_t)r * DIM;
    uint2 xu = *(const uint2*)(X + base + tid * 4);
    __half2 xh0 = *(__half2*)&xu.x, xh1 = *(__half2*)&xu.y;
    float2 f0 = __half22float2(xh0), f1 = __half22float2(xh1);
    float4 v = make_float4(f0.x, f0.y, f1.x, f1.y);

    __shared__ float red[8];
    __shared__ float s_mu, s_inv;
    const int wr = tid >> 5, lane = tid & 31;

    float s = v.x + v.y + v.z + v.w;
#pragma unroll
    for (int o = 16; o; o >>= 1) s += __shfl_xor_sync(0xffffffffu, s, o);
    if (lane == 0) red[wr] = s;
    __syncthreads();
    if (tid == 0) {
        float t = 0.f;
#pragma unroll
        for (int i = 0; i < 8; i++) t += red[i];
        s_mu = t * (1.f / DIM);
    }
    __syncthreads();
    float mu = s_mu;

    float dx = v.x - mu, dy = v.y - mu, dz = v.z - mu, dw = v.w - mu;
    float ss = dx*dx + dy*dy + dz*dz + dw*dw;
#pragma unroll
    for (int o = 16; o; o >>= 1) ss += __shfl_xor_sync(0xffffffffu, ss, o);
    if (lane == 0) red[wr] = ss;
    __syncthreads();
    if (tid == 0) {
        float t = 0.f;
#pragma unroll
        for (int i = 0; i < 8; i++) t += red[i];
        s_inv = rsqrtf(t * (1.f / DIM) + 1e-6f);
    }
    __syncthreads();
    float inv = s_inv;

    float4 gg = *(const float4*)(g + tid * 4);
    float4 bb = *(const float4*)(bta + tid * 4);
    float4 ww = *(const float4*)(w + tid * 4);
    float dot = (dx * inv * gg.x + bb.x) * ww.x
              + (dy * inv * gg.y + bb.y) * ww.y
              + (dz * inv * gg.z + bb.z) * ww.z
              + (dw * inv * gg.w + bb.w) * ww.w;
#pragma unroll
    for (int o = 16; o; o >>= 1) dot += __shfl_xor_sync(0xffffffffu, dot, o);
    if (lane == 0) red[wr] = dot;
    __syncthreads();
    if (tid == 0) {
        float t = 0.f;
#pragma unroll
        for (int i = 0; i < 8; i++) t += red[i];
        t += bias[0];
        out[r] = 1.f / (1.f + expf(-t));
    }
}

// ---------------- launch ----------------
extern "C" void kernel_launch(void* const* d_in, const int* in_sizes, int n_in,
                              void* d_out, int out_size)
{
    const float* x   = (const float*)d_in[0];
    const float* Wq  = (const float*)d_in[1];
    const float* Wk  = (const float*)d_in[2];
    const float* Wv  = (const float*)d_in[3];
    const float* Wo  = (const float*)d_in[4];
    const float* k1w = (const float*)d_in[5];
    const float* k1b = (const float*)d_in[6];
    const float* k2w = (const float*)d_in[7];
    const float* k2b = (const float*)d_in[8];
    const float* lng = (const float*)d_in[9];
    const float* lnb = (const float*)d_in[10];
    float* out = (float*)d_out;

    __half *x16, *q16, *k16, *v16, *a16, *y16, *c16, *h16;
    __half *wq16, *wk16, *wv16, *wo16, *w116;
    cudaGetSymbolAddress((void**)&x16, g_x16);
    cudaGetSymbolAddress((void**)&q16, g_q16);
    cudaGetSymbolAddress((void**)&k16, g_k16);
    cudaGetSymbolAddress((void**)&v16, g_v16);
    cudaGetSymbolAddress((void**)&a16, g_a16);
    cudaGetSymbolAddress((void**)&y16, g_y16);
    cudaGetSymbolAddress((void**)&c16, g_c16);
    cudaGetSymbolAddress((void**)&h16, g_h16);
    cudaGetSymbolAddress((void**)&wq16, g_wq16);
    cudaGetSymbolAddress((void**)&wk16, g_wk16);
    cudaGetSymbolAddress((void**)&wv16, g_wv16);
    cudaGetSymbolAddress((void**)&wo16, g_wo16);
    cudaGetSymbolAddress((void**)&w116, g_w116);

    cudaFuncSetAttribute(attn_tc, cudaFuncAttributeMaxDynamicSharedMemorySize,
                         ATT_SMEM_BYTES);
    cudaFuncSetAttribute(gemm_h, cudaFuncAttributeMaxDynamicSharedMemorySize,
                         GEMM_SMEM);

    conv16<<<(MTOT * DIM) / 1024, 256>>>(x, x16);
    conv16w<<<5 * 1024, 256>>>(Wq, Wk, Wv, Wo, k1w,
                               wq16, wk16, wv16, wo16, w116);

    dim3 gg(DIM / 128, MTOT / 128);   // (8, 128)

    gemm_h<<<gg, 256, GEMM_SMEM>>>(x16, wq16, nullptr, q16, 0);
    gemm_h<<<gg, 256, GEMM_SMEM>>>(x16, wk16, nullptr, k16, 0);
    gemm_h<<<gg, 256, GEMM_SMEM>>>(x16, wv16, nullptr, v16, 0);

    attn_tc<<<dim3(SEQ / QB, BATCH), 256, ATT_SMEM_BYTES>>>(q16, k16, v16, a16);

    gemm_h<<<gg, 256, GEMM_SMEM>>>(a16, wo16, nullptr, c16, 0);
    ln_kernel<<<MTOT, 256>>>(c16, x, lng, lnb, y16);
    gemm_h<<<gg, 256, GEMM_SMEM>>>(y16, w116, k1b, h16, 1);
    ln_head<<<MTOT, 256>>>(h16, lng, lnb, k2w, k2b, out);
}